// round 2
// baseline (speedup 1.0000x reference)
#include <cuda_runtime.h>
#include <math.h>

// ---------------------------------------------------------------------------
// Problem dims
// ---------------------------------------------------------------------------
#define BB 16
#define SS 1024
#define EE 768
#define HH 12
#define DD 64
#define FF 3072
#define ROWS (BB * SS)          // 16384
#define QKV_N (3 * EE)          // 2304

// ---------------------------------------------------------------------------
// Scratch (device globals; no cudaMalloc allowed)
// ---------------------------------------------------------------------------
__device__ float g_h[ROWS * EE];        // LN output (reused for LN1 and LN2)
__device__ float g_qkv[ROWS * QKV_N];   // fused qkv projections [row][sec*768 + h*64 + d]
__device__ float g_o[ROWS * EE];        // attention output (heads concatenated)
__device__ float g_x1[ROWS * EE];       // residual after attention
__device__ float g_f1[ROWS * FF];       // gelu(h2 @ W1 + b1)
__device__ float g_f2[ROWS * EE];       // f1 @ W2 + b2
__device__ float g_wqkv[EE * QKV_N];    // packed qkv weights [e][sec*768 + h*64 + d]
__device__ float g_bqkv[QKV_N];         // packed qkv bias

// ---------------------------------------------------------------------------
// Pack Wq/Wk/Wv ([H,E,D] each) into row-major [E, 2304]; pack biases.
// ---------------------------------------------------------------------------
__global__ void pack_qkv_kernel(const float* __restrict__ Wq,
                                const float* __restrict__ Wk,
                                const float* __restrict__ Wv,
                                const float* __restrict__ bq,
                                const float* __restrict__ bk,
                                const float* __restrict__ bv) {
    int idx = blockIdx.x * blockDim.x + threadIdx.x;
    int total = EE * QKV_N;
    if (idx < total) {
        int e = idx / QKV_N;
        int j = idx % QKV_N;
        int sec = j / EE;       // 0=q 1=k 2=v
        int hd = j % EE;        // h*64 + d
        const float* W = (sec == 0) ? Wq : (sec == 1) ? Wk : Wv;
        // W[h, e, d] at ((hd>>6)*EE + e)*DD + (hd & 63)
        g_wqkv[idx] = W[((hd >> 6) * EE + e) * DD + (hd & 63)];
    }
    if (idx < QKV_N) {
        int sec = idx / EE;
        int hd = idx % EE;
        const float* bsrc = (sec == 0) ? bq : (sec == 1) ? bk : bv;
        g_bqkv[idx] = bsrc[hd];
    }
}

// ---------------------------------------------------------------------------
// Block reduce helper (256 threads)
// ---------------------------------------------------------------------------
__device__ __forceinline__ float block_reduce_sum_256(float v, float* sbuf) {
    int lane = threadIdx.x & 31;
    int wid  = threadIdx.x >> 5;
#pragma unroll
    for (int m = 16; m; m >>= 1) v += __shfl_xor_sync(0xffffffffu, v, m);
    if (lane == 0) sbuf[wid] = v;
    __syncthreads();
    if (wid == 0) {
        v = (lane < 8) ? sbuf[lane] : 0.f;
#pragma unroll
        for (int m = 4; m; m >>= 1) v += __shfl_xor_sync(0xffffffffu, v, m);
        if (lane == 0) sbuf[0] = v;
    }
    __syncthreads();
    float r = sbuf[0];
    __syncthreads();
    return r;
}

// ---------------------------------------------------------------------------
// LayerNorm: out = (res ? res + LN(in) : LN(in)). One block per row (E=768).
// ---------------------------------------------------------------------------
__global__ void __launch_bounds__(256) ln_kernel(const float* __restrict__ in,
                                                 const float* __restrict__ gam,
                                                 const float* __restrict__ bet,
                                                 const float* __restrict__ res,
                                                 float* __restrict__ out) {
    __shared__ float sbuf[8];
    size_t row = blockIdx.x;
    const float* x = in + row * EE;
    float s = 0.f;
    for (int i = threadIdx.x; i < EE; i += 256) s += x[i];
    float mu = block_reduce_sum_256(s, sbuf) * (1.f / EE);
    float v = 0.f;
    for (int i = threadIdx.x; i < EE; i += 256) {
        float d = x[i] - mu;
        v += d * d;
    }
    float var = block_reduce_sum_256(v, sbuf) * (1.f / EE);
    float rstd = rsqrtf(var + 1e-5f);
    for (int i = threadIdx.x; i < EE; i += 256) {
        float y = (x[i] - mu) * rstd * gam[i] + bet[i];
        if (res) y += res[row * EE + i];
        out[row * EE + i] = y;
    }
}

// ---------------------------------------------------------------------------
// SGEMM: C[M,N] = A[M,K] @ B[K,N] + bias[N], epilogue variants.
// 128x128 block tile, BK=16, 256 threads, 8x8 per thread.
// EPI: 0 = bias, 1 = bias + exact gelu, 2 = bias + residual add
// ---------------------------------------------------------------------------
template <int EPI>
__global__ void __launch_bounds__(256) sgemm_kernel(const float* __restrict__ A,
                                                    const float* __restrict__ B,
                                                    const float* __restrict__ bias,
                                                    const float* __restrict__ res,
                                                    float* __restrict__ C,
                                                    int M, int N, int K) {
    __shared__ float As[16][128];
    __shared__ float Bs[16][128];
    int tid = threadIdx.x;
    int tx = tid & 15, ty = tid >> 4;
    int bn = blockIdx.x * 128;
    int bm = blockIdx.y * 128;

    float acc[8][8];
#pragma unroll
    for (int i = 0; i < 8; i++)
#pragma unroll
        for (int j = 0; j < 8; j++) acc[i][j] = 0.f;

    const float* Aptr = A + (size_t)bm * K;
    const float* Bptr = B + bn;

    for (int kt = 0; kt < K; kt += 16) {
        // Load A tile (128x16), store transposed As[k][m]
#pragma unroll
        for (int i = 0; i < 2; i++) {
            int f = tid + i * 256;          // 0..511 float4 slots
            int r = f >> 2;                 // 0..127
            int c = (f & 3) << 2;           // 0,4,8,12
            float4 v = *(const float4*)(Aptr + (size_t)r * K + kt + c);
            As[c + 0][r] = v.x;
            As[c + 1][r] = v.y;
            As[c + 2][r] = v.z;
            As[c + 3][r] = v.w;
        }
        // Load B tile (16x128) directly
#pragma unroll
        for (int i = 0; i < 2; i++) {
            int f = tid + i * 256;
            int r = f >> 5;                 // 0..15
            int c = (f & 31) << 2;          // 0..124
            float4 v = *(const float4*)(Bptr + (size_t)(kt + r) * N + c);
            *(float4*)&Bs[r][c] = v;
        }
        __syncthreads();
#pragma unroll
        for (int k = 0; k < 16; k++) {
            float a[8], bb[8];
            *(float4*)&a[0]  = *(const float4*)&As[k][ty * 8];
            *(float4*)&a[4]  = *(const float4*)&As[k][ty * 8 + 4];
            *(float4*)&bb[0] = *(const float4*)&Bs[k][tx * 8];
            *(float4*)&bb[4] = *(const float4*)&Bs[k][tx * 8 + 4];
#pragma unroll
            for (int i = 0; i < 8; i++)
#pragma unroll
                for (int j = 0; j < 8; j++)
                    acc[i][j] = fmaf(a[i], bb[j], acc[i][j]);
        }
        __syncthreads();
    }

    int row0 = bm + ty * 8;
    int col0 = bn + tx * 8;
#pragma unroll
    for (int i = 0; i < 8; i++) {
#pragma unroll
        for (int j = 0; j < 8; j++) {
            float v = acc[i][j] + bias[col0 + j];
            if (EPI == 1) v = 0.5f * v * (1.0f + erff(v * 0.70710678118654752f));
            if (EPI == 2) v += res[(size_t)(row0 + i) * N + col0 + j];
            acc[i][j] = v;
        }
        float4 v0 = make_float4(acc[i][0], acc[i][1], acc[i][2], acc[i][3]);
        float4 v1 = make_float4(acc[i][4], acc[i][5], acc[i][6], acc[i][7]);
        *(float4*)(C + (size_t)(row0 + i) * N + col0)     = v0;
        *(float4*)(C + (size_t)(row0 + i) * N + col0 + 4) = v1;
    }
}

// ---------------------------------------------------------------------------
// Causal flash attention.
// grid = (S/64, B*H). block = 256 threads (16x16, 4x4 micro-tile).
// qkv layout: [row = b*S+s][sec*768 + h*64 + d], sec 0/1/2 = q/k/v.
// o layout:   [row][h*64 + d]   (heads concatenated)
// ---------------------------------------------------------------------------
#define AP 68   // padded smem stride

__global__ void __launch_bounds__(256) attn_kernel(const float* __restrict__ qkv,
                                                   float* __restrict__ o) {
    extern __shared__ float sm[];
    float* Qs = sm;                // [64][AP]  Qs[d][r]
    float* Ks = sm + 64 * AP;      // [64][AP]  Ks[d][t]
    float* Vs = sm + 2 * 64 * AP;  // [64][AP]  Vs[t][d]
    float* Ps = sm + 3 * 64 * AP;  // [64][AP]  Ps[t][r]

    int qt = blockIdx.x;
    int bh = blockIdx.y;
    int b = bh / HH, h = bh % HH;
    int tid = threadIdx.x;
    int tx = tid & 15, ty = tid >> 4;

    size_t base = (size_t)b * SS * QKV_N;
    int hoff = h * DD;

    // load Q tile (scaled by 1/sqrt(D)), transposed into Qs[d][r]
    for (int idx = tid; idx < 4096; idx += 256) {
        int r = idx >> 6, d = idx & 63;
        Qs[d * AP + r] = qkv[base + (size_t)(qt * 64 + r) * QKV_N + hoff + d] * 0.125f;
    }

    float m_i[4], l_i[4], acc[4][4];
#pragma unroll
    for (int i = 0; i < 4; i++) {
        m_i[i] = -1e30f;
        l_i[i] = 0.f;
#pragma unroll
        for (int j = 0; j < 4; j++) acc[i][j] = 0.f;
    }

    for (int kt = 0; kt <= qt; kt++) {
        __syncthreads();
        // load K (transposed) and V tiles
        for (int idx = tid; idx < 4096; idx += 256) {
            int r = idx >> 6, d = idx & 63;
            size_t off = base + (size_t)(kt * 64 + r) * QKV_N + hoff + d;
            Ks[d * AP + r] = qkv[off + EE];
            Vs[r * AP + d] = qkv[off + 2 * EE];
        }
        __syncthreads();

        // S = Q @ K^T   (rows = ty*4+i, key cols = tx*4+j)
        float s[4][4];
#pragma unroll
        for (int i = 0; i < 4; i++)
#pragma unroll
            for (int j = 0; j < 4; j++) s[i][j] = 0.f;
#pragma unroll 8
        for (int k = 0; k < 64; k++) {
            float a[4], bb[4];
#pragma unroll
            for (int i = 0; i < 4; i++) a[i] = Qs[k * AP + ty * 4 + i];
#pragma unroll
            for (int j = 0; j < 4; j++) bb[j] = Ks[k * AP + tx * 4 + j];
#pragma unroll
            for (int i = 0; i < 4; i++)
#pragma unroll
                for (int j = 0; j < 4; j++) s[i][j] = fmaf(a[i], bb[j], s[i][j]);
        }

        if (kt == qt) {  // causal mask on diagonal tile
#pragma unroll
            for (int i = 0; i < 4; i++)
#pragma unroll
                for (int j = 0; j < 4; j++)
                    if (tx * 4 + j > ty * 4 + i) s[i][j] = -1e30f;
        }

        // online softmax (row groups of 16 lanes share rows)
#pragma unroll
        for (int i = 0; i < 4; i++) {
            float mt = fmaxf(fmaxf(s[i][0], s[i][1]), fmaxf(s[i][2], s[i][3]));
#pragma unroll
            for (int off = 8; off; off >>= 1)
                mt = fmaxf(mt, __shfl_xor_sync(0xffffffffu, mt, off));
            float mnew = fmaxf(m_i[i], mt);
            float sc = __expf(m_i[i] - mnew);
            float rs = 0.f;
#pragma unroll
            for (int j = 0; j < 4; j++) {
                float p = __expf(s[i][j] - mnew);
                s[i][j] = p;
                rs += p;
            }
#pragma unroll
            for (int off = 8; off; off >>= 1)
                rs += __shfl_xor_sync(0xffffffffu, rs, off);
            l_i[i] = l_i[i] * sc + rs;
            m_i[i] = mnew;
#pragma unroll
            for (int j = 0; j < 4; j++) acc[i][j] *= sc;
        }

        // store P transposed: Ps[t][r]
#pragma unroll
        for (int i = 0; i < 4; i++)
#pragma unroll
            for (int j = 0; j < 4; j++)
                Ps[(tx * 4 + j) * AP + ty * 4 + i] = s[i][j];
        __syncthreads();

        // O += P @ V   (output cols = d = tx*4+j)
#pragma unroll 8
        for (int k = 0; k < 64; k++) {
            float a[4], bb[4];
#pragma unroll
            for (int i = 0; i < 4; i++) a[i] = Ps[k * AP + ty * 4 + i];
#pragma unroll
            for (int j = 0; j < 4; j++) bb[j] = Vs[k * AP + tx * 4 + j];
#pragma unroll
            for (int i = 0; i < 4; i++)
#pragma unroll
                for (int j = 0; j < 4; j++) acc[i][j] = fmaf(a[i], bb[j], acc[i][j]);
        }
    }

    // write O / l
#pragma unroll
    for (int i = 0; i < 4; i++) {
        float inv = 1.f / l_i[i];
        size_t row = (size_t)b * SS + qt * 64 + ty * 4 + i;
#pragma unroll
        for (int j = 0; j < 4; j++)
            o[row * EE + hoff + tx * 4 + j] = acc[i][j] * inv;
    }
}

// ---------------------------------------------------------------------------
// Launch
// ---------------------------------------------------------------------------
extern "C" void kernel_launch(void* const* d_in, const int* in_sizes, int n_in,
                              void* d_out, int out_size) {
    const float* x     = (const float*)d_in[0];
    const float* Wq    = (const float*)d_in[1];
    const float* bq    = (const float*)d_in[2];
    const float* Wk    = (const float*)d_in[3];
    const float* bk    = (const float*)d_in[4];
    const float* Wv    = (const float*)d_in[5];
    const float* bv    = (const float*)d_in[6];
    const float* Wp    = (const float*)d_in[7];
    const float* bp    = (const float*)d_in[8];
    const float* ln1_g = (const float*)d_in[9];
    const float* ln1_b = (const float*)d_in[10];
    const float* ln2_g = (const float*)d_in[11];
    const float* ln2_b = (const float*)d_in[12];
    const float* W1    = (const float*)d_in[13];
    const float* b1    = (const float*)d_in[14];
    const float* W2    = (const float*)d_in[15];
    const float* b2    = (const float*)d_in[16];
    const float* lnf_g = (const float*)d_in[17];
    const float* lnf_b = (const float*)d_in[18];
    float* out = (float*)d_out;

    float *p_h, *p_qkv, *p_o, *p_x1, *p_f1, *p_f2, *p_wqkv, *p_bqkv;
    cudaGetSymbolAddress((void**)&p_h, g_h);
    cudaGetSymbolAddress((void**)&p_qkv, g_qkv);
    cudaGetSymbolAddress((void**)&p_o, g_o);
    cudaGetSymbolAddress((void**)&p_x1, g_x1);
    cudaGetSymbolAddress((void**)&p_f1, g_f1);
    cudaGetSymbolAddress((void**)&p_f2, g_f2);
    cudaGetSymbolAddress((void**)&p_wqkv, g_wqkv);
    cudaGetSymbolAddress((void**)&p_bqkv, g_bqkv);

    int attn_smem = 4 * 64 * AP * (int)sizeof(float);  // 69632 B
    cudaFuncSetAttribute(attn_kernel, cudaFuncAttributeMaxDynamicSharedMemorySize,
                         attn_smem);

    // 1. pack qkv weights + biases
    {
        int total = EE * QKV_N;
        pack_qkv_kernel<<<(total + 255) / 256, 256>>>(Wq, Wk, Wv, bq, bk, bv);
    }

    // 2. LN1: h = LN(x)
    ln_kernel<<<ROWS, 256>>>(x, ln1_g, ln1_b, nullptr, p_h);

    // 3. qkv = h @ Wqkv + bqkv      [16384, 2304]
    sgemm_kernel<0><<<dim3(QKV_N / 128, ROWS / 128), 256>>>(
        p_h, p_wqkv, p_bqkv, nullptr, p_qkv, ROWS, QKV_N, EE);

    // 4. attention -> o [16384, 768]
    attn_kernel<<<dim3(SS / 64, BB * HH), 256, attn_smem>>>(p_qkv, p_o);

    // 5. x1 = x + o @ Wp + bp
    sgemm_kernel<2><<<dim3(EE / 128, ROWS / 128), 256>>>(
        p_o, Wp, bp, x, p_x1, ROWS, EE, EE);

    // 6. LN2: h2 = LN(x1)  (reuse g_h)
    ln_kernel<<<ROWS, 256>>>(p_x1, ln2_g, ln2_b, nullptr, p_h);

    // 7. f1 = gelu(h2 @ W1 + b1)   [16384, 3072]
    sgemm_kernel<1><<<dim3(FF / 128, ROWS / 128), 256>>>(
        p_h, W1, b1, nullptr, p_f1, ROWS, FF, EE);

    // 8. f2 = f1 @ W2 + b2         [16384, 768]
    sgemm_kernel<0><<<dim3(EE / 128, ROWS / 128), 256>>>(
        p_f1, W2, b2, nullptr, p_f2, ROWS, EE, FF);

    // 9. out = x1 + LN(f2)
    ln_kernel<<<ROWS, 256>>>(p_f2, lnf_g, lnf_b, p_x1, out);
}

// round 5
// speedup vs baseline: 3.5484x; 3.5484x over previous
#include <cuda_runtime.h>
#include <cuda_bf16.h>
#include <math.h>
#include <stdint.h>

#define BB 16
#define SS 1024
#define EE 768
#define HH 12
#define DD 64
#define FF 3072
#define ROWS (BB * SS)
#define QKV_N (3 * EE)

// scratch
__device__ __nv_bfloat16 g_ahi[ROWS * EE], g_alo[ROWS * EE];
__device__ __nv_bfloat16 g_fhi[ROWS * FF], g_flo[ROWS * FF];
__device__ __nv_bfloat16 g_wqkvt_hi[QKV_N * EE], g_wqkvt_lo[QKV_N * EE];
__device__ __nv_bfloat16 g_wpt_hi[EE * EE], g_wpt_lo[EE * EE];
__device__ __nv_bfloat16 g_w1t_hi[FF * EE], g_w1t_lo[FF * EE];
__device__ __nv_bfloat16 g_w2t_hi[EE * FF], g_w2t_lo[EE * FF];
__device__ float g_bqkv[QKV_N];
__device__ float g_qkv[ROWS * QKV_N];
__device__ float g_x1[ROWS * EE];
__device__ float g_f2[ROWS * EE];

__device__ __forceinline__ void split_bf16(float v, __nv_bfloat16* hi, __nv_bfloat16* lo) {
    __nv_bfloat16 h = __float2bfloat16(v);
    *hi = h;
    *lo = __float2bfloat16(v - __bfloat162float(h));
}
__device__ __forceinline__ uint32_t swz(uint32_t o) { return o ^ ((o >> 3) & 0x70); }

// ---------------- weight prep ----------------
__global__ void pack_wqkv_kernel(const float* __restrict__ Wq, const float* __restrict__ Wk,
                                 const float* __restrict__ Wv, const float* __restrict__ bq,
                                 const float* __restrict__ bk, const float* __restrict__ bv) {
    int idx = blockIdx.x * blockDim.x + threadIdx.x;
    if (idx < QKV_N * EE) {
        int n = idx / EE, e = idx % EE;
        int sec = n / 768;
        int hd = n % 768;
        const float* W = (sec == 0) ? Wq : (sec == 1) ? Wk : Wv;
        float v = W[((hd >> 6) * EE + e) * DD + (hd & 63)];
        split_bf16(v, &g_wqkvt_hi[idx], &g_wqkvt_lo[idx]);
    }
    if (idx < QKV_N) {
        int sec = idx / 768;
        const float* bsrc = (sec == 0) ? bq : (sec == 1) ? bk : bv;
        g_bqkv[idx] = bsrc[idx % 768];
    }
}

__global__ void transpose_pair_kernel(const float* __restrict__ in,
                                      __nv_bfloat16* __restrict__ ohi,
                                      __nv_bfloat16* __restrict__ olo, int K, int N) {
    int idx = blockIdx.x * blockDim.x + threadIdx.x;
    if (idx >= N * K) return;
    int n = idx / K, k = idx % K;
    split_bf16(in[(size_t)k * N + n], &ohi[idx], &olo[idx]);
}

// ---------------- LN ----------------
__device__ __forceinline__ float block_reduce_sum_256(float v, float* sbuf) {
    int lane = threadIdx.x & 31, wid = threadIdx.x >> 5;
#pragma unroll
    for (int m = 16; m; m >>= 1) v += __shfl_xor_sync(0xffffffffu, v, m);
    if (lane == 0) sbuf[wid] = v;
    __syncthreads();
    if (wid == 0) {
        v = (lane < 8) ? sbuf[lane] : 0.f;
#pragma unroll
        for (int m = 4; m; m >>= 1) v += __shfl_xor_sync(0xffffffffu, v, m);
        if (lane == 0) sbuf[0] = v;
    }
    __syncthreads();
    float r = sbuf[0];
    __syncthreads();
    return r;
}

__global__ void __launch_bounds__(256) ln_pair_kernel(const float* __restrict__ in,
                                                      const float* __restrict__ gam,
                                                      const float* __restrict__ bet,
                                                      __nv_bfloat16* __restrict__ ohi,
                                                      __nv_bfloat16* __restrict__ olo) {
    __shared__ float sbuf[8];
    size_t row = blockIdx.x;
    const float* x = in + row * EE;
    float s = 0.f;
    for (int i = threadIdx.x; i < EE; i += 256) s += x[i];
    float mu = block_reduce_sum_256(s, sbuf) * (1.f / EE);
    float v = 0.f;
    for (int i = threadIdx.x; i < EE; i += 256) { float d = x[i] - mu; v += d * d; }
    float rstd = rsqrtf(block_reduce_sum_256(v, sbuf) * (1.f / EE) + 1e-5f);
    for (int i = threadIdx.x; i < EE; i += 256) {
        float y = (x[i] - mu) * rstd * gam[i] + bet[i];
        split_bf16(y, &ohi[row * EE + i], &olo[row * EE + i]);
    }
}

__global__ void __launch_bounds__(256) ln_final_kernel(const float* __restrict__ in,
                                                       const float* __restrict__ gam,
                                                       const float* __restrict__ bet,
                                                       const float* __restrict__ res,
                                                       float* __restrict__ out) {
    __shared__ float sbuf[8];
    size_t row = blockIdx.x;
    const float* x = in + row * EE;
    float s = 0.f;
    for (int i = threadIdx.x; i < EE; i += 256) s += x[i];
    float mu = block_reduce_sum_256(s, sbuf) * (1.f / EE);
    float v = 0.f;
    for (int i = threadIdx.x; i < EE; i += 256) { float d = x[i] - mu; v += d * d; }
    float rstd = rsqrtf(block_reduce_sum_256(v, sbuf) * (1.f / EE) + 1e-5f);
    for (int i = threadIdx.x; i < EE; i += 256)
        out[row * EE + i] = (x[i] - mu) * rstd * gam[i] + bet[i] + res[row * EE + i];
}

// ---------------- HMMA GEMM (mma.sync bf16, 3-pass split) ----------------
// C[M,N] = A[M,K] @ B[N,K]^T. 128x128 tile, BK=64, 2-stage cp.async pipeline.
// EPI: 0 bias->f32, 1 bias+gelu->bf16 pair, 2 bias+res->f32
#define STG 65536   // bytes per stage: Ah(16K) Al(16K) Bh(16K) Bl(16K)

__device__ __forceinline__ void cpasync16(uint32_t dst, const void* src) {
    asm volatile("cp.async.cg.shared.global [%0], [%1], 16;" :: "r"(dst), "l"(src));
}
__device__ __forceinline__ void ldm4(uint32_t* r, uint32_t addr) {
    asm volatile("ldmatrix.sync.aligned.m8n8.x4.shared.b16 {%0,%1,%2,%3}, [%4];"
                 : "=r"(r[0]), "=r"(r[1]), "=r"(r[2]), "=r"(r[3]) : "r"(addr));
}
__device__ __forceinline__ void mma16816(float* d, const uint32_t* a, uint32_t b0, uint32_t b1) {
    asm volatile(
        "mma.sync.aligned.m16n8k16.row.col.f32.bf16.bf16.f32 "
        "{%0,%1,%2,%3}, {%4,%5,%6,%7}, {%8,%9}, {%0,%1,%2,%3};"
        : "+f"(d[0]), "+f"(d[1]), "+f"(d[2]), "+f"(d[3])
        : "r"(a[0]), "r"(a[1]), "r"(a[2]), "r"(a[3]), "r"(b0), "r"(b1));
}

template <int EPI>
__global__ void __launch_bounds__(256, 1) tcgemm(const __nv_bfloat16* __restrict__ Ahi,
                                                 const __nv_bfloat16* __restrict__ Alo,
                                                 const __nv_bfloat16* __restrict__ Bhi,
                                                 const __nv_bfloat16* __restrict__ Blo,
                                                 const float* __restrict__ bias,
                                                 const float* __restrict__ res,
                                                 float* __restrict__ C,
                                                 __nv_bfloat16* __restrict__ Chi,
                                                 __nv_bfloat16* __restrict__ Clo,
                                                 int N, int K) {
    extern __shared__ char sm[];
    uint32_t sbase = (uint32_t)__cvta_generic_to_shared(sm);
    int tid = threadIdx.x;
    int lane = tid & 31, w = tid >> 5;
    int wm = w >> 2, wn = w & 3;                 // warp grid 2x4 over 128x128
    int bn = blockIdx.x * 128, bm = blockIdx.y * 128;

    const __nv_bfloat16* srcs[4] = {Ahi, Alo, Bhi, Blo};

    float acc[4][4][4];
#pragma unroll
    for (int i = 0; i < 4; i++)
#pragma unroll
        for (int j = 0; j < 4; j++)
#pragma unroll
            for (int q = 0; q < 4; q++) acc[i][j][q] = 0.f;

    int nk = K >> 6;

    // per-thread gmem->smem mapping: 16 cp.async of 16B
    // i in [0,4096): tile t=i>>10, r=(i&1023)>>3, chunk c=i&7
    // stage load helper (inlined twice)
#define LOAD_STAGE(kc, buf)                                                          \
    {                                                                                \
        uint32_t sb_ = sbase + (buf) * STG;                                          \
        _Pragma("unroll")                                                            \
        for (int ii = 0; ii < 16; ii++) {                                            \
            int i = tid + ii * 256;                                                  \
            int t = i >> 10, wrd = i & 1023, r = wrd >> 3, c = wrd & 7;              \
            int rb = (t < 2) ? bm : bn;                                              \
            const __nv_bfloat16* sp = srcs[t] + (size_t)(rb + r) * K + (kc) * 64 + c * 8; \
            cpasync16(sb_ + t * 16384 + swz(r * 128 + c * 16), sp);                  \
        }                                                                            \
        asm volatile("cp.async.commit_group;" ::: "memory");                         \
    }

    LOAD_STAGE(0, 0);

    // per-lane fragment address components
    int ra = (lane & 7) + ((lane & 8) ? 8 : 0);      // A row offset within m-tile
    int ka = (lane & 16) ? 8 : 0;                    // A k offset
    int rb_n = (lane & 7) + ((lane & 16) ? 8 : 0);   // B row offset within 16-row pair
    int kb_n = (lane & 8) ? 8 : 0;                   // B k offset

    for (int kc = 0; kc < nk; kc++) {
        if (kc + 1 < nk) {
            LOAD_STAGE(kc + 1, (kc + 1) & 1);
            asm volatile("cp.async.wait_group 1;" ::: "memory");
        } else {
            asm volatile("cp.async.wait_group 0;" ::: "memory");
        }
        __syncthreads();
        uint32_t sb = sbase + (kc & 1) * STG;
#pragma unroll
        for (int ks = 0; ks < 4; ks++) {
            uint32_t Ah[4][4], Al[4][4], Bh[2][4], Bl[2][4];
#pragma unroll
            for (int mt = 0; mt < 4; mt++) {
                int row = wm * 64 + mt * 16 + ra;
                uint32_t off = swz(row * 128 + (ks * 16 + ka) * 2);
                ldm4(Ah[mt], sb + off);
                ldm4(Al[mt], sb + 16384 + off);
            }
#pragma unroll
            for (int pr = 0; pr < 2; pr++) {
                int row = wn * 32 + pr * 16 + rb_n;
                uint32_t off = swz(row * 128 + (ks * 16 + kb_n) * 2);
                ldm4(Bh[pr], sb + 32768 + off);
                ldm4(Bl[pr], sb + 49152 + off);
            }
#pragma unroll
            for (int mt = 0; mt < 4; mt++)
#pragma unroll
                for (int nt = 0; nt < 4; nt++) {
                    int pr = nt >> 1, o = (nt & 1) * 2;
                    mma16816(acc[mt][nt], Ah[mt], Bh[pr][o], Bh[pr][o + 1]);
                    mma16816(acc[mt][nt], Ah[mt], Bl[pr][o], Bl[pr][o + 1]);
                    mma16816(acc[mt][nt], Al[mt], Bh[pr][o], Bh[pr][o + 1]);
                }
        }
        __syncthreads();
    }

    // epilogue from registers
    int l4 = lane >> 2, l2 = (lane & 3) * 2;
#pragma unroll
    for (int mt = 0; mt < 4; mt++)
#pragma unroll
        for (int nt = 0; nt < 4; nt++) {
            int col = bn + wn * 32 + nt * 8 + l2;
            float b0 = bias[col], b1 = bias[col + 1];
#pragma unroll
            for (int half = 0; half < 2; half++) {
                size_t row = (size_t)(bm + wm * 64 + mt * 16 + l4 + half * 8);
                float v0 = acc[mt][nt][half * 2 + 0] + b0;
                float v1 = acc[mt][nt][half * 2 + 1] + b1;
                if (EPI == 2) {
                    v0 += res[row * N + col];
                    v1 += res[row * N + col + 1];
                }
                if (EPI == 1) {
                    v0 = 0.5f * v0 * (1.0f + erff(v0 * 0.70710678118654752f));
                    v1 = 0.5f * v1 * (1.0f + erff(v1 * 0.70710678118654752f));
                    __nv_bfloat16 h0, l0, h1, l1;
                    split_bf16(v0, &h0, &l0);
                    split_bf16(v1, &h1, &l1);
                    *(__nv_bfloat162*)&Chi[row * N + col] = __nv_bfloat162(h0, h1);
                    *(__nv_bfloat162*)&Clo[row * N + col] = __nv_bfloat162(l0, l1);
                } else {
                    *(float2*)&C[row * N + col] = make_float2(v0, v1);
                }
            }
        }
#undef LOAD_STAGE
}

// ---------------- attention (fp32; outputs bf16 hi/lo) ----------------
#define AP 68
__global__ void __launch_bounds__(256) attn_kernel(const float* __restrict__ qkv,
                                                   __nv_bfloat16* __restrict__ ohi,
                                                   __nv_bfloat16* __restrict__ olo) {
    extern __shared__ float smf[];
    float* Qs = smf;
    float* Ks = smf + 64 * AP;
    float* Vs = smf + 2 * 64 * AP;
    float* Ps = smf + 3 * 64 * AP;
    int qt = blockIdx.x, bh = blockIdx.y;
    int b = bh / HH, h = bh % HH;
    int tid = threadIdx.x, tx = tid & 15, ty = tid >> 4;
    size_t base = (size_t)b * SS * QKV_N;
    int hoff = h * DD;
    for (int idx = tid; idx < 4096; idx += 256) {
        int r = idx >> 6, d = idx & 63;
        Qs[d * AP + r] = qkv[base + (size_t)(qt * 64 + r) * QKV_N + hoff + d] * 0.125f;
    }
    float m_i[4], l_i[4], acc[4][4];
#pragma unroll
    for (int i = 0; i < 4; i++) {
        m_i[i] = -1e30f; l_i[i] = 0.f;
#pragma unroll
        for (int j = 0; j < 4; j++) acc[i][j] = 0.f;
    }
    for (int kt = 0; kt <= qt; kt++) {
        __syncthreads();
        for (int idx = tid; idx < 4096; idx += 256) {
            int r = idx >> 6, d = idx & 63;
            size_t off = base + (size_t)(kt * 64 + r) * QKV_N + hoff + d;
            Ks[d * AP + r] = qkv[off + EE];
            Vs[r * AP + d] = qkv[off + 2 * EE];
        }
        __syncthreads();
        float s[4][4];
#pragma unroll
        for (int i = 0; i < 4; i++)
#pragma unroll
            for (int j = 0; j < 4; j++) s[i][j] = 0.f;
#pragma unroll 8
        for (int k = 0; k < 64; k++) {
            float a[4], bb[4];
#pragma unroll
            for (int i = 0; i < 4; i++) a[i] = Qs[k * AP + ty * 4 + i];
#pragma unroll
            for (int j = 0; j < 4; j++) bb[j] = Ks[k * AP + tx * 4 + j];
#pragma unroll
            for (int i = 0; i < 4; i++)
#pragma unroll
                for (int j = 0; j < 4; j++) s[i][j] = fmaf(a[i], bb[j], s[i][j]);
        }
        if (kt == qt) {
#pragma unroll
            for (int i = 0; i < 4; i++)
#pragma unroll
                for (int j = 0; j < 4; j++)
                    if (tx * 4 + j > ty * 4 + i) s[i][j] = -1e30f;
        }
#pragma unroll
        for (int i = 0; i < 4; i++) {
            float mt = fmaxf(fmaxf(s[i][0], s[i][1]), fmaxf(s[i][2], s[i][3]));
#pragma unroll
            for (int off = 8; off; off >>= 1) mt = fmaxf(mt, __shfl_xor_sync(0xffffffffu, mt, off));
            float mnew = fmaxf(m_i[i], mt);
            float sc = __expf(m_i[i] - mnew);
            float rs = 0.f;
#pragma unroll
            for (int j = 0; j < 4; j++) { float p = __expf(s[i][j] - mnew); s[i][j] = p; rs += p; }
#pragma unroll
            for (int off = 8; off; off >>= 1) rs += __shfl_xor_sync(0xffffffffu, rs, off);
            l_i[i] = l_i[i] * sc + rs;
            m_i[i] = mnew;
#pragma unroll
            for (int j = 0; j < 4; j++) acc[i][j] *= sc;
        }
#pragma unroll
        for (int i = 0; i < 4; i++)
#pragma unroll
            for (int j = 0; j < 4; j++) Ps[(tx * 4 + j) * AP + ty * 4 + i] = s[i][j];
        __syncthreads();
#pragma unroll 8
        for (int k = 0; k < 64; k++) {
            float a[4], bb[4];
#pragma unroll
            for (int i = 0; i < 4; i++) a[i] = Ps[k * AP + ty * 4 + i];
#pragma unroll
            for (int j = 0; j < 4; j++) bb[j] = Vs[k * AP + tx * 4 + j];
#pragma unroll
            for (int i = 0; i < 4; i++)
#pragma unroll
                for (int j = 0; j < 4; j++) acc[i][j] = fmaf(a[i], bb[j], acc[i][j]);
        }
    }
#pragma unroll
    for (int i = 0; i < 4; i++) {
        float inv = 1.f / l_i[i];
        size_t row = (size_t)b * SS + qt * 64 + ty * 4 + i;
#pragma unroll
        for (int j = 0; j < 4; j++)
            split_bf16(acc[i][j] * inv,
                       &ohi[row * EE + hoff + tx * 4 + j],
                       &olo[row * EE + hoff + tx * 4 + j]);
    }
}

// ---------------- launch ----------------
extern "C" void kernel_launch(void* const* d_in, const int* in_sizes, int n_in,
                              void* d_out, int out_size) {
    const float* x = (const float*)d_in[0];
    const float* Wq = (const float*)d_in[1];
    const float* bq = (const float*)d_in[2];
    const float* Wk = (const float*)d_in[3];
    const float* bk = (const float*)d_in[4];
    const float* Wv = (const float*)d_in[5];
    const float* bv = (const float*)d_in[6];
    const float* Wp = (const float*)d_in[7];
    const float* bp = (const float*)d_in[8];
    const float* ln1_g = (const float*)d_in[9];
    const float* ln1_b = (const float*)d_in[10];
    const float* ln2_g = (const float*)d_in[11];
    const float* ln2_b = (const float*)d_in[12];
    const float* W1 = (const float*)d_in[13];
    const float* b1 = (const float*)d_in[14];
    const float* W2 = (const float*)d_in[15];
    const float* b2 = (const float*)d_in[16];
    const float* lnf_g = (const float*)d_in[17];
    const float* lnf_b = (const float*)d_in[18];
    float* out = (float*)d_out;

    __nv_bfloat16 *p_ahi, *p_alo, *p_fhi, *p_flo;
    __nv_bfloat16 *p_wqh, *p_wql, *p_wph, *p_wpl, *p_w1h, *p_w1l, *p_w2h, *p_w2l;
    float *p_bqkv, *p_qkv, *p_x1, *p_f2;
    cudaGetSymbolAddress((void**)&p_ahi, g_ahi);
    cudaGetSymbolAddress((void**)&p_alo, g_alo);
    cudaGetSymbolAddress((void**)&p_fhi, g_fhi);
    cudaGetSymbolAddress((void**)&p_flo, g_flo);
    cudaGetSymbolAddress((void**)&p_wqh, g_wqkvt_hi);
    cudaGetSymbolAddress((void**)&p_wql, g_wqkvt_lo);
    cudaGetSymbolAddress((void**)&p_wph, g_wpt_hi);
    cudaGetSymbolAddress((void**)&p_wpl, g_wpt_lo);
    cudaGetSymbolAddress((void**)&p_w1h, g_w1t_hi);
    cudaGetSymbolAddress((void**)&p_w1l, g_w1t_lo);
    cudaGetSymbolAddress((void**)&p_w2h, g_w2t_hi);
    cudaGetSymbolAddress((void**)&p_w2l, g_w2t_lo);
    cudaGetSymbolAddress((void**)&p_bqkv, g_bqkv);
    cudaGetSymbolAddress((void**)&p_qkv, g_qkv);
    cudaGetSymbolAddress((void**)&p_x1, g_x1);
    cudaGetSymbolAddress((void**)&p_f2, g_f2);

    int gsmem = 2 * STG;  // 131072
    cudaFuncSetAttribute(tcgemm<0>, cudaFuncAttributeMaxDynamicSharedMemorySize, gsmem);
    cudaFuncSetAttribute(tcgemm<1>, cudaFuncAttributeMaxDynamicSharedMemorySize, gsmem);
    cudaFuncSetAttribute(tcgemm<2>, cudaFuncAttributeMaxDynamicSharedMemorySize, gsmem);
    int asmem = 4 * 64 * AP * (int)sizeof(float);
    cudaFuncSetAttribute(attn_kernel, cudaFuncAttributeMaxDynamicSharedMemorySize, asmem);

    pack_wqkv_kernel<<<(QKV_N * EE + 255) / 256, 256>>>(Wq, Wk, Wv, bq, bk, bv);
    transpose_pair_kernel<<<(EE * EE + 255) / 256, 256>>>(Wp, p_wph, p_wpl, EE, EE);
    transpose_pair_kernel<<<(EE * FF + 255) / 256, 256>>>(W1, p_w1h, p_w1l, EE, FF);
    transpose_pair_kernel<<<(FF * EE + 255) / 256, 256>>>(W2, p_w2h, p_w2l, FF, EE);

    ln_pair_kernel<<<ROWS, 256>>>(x, ln1_g, ln1_b, p_ahi, p_alo);
    tcgemm<0><<<dim3(QKV_N / 128, ROWS / 128), 256, gsmem>>>(
        p_ahi, p_alo, p_wqh, p_wql, p_bqkv, nullptr, p_qkv, nullptr, nullptr, QKV_N, EE);
    attn_kernel<<<dim3(SS / 64, BB * HH), 256, asmem>>>(p_qkv, p_ahi, p_alo);
    tcgemm<2><<<dim3(EE / 128, ROWS / 128), 256, gsmem>>>(
        p_ahi, p_alo, p_wph, p_wpl, bp, x, p_x1, nullptr, nullptr, EE, EE);
    ln_pair_kernel<<<ROWS, 256>>>(p_x1, ln2_g, ln2_b, p_ahi, p_alo);
    tcgemm<1><<<dim3(FF / 128, ROWS / 128), 256, gsmem>>>(
        p_ahi, p_alo, p_w1h, p_w1l, b1, nullptr, nullptr, p_fhi, p_flo, FF, EE);
    tcgemm<0><<<dim3(EE / 128, ROWS / 128), 256, gsmem>>>(
        p_fhi, p_flo, p_w2h, p_w2l, b2, nullptr, p_f2, nullptr, nullptr, EE, FF);
    ln_final_kernel<<<ROWS, 256>>>(p_f2, lnf_g, lnf_b, p_x1, out);
}

// round 6
// speedup vs baseline: 4.2964x; 1.2108x over previous
#include <cuda_runtime.h>
#include <cuda_bf16.h>
#include <math.h>
#include <stdint.h>

#define BB 16
#define SS 1024
#define EE 768
#define HH 12
#define DD 64
#define FF 3072
#define ROWS (BB * SS)
#define QKV_N (3 * EE)

// scratch
__device__ __nv_bfloat16 g_ahi[ROWS * EE], g_alo[ROWS * EE];
__device__ __nv_bfloat16 g_fhi[ROWS * FF], g_flo[ROWS * FF];
__device__ __nv_bfloat16 g_wqkvt_hi[QKV_N * EE], g_wqkvt_lo[QKV_N * EE];
__device__ __nv_bfloat16 g_wpt_hi[EE * EE], g_wpt_lo[EE * EE];
__device__ __nv_bfloat16 g_w1t_hi[FF * EE], g_w1t_lo[FF * EE];
__device__ __nv_bfloat16 g_w2t_hi[EE * FF], g_w2t_lo[EE * FF];
__device__ float g_bqkv[QKV_N];
__device__ float g_qkv[ROWS * QKV_N];
__device__ float g_x1[ROWS * EE];
__device__ float g_f2[ROWS * EE];

__device__ __forceinline__ void split_bf16(float v, __nv_bfloat16* hi, __nv_bfloat16* lo) {
    __nv_bfloat16 h = __float2bfloat16(v);
    *hi = h;
    *lo = __float2bfloat16(v - __bfloat162float(h));
}
__device__ __forceinline__ uint32_t swz(uint32_t o) { return o ^ ((o >> 3) & 0x70); }
__device__ __forceinline__ uint32_t pack2(float x, float y) {
    __nv_bfloat162 t = __floats2bfloat162_rn(x, y);
    return *(uint32_t*)&t;
}

// ---------------- weight prep ----------------
__global__ void pack_wqkv_kernel(const float* __restrict__ Wq, const float* __restrict__ Wk,
                                 const float* __restrict__ Wv, const float* __restrict__ bq,
                                 const float* __restrict__ bk, const float* __restrict__ bv) {
    int idx = blockIdx.x * blockDim.x + threadIdx.x;
    if (idx < QKV_N * EE) {
        int n = idx / EE, e = idx % EE;
        int sec = n / 768;
        int hd = n % 768;
        const float* W = (sec == 0) ? Wq : (sec == 1) ? Wk : Wv;
        float v = W[((hd >> 6) * EE + e) * DD + (hd & 63)];
        split_bf16(v, &g_wqkvt_hi[idx], &g_wqkvt_lo[idx]);
    }
    if (idx < QKV_N) {
        int sec = idx / 768;
        const float* bsrc = (sec == 0) ? bq : (sec == 1) ? bk : bv;
        g_bqkv[idx] = bsrc[idx % 768];
    }
}

__global__ void transpose_pair_kernel(const float* __restrict__ in,
                                      __nv_bfloat16* __restrict__ ohi,
                                      __nv_bfloat16* __restrict__ olo, int K, int N) {
    int idx = blockIdx.x * blockDim.x + threadIdx.x;
    if (idx >= N * K) return;
    int n = idx / K, k = idx % K;
    split_bf16(in[(size_t)k * N + n], &ohi[idx], &olo[idx]);
}

// ---------------- LN ----------------
__device__ __forceinline__ float block_reduce_sum_256(float v, float* sbuf) {
    int lane = threadIdx.x & 31, wid = threadIdx.x >> 5;
#pragma unroll
    for (int m = 16; m; m >>= 1) v += __shfl_xor_sync(0xffffffffu, v, m);
    if (lane == 0) sbuf[wid] = v;
    __syncthreads();
    if (wid == 0) {
        v = (lane < 8) ? sbuf[lane] : 0.f;
#pragma unroll
        for (int m = 4; m; m >>= 1) v += __shfl_xor_sync(0xffffffffu, v, m);
        if (lane == 0) sbuf[0] = v;
    }
    __syncthreads();
    float r = sbuf[0];
    __syncthreads();
    return r;
}

__global__ void __launch_bounds__(256) ln_pair_kernel(const float* __restrict__ in,
                                                      const float* __restrict__ gam,
                                                      const float* __restrict__ bet,
                                                      __nv_bfloat16* __restrict__ ohi,
                                                      __nv_bfloat16* __restrict__ olo) {
    __shared__ float sbuf[8];
    size_t row = blockIdx.x;
    const float* x = in + row * EE;
    float s = 0.f;
    for (int i = threadIdx.x; i < EE; i += 256) s += x[i];
    float mu = block_reduce_sum_256(s, sbuf) * (1.f / EE);
    float v = 0.f;
    for (int i = threadIdx.x; i < EE; i += 256) { float d = x[i] - mu; v += d * d; }
    float rstd = rsqrtf(block_reduce_sum_256(v, sbuf) * (1.f / EE) + 1e-5f);
    for (int i = threadIdx.x; i < EE; i += 256) {
        float y = (x[i] - mu) * rstd * gam[i] + bet[i];
        split_bf16(y, &ohi[row * EE + i], &olo[row * EE + i]);
    }
}

__global__ void __launch_bounds__(256) ln_final_kernel(const float* __restrict__ in,
                                                       const float* __restrict__ gam,
                                                       const float* __restrict__ bet,
                                                       const float* __restrict__ res,
                                                       float* __restrict__ out) {
    __shared__ float sbuf[8];
    size_t row = blockIdx.x;
    const float* x = in + row * EE;
    float s = 0.f;
    for (int i = threadIdx.x; i < EE; i += 256) s += x[i];
    float mu = block_reduce_sum_256(s, sbuf) * (1.f / EE);
    float v = 0.f;
    for (int i = threadIdx.x; i < EE; i += 256) { float d = x[i] - mu; v += d * d; }
    float rstd = rsqrtf(block_reduce_sum_256(v, sbuf) * (1.f / EE) + 1e-5f);
    for (int i = threadIdx.x; i < EE; i += 256)
        out[row * EE + i] = (x[i] - mu) * rstd * gam[i] + bet[i] + res[row * EE + i];
}

// ---------------- HMMA primitives ----------------
__device__ __forceinline__ void cpasync16(uint32_t dst, const void* src) {
    asm volatile("cp.async.cg.shared.global [%0], [%1], 16;" :: "r"(dst), "l"(src));
}
__device__ __forceinline__ void ldm4(uint32_t* r, uint32_t addr) {
    asm volatile("ldmatrix.sync.aligned.m8n8.x4.shared.b16 {%0,%1,%2,%3}, [%4];"
                 : "=r"(r[0]), "=r"(r[1]), "=r"(r[2]), "=r"(r[3]) : "r"(addr));
}
__device__ __forceinline__ void mma16816(float* d, const uint32_t* a, uint32_t b0, uint32_t b1) {
    asm volatile(
        "mma.sync.aligned.m16n8k16.row.col.f32.bf16.bf16.f32 "
        "{%0,%1,%2,%3}, {%4,%5,%6,%7}, {%8,%9}, {%0,%1,%2,%3};"
        : "+f"(d[0]), "+f"(d[1]), "+f"(d[2]), "+f"(d[3])
        : "r"(a[0]), "r"(a[1]), "r"(a[2]), "r"(a[3]), "r"(b0), "r"(b1));
}

// ---------------- HMMA GEMM (3-pass bf16 split) ----------------
#define STG 65536

template <int EPI>
__global__ void __launch_bounds__(256, 1) tcgemm(const __nv_bfloat16* __restrict__ Ahi,
                                                 const __nv_bfloat16* __restrict__ Alo,
                                                 const __nv_bfloat16* __restrict__ Bhi,
                                                 const __nv_bfloat16* __restrict__ Blo,
                                                 const float* __restrict__ bias,
                                                 const float* __restrict__ res,
                                                 float* __restrict__ C,
                                                 __nv_bfloat16* __restrict__ Chi,
                                                 __nv_bfloat16* __restrict__ Clo,
                                                 int N, int K) {
    extern __shared__ char sm[];
    uint32_t sbase = (uint32_t)__cvta_generic_to_shared(sm);
    int tid = threadIdx.x;
    int lane = tid & 31, w = tid >> 5;
    int wm = w >> 2, wn = w & 3;
    int bn = blockIdx.x * 128, bm = blockIdx.y * 128;

    const __nv_bfloat16* srcs[4] = {Ahi, Alo, Bhi, Blo};

    float acc[4][4][4];
#pragma unroll
    for (int i = 0; i < 4; i++)
#pragma unroll
        for (int j = 0; j < 4; j++)
#pragma unroll
            for (int q = 0; q < 4; q++) acc[i][j][q] = 0.f;

    int nk = K >> 6;

#define LOAD_STAGE(kc, buf)                                                          \
    {                                                                                \
        uint32_t sb_ = sbase + (buf) * STG;                                          \
        _Pragma("unroll")                                                            \
        for (int ii = 0; ii < 16; ii++) {                                            \
            int i = tid + ii * 256;                                                  \
            int t = i >> 10, wrd = i & 1023, r = wrd >> 3, c = wrd & 7;              \
            int rb = (t < 2) ? bm : bn;                                              \
            const __nv_bfloat16* sp = srcs[t] + (size_t)(rb + r) * K + (kc) * 64 + c * 8; \
            cpasync16(sb_ + t * 16384 + swz(r * 128 + c * 16), sp);                  \
        }                                                                            \
        asm volatile("cp.async.commit_group;" ::: "memory");                         \
    }

    LOAD_STAGE(0, 0);

    int ra = (lane & 7) + ((lane & 8) ? 8 : 0);
    int ka = (lane & 16) ? 8 : 0;
    int rb_n = (lane & 7) + ((lane & 16) ? 8 : 0);
    int kb_n = (lane & 8) ? 8 : 0;

    for (int kc = 0; kc < nk; kc++) {
        if (kc + 1 < nk) {
            LOAD_STAGE(kc + 1, (kc + 1) & 1);
            asm volatile("cp.async.wait_group 1;" ::: "memory");
        } else {
            asm volatile("cp.async.wait_group 0;" ::: "memory");
        }
        __syncthreads();
        uint32_t sb = sbase + (kc & 1) * STG;
#pragma unroll
        for (int ks = 0; ks < 4; ks++) {
            uint32_t Ah[4][4], Al[4][4], Bh[2][4], Bl[2][4];
#pragma unroll
            for (int mt = 0; mt < 4; mt++) {
                int row = wm * 64 + mt * 16 + ra;
                uint32_t off = swz(row * 128 + (ks * 16 + ka) * 2);
                ldm4(Ah[mt], sb + off);
                ldm4(Al[mt], sb + 16384 + off);
            }
#pragma unroll
            for (int pr = 0; pr < 2; pr++) {
                int row = wn * 32 + pr * 16 + rb_n;
                uint32_t off = swz(row * 128 + (ks * 16 + kb_n) * 2);
                ldm4(Bh[pr], sb + 32768 + off);
                ldm4(Bl[pr], sb + 49152 + off);
            }
#pragma unroll
            for (int mt = 0; mt < 4; mt++)
#pragma unroll
                for (int nt = 0; nt < 4; nt++) {
                    int pr = nt >> 1, o = (nt & 1) * 2;
                    mma16816(acc[mt][nt], Ah[mt], Bh[pr][o], Bh[pr][o + 1]);
                    mma16816(acc[mt][nt], Ah[mt], Bl[pr][o], Bl[pr][o + 1]);
                    mma16816(acc[mt][nt], Al[mt], Bh[pr][o], Bh[pr][o + 1]);
                }
        }
        __syncthreads();
    }

    int l4 = lane >> 2, l2 = (lane & 3) * 2;
#pragma unroll
    for (int mt = 0; mt < 4; mt++)
#pragma unroll
        for (int nt = 0; nt < 4; nt++) {
            int col = bn + wn * 32 + nt * 8 + l2;
            float b0 = bias[col], b1 = bias[col + 1];
#pragma unroll
            for (int half = 0; half < 2; half++) {
                size_t row = (size_t)(bm + wm * 64 + mt * 16 + l4 + half * 8);
                float v0 = acc[mt][nt][half * 2 + 0] + b0;
                float v1 = acc[mt][nt][half * 2 + 1] + b1;
                if (EPI == 2) {
                    v0 += res[row * N + col];
                    v1 += res[row * N + col + 1];
                }
                if (EPI == 1) {
                    v0 = 0.5f * v0 * (1.0f + erff(v0 * 0.70710678118654752f));
                    v1 = 0.5f * v1 * (1.0f + erff(v1 * 0.70710678118654752f));
                    __nv_bfloat16 h0, l0, h1, l1;
                    split_bf16(v0, &h0, &l0);
                    split_bf16(v1, &h1, &l1);
                    *(__nv_bfloat162*)&Chi[row * N + col] = __nv_bfloat162(h0, h1);
                    *(__nv_bfloat162*)&Clo[row * N + col] = __nv_bfloat162(l0, l1);
                } else {
                    *(float2*)&C[row * N + col] = make_float2(v0, v1);
                }
            }
        }
#undef LOAD_STAGE
}

// ---------------- HMMA flash attention ----------------
// grid (S/64, B*H), 128 threads (4 warps, 16 q-rows each).
// smem: Qh/Ql [64][64] bf16 (16KB), Kh/Kl [t][d] (16KB), Vh/Vl [d][t] (16KB).
__global__ void __launch_bounds__(128) attn_kernel(const float* __restrict__ qkv,
                                                   __nv_bfloat16* __restrict__ ohi,
                                                   __nv_bfloat16* __restrict__ olo) {
    extern __shared__ char smc[];
    uint32_t sb = (uint32_t)__cvta_generic_to_shared(smc);
    uint32_t Qh = sb, Ql = sb + 8192;
    uint32_t Kh = sb + 16384, Kl = sb + 24576;
    uint32_t Vh = sb + 32768, Vl = sb + 40960;

    int qt = blockIdx.x, bh = blockIdx.y;
    int b = bh / HH, h = bh % HH;
    int tid = threadIdx.x, lane = tid & 31, w = tid >> 5;
    size_t base = (size_t)b * SS * QKV_N;
    int hoff = h * DD;

    // load Q (scaled), split, swizzled [r][d]
    for (int i = tid; i < 4096; i += 128) {
        int r = i >> 6, d = i & 63;
        float v = qkv[base + (size_t)(qt * 64 + r) * QKV_N + hoff + d] * 0.125f;
        __nv_bfloat16 hi, lo;
        split_bf16(v, &hi, &lo);
        uint32_t off = swz(r * 128 + d * 2);
        *(__nv_bfloat16*)(smc + off) = hi;
        *(__nv_bfloat16*)(smc + 8192 + off) = lo;
    }

    int ra = (lane & 7) + ((lane & 8) ? 8 : 0);
    int ka = (lane & 16) ? 8 : 0;
    int rbn = (lane & 7) + ((lane & 16) ? 8 : 0);
    int kbn = (lane & 8) ? 8 : 0;
    int r0 = lane >> 2, c0 = (lane & 3) * 2;

    float m0 = -1e30f, m1 = -1e30f, l0 = 0.f, l1 = 0.f;
    float o[8][4];
#pragma unroll
    for (int i = 0; i < 8; i++)
#pragma unroll
        for (int j = 0; j < 4; j++) o[i][j] = 0.f;

    for (int kt = 0; kt <= qt; kt++) {
        __syncthreads();
        // K -> [t][d] hi/lo ; V -> [d][t] hi/lo (transposed)
        for (int i = tid; i < 4096; i += 128) {
            int r = i >> 6, d = i & 63;
            size_t off = base + (size_t)(kt * 64 + r) * QKV_N + hoff + d;
            __nv_bfloat16 hi, lo;
            split_bf16(qkv[off + EE], &hi, &lo);
            uint32_t ko = swz(r * 128 + d * 2);
            *(__nv_bfloat16*)(smc + 16384 + ko) = hi;
            *(__nv_bfloat16*)(smc + 24576 + ko) = lo;
            split_bf16(qkv[off + 2 * EE], &hi, &lo);
            uint32_t vo = swz(d * 128 + r * 2);
            *(__nv_bfloat16*)(smc + 32768 + vo) = hi;
            *(__nv_bfloat16*)(smc + 40960 + vo) = lo;
        }
        __syncthreads();

        // S = Q K^T (3-pass)
        float s[8][4];
#pragma unroll
        for (int i = 0; i < 8; i++)
#pragma unroll
            for (int j = 0; j < 4; j++) s[i][j] = 0.f;
#pragma unroll
        for (int kc = 0; kc < 4; kc++) {
            uint32_t qh[4], ql[4], kh[4][4], kl[4][4];
            uint32_t aoff = swz((w * 16 + ra) * 128 + (kc * 16 + ka) * 2);
            ldm4(qh, Qh + aoff);
            ldm4(ql, Ql + aoff);
#pragma unroll
            for (int tg = 0; tg < 4; tg++) {
                uint32_t boff = swz((tg * 16 + rbn) * 128 + (kc * 16 + kbn) * 2);
                ldm4(kh[tg], Kh + boff);
                ldm4(kl[tg], Kl + boff);
            }
#pragma unroll
            for (int nt = 0; nt < 8; nt++) {
                int pr = nt >> 1, oo = (nt & 1) * 2;
                mma16816(s[nt], qh, kh[pr][oo], kh[pr][oo + 1]);
                mma16816(s[nt], qh, kl[pr][oo], kl[pr][oo + 1]);
                mma16816(s[nt], ql, kh[pr][oo], kh[pr][oo + 1]);
            }
        }

        if (kt == qt) {  // causal mask on diagonal tile
            int row0 = w * 16 + r0, row1 = row0 + 8;
#pragma unroll
            for (int nt = 0; nt < 8; nt++) {
                int c = nt * 8 + c0;
                if (c > row0) s[nt][0] = -1e30f;
                if (c + 1 > row0) s[nt][1] = -1e30f;
                if (c > row1) s[nt][2] = -1e30f;
                if (c + 1 > row1) s[nt][3] = -1e30f;
            }
        }

        // online softmax
        float mt0 = -1e30f, mt1 = -1e30f;
#pragma unroll
        for (int nt = 0; nt < 8; nt++) {
            mt0 = fmaxf(mt0, fmaxf(s[nt][0], s[nt][1]));
            mt1 = fmaxf(mt1, fmaxf(s[nt][2], s[nt][3]));
        }
#pragma unroll
        for (int off = 1; off <= 2; off <<= 1) {
            mt0 = fmaxf(mt0, __shfl_xor_sync(0xffffffffu, mt0, off));
            mt1 = fmaxf(mt1, __shfl_xor_sync(0xffffffffu, mt1, off));
        }
        float mn0 = fmaxf(m0, mt0), mn1 = fmaxf(m1, mt1);
        float sc0 = __expf(m0 - mn0), sc1 = __expf(m1 - mn1);
        float rs0 = 0.f, rs1 = 0.f;
#pragma unroll
        for (int nt = 0; nt < 8; nt++) {
            s[nt][0] = __expf(s[nt][0] - mn0);
            s[nt][1] = __expf(s[nt][1] - mn0);
            s[nt][2] = __expf(s[nt][2] - mn1);
            s[nt][3] = __expf(s[nt][3] - mn1);
            rs0 += s[nt][0] + s[nt][1];
            rs1 += s[nt][2] + s[nt][3];
        }
#pragma unroll
        for (int off = 1; off <= 2; off <<= 1) {
            rs0 += __shfl_xor_sync(0xffffffffu, rs0, off);
            rs1 += __shfl_xor_sync(0xffffffffu, rs1, off);
        }
        l0 = l0 * sc0 + rs0;
        l1 = l1 * sc1 + rs1;
        m0 = mn0;
        m1 = mn1;
#pragma unroll
        for (int i = 0; i < 8; i++) {
            o[i][0] *= sc0; o[i][1] *= sc0;
            o[i][2] *= sc1; o[i][3] *= sc1;
        }

        // O += P V (3-pass, P from registers)
#pragma unroll
        for (int kc = 0; kc < 4; kc++) {
            // split P fragments
            float p00 = s[2 * kc][0], p01 = s[2 * kc][1];
            float p02 = s[2 * kc][2], p03 = s[2 * kc][3];
            float p10 = s[2 * kc + 1][0], p11 = s[2 * kc + 1][1];
            float p12 = s[2 * kc + 1][2], p13 = s[2 * kc + 1][3];
            uint32_t aph[4], apl[4];
            aph[0] = pack2(p00, p01);
            aph[1] = pack2(p02, p03);
            aph[2] = pack2(p10, p11);
            aph[3] = pack2(p12, p13);
            __nv_bfloat162 t0 = *(__nv_bfloat162*)&aph[0];
            __nv_bfloat162 t1 = *(__nv_bfloat162*)&aph[1];
            __nv_bfloat162 t2 = *(__nv_bfloat162*)&aph[2];
            __nv_bfloat162 t3 = *(__nv_bfloat162*)&aph[3];
            apl[0] = pack2(p00 - __bfloat162float(t0.x), p01 - __bfloat162float(t0.y));
            apl[1] = pack2(p02 - __bfloat162float(t1.x), p03 - __bfloat162float(t1.y));
            apl[2] = pack2(p10 - __bfloat162float(t2.x), p11 - __bfloat162float(t2.y));
            apl[3] = pack2(p12 - __bfloat162float(t3.x), p13 - __bfloat162float(t3.y));
            uint32_t vh[4][4], vl[4][4];
#pragma unroll
            for (int dg = 0; dg < 4; dg++) {
                uint32_t boff = swz((dg * 16 + rbn) * 128 + (kc * 16 + kbn) * 2);
                ldm4(vh[dg], Vh + boff);
                ldm4(vl[dg], Vl + boff);
            }
#pragma unroll
            for (int dt = 0; dt < 8; dt++) {
                int pr = dt >> 1, oo = (dt & 1) * 2;
                mma16816(o[dt], aph, vh[pr][oo], vh[pr][oo + 1]);
                mma16816(o[dt], aph, vl[pr][oo], vl[pr][oo + 1]);
                mma16816(o[dt], apl, vh[pr][oo], vh[pr][oo + 1]);
            }
        }
    }

    float inv0 = 1.f / l0, inv1 = 1.f / l1;
    size_t row0 = (size_t)b * SS + qt * 64 + w * 16 + r0;
    size_t row1 = row0 + 8;
#pragma unroll
    for (int dt = 0; dt < 8; dt++) {
        int d = hoff + dt * 8 + c0;
        __nv_bfloat16 h0, lo0, h1, lo1;
        split_bf16(o[dt][0] * inv0, &h0, &lo0);
        split_bf16(o[dt][1] * inv0, &h1, &lo1);
        *(__nv_bfloat162*)&ohi[row0 * EE + d] = __nv_bfloat162(h0, h1);
        *(__nv_bfloat162*)&olo[row0 * EE + d] = __nv_bfloat162(lo0, lo1);
        split_bf16(o[dt][2] * inv1, &h0, &lo0);
        split_bf16(o[dt][3] * inv1, &h1, &lo1);
        *(__nv_bfloat162*)&ohi[row1 * EE + d] = __nv_bfloat162(h0, h1);
        *(__nv_bfloat162*)&olo[row1 * EE + d] = __nv_bfloat162(lo0, lo1);
    }
}

// ---------------- launch ----------------
extern "C" void kernel_launch(void* const* d_in, const int* in_sizes, int n_in,
                              void* d_out, int out_size) {
    const float* x = (const float*)d_in[0];
    const float* Wq = (const float*)d_in[1];
    const float* bq = (const float*)d_in[2];
    const float* Wk = (const float*)d_in[3];
    const float* bk = (const float*)d_in[4];
    const float* Wv = (const float*)d_in[5];
    const float* bv = (const float*)d_in[6];
    const float* Wp = (const float*)d_in[7];
    const float* bp = (const float*)d_in[8];
    const float* ln1_g = (const float*)d_in[9];
    const float* ln1_b = (const float*)d_in[10];
    const float* ln2_g = (const float*)d_in[11];
    const float* ln2_b = (const float*)d_in[12];
    const float* W1 = (const float*)d_in[13];
    const float* b1 = (const float*)d_in[14];
    const float* W2 = (const float*)d_in[15];
    const float* b2 = (const float*)d_in[16];
    const float* lnf_g = (const float*)d_in[17];
    const float* lnf_b = (const float*)d_in[18];
    float* out = (float*)d_out;

    __nv_bfloat16 *p_ahi, *p_alo, *p_fhi, *p_flo;
    __nv_bfloat16 *p_wqh, *p_wql, *p_wph, *p_wpl, *p_w1h, *p_w1l, *p_w2h, *p_w2l;
    float *p_bqkv, *p_qkv, *p_x1, *p_f2;
    cudaGetSymbolAddress((void**)&p_ahi, g_ahi);
    cudaGetSymbolAddress((void**)&p_alo, g_alo);
    cudaGetSymbolAddress((void**)&p_fhi, g_fhi);
    cudaGetSymbolAddress((void**)&p_flo, g_flo);
    cudaGetSymbolAddress((void**)&p_wqh, g_wqkvt_hi);
    cudaGetSymbolAddress((void**)&p_wql, g_wqkvt_lo);
    cudaGetSymbolAddress((void**)&p_wph, g_wpt_hi);
    cudaGetSymbolAddress((void**)&p_wpl, g_wpt_lo);
    cudaGetSymbolAddress((void**)&p_w1h, g_w1t_hi);
    cudaGetSymbolAddress((void**)&p_w1l, g_w1t_lo);
    cudaGetSymbolAddress((void**)&p_w2h, g_w2t_hi);
    cudaGetSymbolAddress((void**)&p_w2l, g_w2t_lo);
    cudaGetSymbolAddress((void**)&p_bqkv, g_bqkv);
    cudaGetSymbolAddress((void**)&p_qkv, g_qkv);
    cudaGetSymbolAddress((void**)&p_x1, g_x1);
    cudaGetSymbolAddress((void**)&p_f2, g_f2);

    int gsmem = 2 * STG;
    cudaFuncSetAttribute(tcgemm<0>, cudaFuncAttributeMaxDynamicSharedMemorySize, gsmem);
    cudaFuncSetAttribute(tcgemm<1>, cudaFuncAttributeMaxDynamicSharedMemorySize, gsmem);
    cudaFuncSetAttribute(tcgemm<2>, cudaFuncAttributeMaxDynamicSharedMemorySize, gsmem);
    int asmem = 49152;
    cudaFuncSetAttribute(attn_kernel, cudaFuncAttributeMaxDynamicSharedMemorySize, asmem);

    pack_wqkv_kernel<<<(QKV_N * EE + 255) / 256, 256>>>(Wq, Wk, Wv, bq, bk, bv);
    transpose_pair_kernel<<<(EE * EE + 255) / 256, 256>>>(Wp, p_wph, p_wpl, EE, EE);
    transpose_pair_kernel<<<(EE * FF + 255) / 256, 256>>>(W1, p_w1h, p_w1l, EE, FF);
    transpose_pair_kernel<<<(FF * EE + 255) / 256, 256>>>(W2, p_w2h, p_w2l, FF, EE);

    ln_pair_kernel<<<ROWS, 256>>>(x, ln1_g, ln1_b, p_ahi, p_alo);
    tcgemm<0><<<dim3(QKV_N / 128, ROWS / 128), 256, gsmem>>>(
        p_ahi, p_alo, p_wqh, p_wql, p_bqkv, nullptr, p_qkv, nullptr, nullptr, QKV_N, EE);
    attn_kernel<<<dim3(SS / 64, BB * HH), 128, asmem>>>(p_qkv, p_ahi, p_alo);
    tcgemm<2><<<dim3(EE / 128, ROWS / 128), 256, gsmem>>>(
        p_ahi, p_alo, p_wph, p_wpl, bp, x, p_x1, nullptr, nullptr, EE, EE);
    ln_pair_kernel<<<ROWS, 256>>>(p_x1, ln2_g, ln2_b, p_ahi, p_alo);
    tcgemm<1><<<dim3(FF / 128, ROWS / 128), 256, gsmem>>>(
        p_ahi, p_alo, p_w1h, p_w1l, b1, nullptr, nullptr, p_fhi, p_flo, FF, EE);
    tcgemm<0><<<dim3(EE / 128, ROWS / 128), 256, gsmem>>>(
        p_fhi, p_flo, p_w2h, p_w2l, b2, nullptr, p_f2, nullptr, nullptr, EE, FF);
    ln_final_kernel<<<ROWS, 256>>>(p_f2, lnf_g, lnf_b, p_x1, out);
}

// round 7
// speedup vs baseline: 5.4662x; 1.2723x over previous
#include <cuda_runtime.h>
#include <cuda_fp16.h>
#include <math.h>
#include <stdint.h>

#define BB 16
#define SS 1024
#define EE 768
#define HH 12
#define DD 64
#define FF 3072
#define ROWS (BB * SS)
#define QKV_N (3 * EE)

// scratch
__device__ __half g_ahi[ROWS * EE], g_alo[ROWS * EE];      // activation hi/lo
__device__ __half g_fhi[ROWS * FF], g_flo[ROWS * FF];      // ffn1 out hi/lo
__device__ __half g_wqkvt[QKV_N * EE];                     // weights: fp16 hi only, [N][K]
__device__ __half g_wpt[EE * EE];
__device__ __half g_w1t[FF * EE];
__device__ __half g_w2t[EE * FF];
__device__ float g_bqkv[QKV_N];
__device__ float g_qkv[ROWS * QKV_N];
__device__ float g_x1[ROWS * EE];
__device__ float g_f2[ROWS * EE];

__device__ __forceinline__ void split_f16(float v, __half* hi, __half* lo) {
    __half h = __float2half_rn(v);
    *hi = h;
    *lo = __float2half_rn(v - __half2float(h));
}
__device__ __forceinline__ uint32_t swz(uint32_t o) { return o ^ ((o >> 3) & 0x70); }
__device__ __forceinline__ uint32_t pack2(float x, float y) {
    __half2 t = __floats2half2_rn(x, y);
    return *(uint32_t*)&t;
}

// ---------------- weight prep ----------------
__global__ void pack_wqkv_kernel(const float* __restrict__ Wq, const float* __restrict__ Wk,
                                 const float* __restrict__ Wv, const float* __restrict__ bq,
                                 const float* __restrict__ bk, const float* __restrict__ bv) {
    int idx = blockIdx.x * blockDim.x + threadIdx.x;
    if (idx < QKV_N * EE) {
        int n = idx / EE, e = idx % EE;
        int sec = n / 768;
        int hd = n % 768;
        const float* W = (sec == 0) ? Wq : (sec == 1) ? Wk : Wv;
        g_wqkvt[idx] = __float2half_rn(W[((hd >> 6) * EE + e) * DD + (hd & 63)]);
    }
    if (idx < QKV_N) {
        int sec = idx / 768;
        const float* bsrc = (sec == 0) ? bq : (sec == 1) ? bk : bv;
        g_bqkv[idx] = bsrc[idx % 768];
    }
}

__global__ void transpose_h_kernel(const float* __restrict__ in,
                                   __half* __restrict__ oh, int K, int N) {
    int idx = blockIdx.x * blockDim.x + threadIdx.x;
    if (idx >= N * K) return;
    int n = idx / K, k = idx % K;
    oh[idx] = __float2half_rn(in[(size_t)k * N + n]);
}

// ---------------- LN ----------------
__device__ __forceinline__ float block_reduce_sum_256(float v, float* sbuf) {
    int lane = threadIdx.x & 31, wid = threadIdx.x >> 5;
#pragma unroll
    for (int m = 16; m; m >>= 1) v += __shfl_xor_sync(0xffffffffu, v, m);
    if (lane == 0) sbuf[wid] = v;
    __syncthreads();
    if (wid == 0) {
        v = (lane < 8) ? sbuf[lane] : 0.f;
#pragma unroll
        for (int m = 4; m; m >>= 1) v += __shfl_xor_sync(0xffffffffu, v, m);
        if (lane == 0) sbuf[0] = v;
    }
    __syncthreads();
    float r = sbuf[0];
    __syncthreads();
    return r;
}

__global__ void __launch_bounds__(256) ln_pair_kernel(const float* __restrict__ in,
                                                      const float* __restrict__ gam,
                                                      const float* __restrict__ bet,
                                                      __half* __restrict__ ohi,
                                                      __half* __restrict__ olo) {
    __shared__ float sbuf[8];
    size_t row = blockIdx.x;
    const float* x = in + row * EE;
    float s = 0.f;
    for (int i = threadIdx.x; i < EE; i += 256) s += x[i];
    float mu = block_reduce_sum_256(s, sbuf) * (1.f / EE);
    float v = 0.f;
    for (int i = threadIdx.x; i < EE; i += 256) { float d = x[i] - mu; v += d * d; }
    float rstd = rsqrtf(block_reduce_sum_256(v, sbuf) * (1.f / EE) + 1e-5f);
    for (int i = threadIdx.x; i < EE; i += 256) {
        float y = (x[i] - mu) * rstd * gam[i] + bet[i];
        split_f16(y, &ohi[row * EE + i], &olo[row * EE + i]);
    }
}

__global__ void __launch_bounds__(256) ln_final_kernel(const float* __restrict__ in,
                                                       const float* __restrict__ gam,
                                                       const float* __restrict__ bet,
                                                       const float* __restrict__ res,
                                                       float* __restrict__ out) {
    __shared__ float sbuf[8];
    size_t row = blockIdx.x;
    const float* x = in + row * EE;
    float s = 0.f;
    for (int i = threadIdx.x; i < EE; i += 256) s += x[i];
    float mu = block_reduce_sum_256(s, sbuf) * (1.f / EE);
    float v = 0.f;
    for (int i = threadIdx.x; i < EE; i += 256) { float d = x[i] - mu; v += d * d; }
    float rstd = rsqrtf(block_reduce_sum_256(v, sbuf) * (1.f / EE) + 1e-5f);
    for (int i = threadIdx.x; i < EE; i += 256)
        out[row * EE + i] = (x[i] - mu) * rstd * gam[i] + bet[i] + res[row * EE + i];
}

// ---------------- HMMA primitives (fp16) ----------------
__device__ __forceinline__ void cpasync16(uint32_t dst, const void* src) {
    asm volatile("cp.async.cg.shared.global [%0], [%1], 16;" :: "r"(dst), "l"(src));
}
__device__ __forceinline__ void ldm4(uint32_t* r, uint32_t addr) {
    asm volatile("ldmatrix.sync.aligned.m8n8.x4.shared.b16 {%0,%1,%2,%3}, [%4];"
                 : "=r"(r[0]), "=r"(r[1]), "=r"(r[2]), "=r"(r[3]) : "r"(addr));
}
__device__ __forceinline__ void mma16816(float* d, const uint32_t* a, uint32_t b0, uint32_t b1) {
    asm volatile(
        "mma.sync.aligned.m16n8k16.row.col.f32.f16.f16.f32 "
        "{%0,%1,%2,%3}, {%4,%5,%6,%7}, {%8,%9}, {%0,%1,%2,%3};"
        : "+f"(d[0]), "+f"(d[1]), "+f"(d[2]), "+f"(d[3])
        : "r"(a[0]), "r"(a[1]), "r"(a[2]), "r"(a[3]), "r"(b0), "r"(b1));
}

// ---------------- HMMA GEMM (fp16 2-pass split: AhBh + AlBh) ----------------
// A split hi/lo; B single fp16. 128x128 tile, BK=64, 3-stage cp.async pipeline.
// EPI: 0 bias->f32, 1 bias+gelu->fp16 pair, 2 bias+res->f32
#define STG 49152   // Ah 16K | Al 16K | Bh 16K

template <int EPI>
__global__ void __launch_bounds__(256, 1) tcgemm(const __half* __restrict__ Ahi,
                                                 const __half* __restrict__ Alo,
                                                 const __half* __restrict__ Bh,
                                                 const float* __restrict__ bias,
                                                 const float* __restrict__ res,
                                                 float* __restrict__ C,
                                                 __half* __restrict__ Chi,
                                                 __half* __restrict__ Clo,
                                                 int N, int K) {
    extern __shared__ char sm[];
    uint32_t sbase = (uint32_t)__cvta_generic_to_shared(sm);
    int tid = threadIdx.x;
    int lane = tid & 31, w = tid >> 5;
    int wm = w >> 2, wn = w & 3;
    int bn = blockIdx.x * 128, bm = blockIdx.y * 128;

    const __half* srcs[3] = {Ahi, Alo, Bh};

    float acc[4][4][4];
#pragma unroll
    for (int i = 0; i < 4; i++)
#pragma unroll
        for (int j = 0; j < 4; j++)
#pragma unroll
            for (int q = 0; q < 4; q++) acc[i][j][q] = 0.f;

    int nk = K >> 6;

#define LOAD_STAGE(kc, buf)                                                          \
    {                                                                                \
        uint32_t sb_ = sbase + (buf) * STG;                                          \
        _Pragma("unroll")                                                            \
        for (int ii = 0; ii < 12; ii++) {                                            \
            int i = tid + ii * 256;                                                  \
            int t = i >> 10, wrd = i & 1023, r = wrd >> 3, c = wrd & 7;              \
            int rb = (t < 2) ? bm : bn;                                              \
            const __half* sp = srcs[t] + (size_t)(rb + r) * K + (kc) * 64 + c * 8;   \
            cpasync16(sb_ + t * 16384 + swz(r * 128 + c * 16), sp);                  \
        }                                                                            \
        asm volatile("cp.async.commit_group;" ::: "memory");                         \
    }

    LOAD_STAGE(0, 0);
    LOAD_STAGE(1, 1);

    int ra = (lane & 7) + ((lane & 8) ? 8 : 0);
    int ka = (lane & 16) ? 8 : 0;
    int rb_n = (lane & 7) + ((lane & 16) ? 8 : 0);
    int kb_n = (lane & 8) ? 8 : 0;

    int buf = 0;
    for (int kc = 0; kc < nk; kc++) {
        if (kc + 2 < nk) {
            int nb = buf + 2;
            if (nb >= 3) nb -= 3;
            LOAD_STAGE(kc + 2, nb);
            asm volatile("cp.async.wait_group 2;" ::: "memory");
        } else if (kc + 1 < nk) {
            asm volatile("cp.async.wait_group 1;" ::: "memory");
        } else {
            asm volatile("cp.async.wait_group 0;" ::: "memory");
        }
        __syncthreads();
        uint32_t sb = sbase + buf * STG;
#pragma unroll
        for (int ks = 0; ks < 4; ks++) {
            uint32_t Ah[4][4], Al[4][4], Bf[2][4];
#pragma unroll
            for (int mt = 0; mt < 4; mt++) {
                int row = wm * 64 + mt * 16 + ra;
                uint32_t off = swz(row * 128 + (ks * 16 + ka) * 2);
                ldm4(Ah[mt], sb + off);
                ldm4(Al[mt], sb + 16384 + off);
            }
#pragma unroll
            for (int pr = 0; pr < 2; pr++) {
                int row = wn * 32 + pr * 16 + rb_n;
                uint32_t off = swz(row * 128 + (ks * 16 + kb_n) * 2);
                ldm4(Bf[pr], sb + 32768 + off);
            }
#pragma unroll
            for (int mt = 0; mt < 4; mt++)
#pragma unroll
                for (int nt = 0; nt < 4; nt++) {
                    int pr = nt >> 1, o = (nt & 1) * 2;
                    mma16816(acc[mt][nt], Ah[mt], Bf[pr][o], Bf[pr][o + 1]);
                    mma16816(acc[mt][nt], Al[mt], Bf[pr][o], Bf[pr][o + 1]);
                }
        }
        __syncthreads();
        if (++buf == 3) buf = 0;
    }

    int l4 = lane >> 2, l2 = (lane & 3) * 2;
#pragma unroll
    for (int mt = 0; mt < 4; mt++)
#pragma unroll
        for (int nt = 0; nt < 4; nt++) {
            int col = bn + wn * 32 + nt * 8 + l2;
            float b0 = bias[col], b1 = bias[col + 1];
#pragma unroll
            for (int half = 0; half < 2; half++) {
                size_t row = (size_t)(bm + wm * 64 + mt * 16 + l4 + half * 8);
                float v0 = acc[mt][nt][half * 2 + 0] + b0;
                float v1 = acc[mt][nt][half * 2 + 1] + b1;
                if (EPI == 2) {
                    v0 += res[row * N + col];
                    v1 += res[row * N + col + 1];
                }
                if (EPI == 1) {
                    v0 = 0.5f * v0 * (1.0f + erff(v0 * 0.70710678118654752f));
                    v1 = 0.5f * v1 * (1.0f + erff(v1 * 0.70710678118654752f));
                    __half h0, l0, h1, l1;
                    split_f16(v0, &h0, &l0);
                    split_f16(v1, &h1, &l1);
                    *(__half2*)&Chi[row * N + col] = __half2(h0, h1);
                    *(__half2*)&Clo[row * N + col] = __half2(l0, l1);
                } else {
                    *(float2*)&C[row * N + col] = make_float2(v0, v1);
                }
            }
        }
#undef LOAD_STAGE
}

// ---------------- HMMA flash attention (fp16 2-pass) ----------------
// grid (S/64, B*H), 128 threads. smem: Qh Ql [r][d], Kh [t][d], Vh [d][t] = 32KB.
__global__ void __launch_bounds__(128) attn_kernel(const float* __restrict__ qkv,
                                                   __half* __restrict__ ohi,
                                                   __half* __restrict__ olo) {
    extern __shared__ char smc[];
    uint32_t sb = (uint32_t)__cvta_generic_to_shared(smc);
    uint32_t Qh = sb, Ql = sb + 8192;
    uint32_t Kh = sb + 16384, Vh = sb + 24576;

    int qt = blockIdx.x, bh = blockIdx.y;
    int b = bh / HH, h = bh % HH;
    int tid = threadIdx.x, lane = tid & 31, w = tid >> 5;
    size_t base = (size_t)b * SS * QKV_N;
    int hoff = h * DD;

    for (int i = tid; i < 4096; i += 128) {
        int r = i >> 6, d = i & 63;
        float v = qkv[base + (size_t)(qt * 64 + r) * QKV_N + hoff + d] * 0.125f;
        __half hi, lo;
        split_f16(v, &hi, &lo);
        uint32_t off = swz(r * 128 + d * 2);
        *(__half*)(smc + off) = hi;
        *(__half*)(smc + 8192 + off) = lo;
    }

    int ra = (lane & 7) + ((lane & 8) ? 8 : 0);
    int ka = (lane & 16) ? 8 : 0;
    int rbn = (lane & 7) + ((lane & 16) ? 8 : 0);
    int kbn = (lane & 8) ? 8 : 0;
    int r0 = lane >> 2, c0 = (lane & 3) * 2;

    float m0 = -1e30f, m1 = -1e30f, l0 = 0.f, l1 = 0.f;
    float o[8][4];
#pragma unroll
    for (int i = 0; i < 8; i++)
#pragma unroll
        for (int j = 0; j < 4; j++) o[i][j] = 0.f;

    for (int kt = 0; kt <= qt; kt++) {
        __syncthreads();
        for (int i = tid; i < 4096; i += 128) {
            int r = i >> 6, d = i & 63;
            size_t off = base + (size_t)(kt * 64 + r) * QKV_N + hoff + d;
            *(__half*)(smc + 16384 + swz(r * 128 + d * 2)) = __float2half_rn(qkv[off + EE]);
            *(__half*)(smc + 24576 + swz(d * 128 + r * 2)) = __float2half_rn(qkv[off + 2 * EE]);
        }
        __syncthreads();

        float s[8][4];
#pragma unroll
        for (int i = 0; i < 8; i++)
#pragma unroll
            for (int j = 0; j < 4; j++) s[i][j] = 0.f;
#pragma unroll
        for (int kc = 0; kc < 4; kc++) {
            uint32_t qh[4], ql[4], kh[4][4];
            uint32_t aoff = swz((w * 16 + ra) * 128 + (kc * 16 + ka) * 2);
            ldm4(qh, Qh + aoff);
            ldm4(ql, Ql + aoff);
#pragma unroll
            for (int tg = 0; tg < 4; tg++) {
                uint32_t boff = swz((tg * 16 + rbn) * 128 + (kc * 16 + kbn) * 2);
                ldm4(kh[tg], Kh + boff);
            }
#pragma unroll
            for (int nt = 0; nt < 8; nt++) {
                int pr = nt >> 1, oo = (nt & 1) * 2;
                mma16816(s[nt], qh, kh[pr][oo], kh[pr][oo + 1]);
                mma16816(s[nt], ql, kh[pr][oo], kh[pr][oo + 1]);
            }
        }

        if (kt == qt) {
            int row0 = w * 16 + r0, row1 = row0 + 8;
#pragma unroll
            for (int nt = 0; nt < 8; nt++) {
                int c = nt * 8 + c0;
                if (c > row0) s[nt][0] = -1e30f;
                if (c + 1 > row0) s[nt][1] = -1e30f;
                if (c > row1) s[nt][2] = -1e30f;
                if (c + 1 > row1) s[nt][3] = -1e30f;
            }
        }

        float mt0 = -1e30f, mt1 = -1e30f;
#pragma unroll
        for (int nt = 0; nt < 8; nt++) {
            mt0 = fmaxf(mt0, fmaxf(s[nt][0], s[nt][1]));
            mt1 = fmaxf(mt1, fmaxf(s[nt][2], s[nt][3]));
        }
#pragma unroll
        for (int off = 1; off <= 2; off <<= 1) {
            mt0 = fmaxf(mt0, __shfl_xor_sync(0xffffffffu, mt0, off));
            mt1 = fmaxf(mt1, __shfl_xor_sync(0xffffffffu, mt1, off));
        }
        float mn0 = fmaxf(m0, mt0), mn1 = fmaxf(m1, mt1);
        float sc0 = __expf(m0 - mn0), sc1 = __expf(m1 - mn1);
        float rs0 = 0.f, rs1 = 0.f;
#pragma unroll
        for (int nt = 0; nt < 8; nt++) {
            s[nt][0] = __expf(s[nt][0] - mn0);
            s[nt][1] = __expf(s[nt][1] - mn0);
            s[nt][2] = __expf(s[nt][2] - mn1);
            s[nt][3] = __expf(s[nt][3] - mn1);
            rs0 += s[nt][0] + s[nt][1];
            rs1 += s[nt][2] + s[nt][3];
        }
#pragma unroll
        for (int off = 1; off <= 2; off <<= 1) {
            rs0 += __shfl_xor_sync(0xffffffffu, rs0, off);
            rs1 += __shfl_xor_sync(0xffffffffu, rs1, off);
        }
        l0 = l0 * sc0 + rs0;
        l1 = l1 * sc1 + rs1;
        m0 = mn0;
        m1 = mn1;
#pragma unroll
        for (int i = 0; i < 8; i++) {
            o[i][0] *= sc0; o[i][1] *= sc0;
            o[i][2] *= sc1; o[i][3] *= sc1;
        }

#pragma unroll
        for (int kc = 0; kc < 4; kc++) {
            float p00 = s[2 * kc][0], p01 = s[2 * kc][1];
            float p02 = s[2 * kc][2], p03 = s[2 * kc][3];
            float p10 = s[2 * kc + 1][0], p11 = s[2 * kc + 1][1];
            float p12 = s[2 * kc + 1][2], p13 = s[2 * kc + 1][3];
            uint32_t aph[4], apl[4];
            aph[0] = pack2(p00, p01);
            aph[1] = pack2(p02, p03);
            aph[2] = pack2(p10, p11);
            aph[3] = pack2(p12, p13);
            __half2 t0 = *(__half2*)&aph[0];
            __half2 t1 = *(__half2*)&aph[1];
            __half2 t2 = *(__half2*)&aph[2];
            __half2 t3 = *(__half2*)&aph[3];
            apl[0] = pack2(p00 - __half2float(t0.x), p01 - __half2float(t0.y));
            apl[1] = pack2(p02 - __half2float(t1.x), p03 - __half2float(t1.y));
            apl[2] = pack2(p10 - __half2float(t2.x), p11 - __half2float(t2.y));
            apl[3] = pack2(p12 - __half2float(t3.x), p13 - __half2float(t3.y));
            uint32_t vh[4][4];
#pragma unroll
            for (int dg = 0; dg < 4; dg++) {
                uint32_t boff = swz((dg * 16 + rbn) * 128 + (kc * 16 + kbn) * 2);
                ldm4(vh[dg], Vh + boff);
            }
#pragma unroll
            for (int dt = 0; dt < 8; dt++) {
                int pr = dt >> 1, oo = (dt & 1) * 2;
                mma16816(o[dt], aph, vh[pr][oo], vh[pr][oo + 1]);
                mma16816(o[dt], apl, vh[pr][oo], vh[pr][oo + 1]);
            }
        }
    }

    float inv0 = 1.f / l0, inv1 = 1.f / l1;
    size_t row0 = (size_t)b * SS + qt * 64 + w * 16 + r0;
    size_t row1 = row0 + 8;
#pragma unroll
    for (int dt = 0; dt < 8; dt++) {
        int d = hoff + dt * 8 + c0;
        __half h0, lo0, h1, lo1;
        split_f16(o[dt][0] * inv0, &h0, &lo0);
        split_f16(o[dt][1] * inv0, &h1, &lo1);
        *(__half2*)&ohi[row0 * EE + d] = __half2(h0, h1);
        *(__half2*)&olo[row0 * EE + d] = __half2(lo0, lo1);
        split_f16(o[dt][2] * inv1, &h0, &lo0);
        split_f16(o[dt][3] * inv1, &h1, &lo1);
        *(__half2*)&ohi[row1 * EE + d] = __half2(h0, h1);
        *(__half2*)&olo[row1 * EE + d] = __half2(lo0, lo1);
    }
}

// ---------------- launch ----------------
extern "C" void kernel_launch(void* const* d_in, const int* in_sizes, int n_in,
                              void* d_out, int out_size) {
    const float* x = (const float*)d_in[0];
    const float* Wq = (const float*)d_in[1];
    const float* bq = (const float*)d_in[2];
    const float* Wk = (const float*)d_in[3];
    const float* bk = (const float*)d_in[4];
    const float* Wv = (const float*)d_in[5];
    const float* bv = (const float*)d_in[6];
    const float* Wp = (const float*)d_in[7];
    const float* bp = (const float*)d_in[8];
    const float* ln1_g = (const float*)d_in[9];
    const float* ln1_b = (const float*)d_in[10];
    const float* ln2_g = (const float*)d_in[11];
    const float* ln2_b = (const float*)d_in[12];
    const float* W1 = (const float*)d_in[13];
    const float* b1 = (const float*)d_in[14];
    const float* W2 = (const float*)d_in[15];
    const float* b2 = (const float*)d_in[16];
    const float* lnf_g = (const float*)d_in[17];
    const float* lnf_b = (const float*)d_in[18];
    float* out = (float*)d_out;

    __half *p_ahi, *p_alo, *p_fhi, *p_flo, *p_wq, *p_wp, *p_w1, *p_w2;
    float *p_bqkv, *p_qkv, *p_x1, *p_f2;
    cudaGetSymbolAddress((void**)&p_ahi, g_ahi);
    cudaGetSymbolAddress((void**)&p_alo, g_alo);
    cudaGetSymbolAddress((void**)&p_fhi, g_fhi);
    cudaGetSymbolAddress((void**)&p_flo, g_flo);
    cudaGetSymbolAddress((void**)&p_wq, g_wqkvt);
    cudaGetSymbolAddress((void**)&p_wp, g_wpt);
    cudaGetSymbolAddress((void**)&p_w1, g_w1t);
    cudaGetSymbolAddress((void**)&p_w2, g_w2t);
    cudaGetSymbolAddress((void**)&p_bqkv, g_bqkv);
    cudaGetSymbolAddress((void**)&p_qkv, g_qkv);
    cudaGetSymbolAddress((void**)&p_x1, g_x1);
    cudaGetSymbolAddress((void**)&p_f2, g_f2);

    int gsmem = 3 * STG;  // 147456
    cudaFuncSetAttribute(tcgemm<0>, cudaFuncAttributeMaxDynamicSharedMemorySize, gsmem);
    cudaFuncSetAttribute(tcgemm<1>, cudaFuncAttributeMaxDynamicSharedMemorySize, gsmem);
    cudaFuncSetAttribute(tcgemm<2>, cudaFuncAttributeMaxDynamicSharedMemorySize, gsmem);
    int asmem = 32768;
    cudaFuncSetAttribute(attn_kernel, cudaFuncAttributeMaxDynamicSharedMemorySize, asmem);

    pack_wqkv_kernel<<<(QKV_N * EE + 255) / 256, 256>>>(Wq, Wk, Wv, bq, bk, bv);
    transpose_h_kernel<<<(EE * EE + 255) / 256, 256>>>(Wp, p_wp, EE, EE);
    transpose_h_kernel<<<(EE * FF + 255) / 256, 256>>>(W1, p_w1, EE, FF);
    transpose_h_kernel<<<(FF * EE + 255) / 256, 256>>>(W2, p_w2, FF, EE);

    ln_pair_kernel<<<ROWS, 256>>>(x, ln1_g, ln1_b, p_ahi, p_alo);
    tcgemm<0><<<dim3(QKV_N / 128, ROWS / 128), 256, gsmem>>>(
        p_ahi, p_alo, p_wq, p_bqkv, nullptr, p_qkv, nullptr, nullptr, QKV_N, EE);
    attn_kernel<<<dim3(SS / 64, BB * HH), 128, asmem>>>(p_qkv, p_ahi, p_alo);
    tcgemm<2><<<dim3(EE / 128, ROWS / 128), 256, gsmem>>>(
        p_ahi, p_alo, p_wp, bp, x, p_x1, nullptr, nullptr, EE, EE);
    ln_pair_kernel<<<ROWS, 256>>>(p_x1, ln2_g, ln2_b, p_ahi, p_alo);
    tcgemm<1><<<dim3(FF / 128, ROWS / 128), 256, gsmem>>>(
        p_ahi, p_alo, p_w1, b1, nullptr, nullptr, p_fhi, p_flo, FF, EE);
    tcgemm<0><<<dim3(EE / 128, ROWS / 128), 256, gsmem>>>(
        p_fhi, p_flo, p_w2, b2, nullptr, p_f2, nullptr, nullptr, EE, FF);
    ln_final_kernel<<<ROWS, 256>>>(p_f2, lnf_g, lnf_b, p_x1, out);
}

// round 8
// speedup vs baseline: 7.5992x; 1.3902x over previous
#include <cuda_runtime.h>
#include <cuda_fp16.h>
#include <math.h>
#include <stdint.h>

#define BB 16
#define SS 1024
#define EE 768
#define HH 12
#define DD 64
#define FF 3072
#define ROWS (BB * SS)
#define QKV_N (3 * EE)

// scratch
__device__ __half g_ah[ROWS * EE];          // activation fp16 (LN out / attn out)
__device__ __half g_fh[ROWS * FF];          // ffn1 out fp16
__device__ __half g_wqkvt[QKV_N * EE];      // weights fp16, [N][K]
__device__ __half g_wpt[EE * EE];
__device__ __half g_w1t[FF * EE];
__device__ __half g_w2t[EE * FF];
__device__ float g_bqkv[QKV_N];
__device__ float g_qkv[ROWS * QKV_N];
__device__ float g_x1[ROWS * EE];
__device__ float g_f2[ROWS * EE];

__device__ __forceinline__ void split_f16(float v, __half* hi, __half* lo) {
    __half h = __float2half_rn(v);
    *hi = h;
    *lo = __float2half_rn(v - __half2float(h));
}
__device__ __forceinline__ uint32_t swz(uint32_t o) { return o ^ ((o >> 3) & 0x70); }
__device__ __forceinline__ uint32_t pack2(float x, float y) {
    __half2 t = __floats2half2_rn(x, y);
    return *(uint32_t*)&t;
}

// ---------------- weight prep ----------------
__global__ void pack_wqkv_kernel(const float* __restrict__ Wq, const float* __restrict__ Wk,
                                 const float* __restrict__ Wv, const float* __restrict__ bq,
                                 const float* __restrict__ bk, const float* __restrict__ bv) {
    int idx = blockIdx.x * blockDim.x + threadIdx.x;
    if (idx < QKV_N * EE) {
        int n = idx / EE, e = idx % EE;
        int sec = n / 768;
        int hd = n % 768;
        const float* W = (sec == 0) ? Wq : (sec == 1) ? Wk : Wv;
        g_wqkvt[idx] = __float2half_rn(W[((hd >> 6) * EE + e) * DD + (hd & 63)]);
    }
    if (idx < QKV_N) {
        int sec = idx / 768;
        const float* bsrc = (sec == 0) ? bq : (sec == 1) ? bk : bv;
        g_bqkv[idx] = bsrc[idx % 768];
    }
}

__global__ void transpose_h_kernel(const float* __restrict__ in,
                                   __half* __restrict__ oh, int K, int N) {
    int idx = blockIdx.x * blockDim.x + threadIdx.x;
    if (idx >= N * K) return;
    int n = idx / K, k = idx % K;
    oh[idx] = __float2half_rn(in[(size_t)k * N + n]);
}

// ---------------- LN ----------------
__device__ __forceinline__ float block_reduce_sum_256(float v, float* sbuf) {
    int lane = threadIdx.x & 31, wid = threadIdx.x >> 5;
#pragma unroll
    for (int m = 16; m; m >>= 1) v += __shfl_xor_sync(0xffffffffu, v, m);
    if (lane == 0) sbuf[wid] = v;
    __syncthreads();
    if (wid == 0) {
        v = (lane < 8) ? sbuf[lane] : 0.f;
#pragma unroll
        for (int m = 4; m; m >>= 1) v += __shfl_xor_sync(0xffffffffu, v, m);
        if (lane == 0) sbuf[0] = v;
    }
    __syncthreads();
    float r = sbuf[0];
    __syncthreads();
    return r;
}

__global__ void __launch_bounds__(256) ln_h_kernel(const float* __restrict__ in,
                                                   const float* __restrict__ gam,
                                                   const float* __restrict__ bet,
                                                   __half* __restrict__ oh) {
    __shared__ float sbuf[8];
    size_t row = blockIdx.x;
    const float* x = in + row * EE;
    float s = 0.f;
    for (int i = threadIdx.x; i < EE; i += 256) s += x[i];
    float mu = block_reduce_sum_256(s, sbuf) * (1.f / EE);
    float v = 0.f;
    for (int i = threadIdx.x; i < EE; i += 256) { float d = x[i] - mu; v += d * d; }
    float rstd = rsqrtf(block_reduce_sum_256(v, sbuf) * (1.f / EE) + 1e-5f);
    for (int i = threadIdx.x; i < EE; i += 256)
        oh[row * EE + i] = __float2half_rn((x[i] - mu) * rstd * gam[i] + bet[i]);
}

__global__ void __launch_bounds__(256) ln_final_kernel(const float* __restrict__ in,
                                                       const float* __restrict__ gam,
                                                       const float* __restrict__ bet,
                                                       const float* __restrict__ res,
                                                       float* __restrict__ out) {
    __shared__ float sbuf[8];
    size_t row = blockIdx.x;
    const float* x = in + row * EE;
    float s = 0.f;
    for (int i = threadIdx.x; i < EE; i += 256) s += x[i];
    float mu = block_reduce_sum_256(s, sbuf) * (1.f / EE);
    float v = 0.f;
    for (int i = threadIdx.x; i < EE; i += 256) { float d = x[i] - mu; v += d * d; }
    float rstd = rsqrtf(block_reduce_sum_256(v, sbuf) * (1.f / EE) + 1e-5f);
    for (int i = threadIdx.x; i < EE; i += 256)
        out[row * EE + i] = (x[i] - mu) * rstd * gam[i] + bet[i] + res[row * EE + i];
}

// ---------------- HMMA primitives (fp16) ----------------
__device__ __forceinline__ void cpasync16(uint32_t dst, const void* src) {
    asm volatile("cp.async.cg.shared.global [%0], [%1], 16;" :: "r"(dst), "l"(src));
}
__device__ __forceinline__ void ldm4(uint32_t* r, uint32_t addr) {
    asm volatile("ldmatrix.sync.aligned.m8n8.x4.shared.b16 {%0,%1,%2,%3}, [%4];"
                 : "=r"(r[0]), "=r"(r[1]), "=r"(r[2]), "=r"(r[3]) : "r"(addr));
}
__device__ __forceinline__ void mma16816(float* d, const uint32_t* a, uint32_t b0, uint32_t b1) {
    asm volatile(
        "mma.sync.aligned.m16n8k16.row.col.f32.f16.f16.f32 "
        "{%0,%1,%2,%3}, {%4,%5,%6,%7}, {%8,%9}, {%0,%1,%2,%3};"
        : "+f"(d[0]), "+f"(d[1]), "+f"(d[2]), "+f"(d[3])
        : "r"(a[0]), "r"(a[1]), "r"(a[2]), "r"(a[3]), "r"(b0), "r"(b1));
}

// ---------------- HMMA GEMM (single-pass fp16) ----------------
// C[M,N] = A[M,K] @ B[N,K]^T. 128x128 tile, BK=64, 4-stage cp.async pipeline.
// EPI: 0 bias->f32, 1 bias+gelu->fp16, 2 bias+res->f32
#define STG 32768   // A 16K | B 16K

template <int EPI>
__global__ void __launch_bounds__(256, 1) tcgemm(const __half* __restrict__ Ah,
                                                 const __half* __restrict__ Bh,
                                                 const float* __restrict__ bias,
                                                 const float* __restrict__ res,
                                                 float* __restrict__ C,
                                                 __half* __restrict__ Ch,
                                                 int N, int K) {
    extern __shared__ char sm[];
    uint32_t sbase = (uint32_t)__cvta_generic_to_shared(sm);
    int tid = threadIdx.x;
    int lane = tid & 31, w = tid >> 5;
    int wm = w >> 2, wn = w & 3;
    int bn = blockIdx.x * 128, bm = blockIdx.y * 128;

    float acc[4][4][4];
#pragma unroll
    for (int i = 0; i < 4; i++)
#pragma unroll
        for (int j = 0; j < 4; j++)
#pragma unroll
            for (int q = 0; q < 4; q++) acc[i][j][q] = 0.f;

    int nk = K >> 6;

#define LOAD_STAGE(kc, buf)                                                        \
    {                                                                              \
        uint32_t sb_ = sbase + (buf) * STG;                                        \
        _Pragma("unroll")                                                          \
        for (int ii = 0; ii < 8; ii++) {                                           \
            int i = tid + ii * 256;                                                \
            int t = i >> 10, wrd = i & 1023, r = wrd >> 3, c = wrd & 7;            \
            int rb = t ? bn : bm;                                                  \
            const __half* sp = (t ? Bh : Ah) + (size_t)(rb + r) * K + (kc) * 64 + c * 8; \
            cpasync16(sb_ + t * 16384 + swz(r * 128 + c * 16), sp);                \
        }                                                                          \
        asm volatile("cp.async.commit_group;" ::: "memory");                       \
    }

    LOAD_STAGE(0, 0);
    LOAD_STAGE(1, 1);
    LOAD_STAGE(2, 2);

    int ra = (lane & 7) + ((lane & 8) ? 8 : 0);
    int ka = (lane & 16) ? 8 : 0;
    int rb_n = (lane & 7) + ((lane & 16) ? 8 : 0);
    int kb_n = (lane & 8) ? 8 : 0;

    int buf = 0;
    for (int kc = 0; kc < nk; kc++) {
        if (kc + 3 < nk) {
            int nb = buf + 3;
            if (nb >= 4) nb -= 4;
            LOAD_STAGE(kc + 3, nb);
            asm volatile("cp.async.wait_group 3;" ::: "memory");
        } else if (kc + 2 < nk) {
            asm volatile("cp.async.wait_group 2;" ::: "memory");
        } else if (kc + 1 < nk) {
            asm volatile("cp.async.wait_group 1;" ::: "memory");
        } else {
            asm volatile("cp.async.wait_group 0;" ::: "memory");
        }
        __syncthreads();
        uint32_t sb = sbase + buf * STG;
#pragma unroll
        for (int ks = 0; ks < 4; ks++) {
            uint32_t Af[4][4], Bf[2][4];
#pragma unroll
            for (int mt = 0; mt < 4; mt++) {
                int row = wm * 64 + mt * 16 + ra;
                ldm4(Af[mt], sb + swz(row * 128 + (ks * 16 + ka) * 2));
            }
#pragma unroll
            for (int pr = 0; pr < 2; pr++) {
                int row = wn * 32 + pr * 16 + rb_n;
                ldm4(Bf[pr], sb + 16384 + swz(row * 128 + (ks * 16 + kb_n) * 2));
            }
#pragma unroll
            for (int mt = 0; mt < 4; mt++)
#pragma unroll
                for (int nt = 0; nt < 4; nt++) {
                    int pr = nt >> 1, o = (nt & 1) * 2;
                    mma16816(acc[mt][nt], Af[mt], Bf[pr][o], Bf[pr][o + 1]);
                }
        }
        __syncthreads();
        if (++buf == 4) buf = 0;
    }

    int l4 = lane >> 2, l2 = (lane & 3) * 2;
#pragma unroll
    for (int mt = 0; mt < 4; mt++)
#pragma unroll
        for (int nt = 0; nt < 4; nt++) {
            int col = bn + wn * 32 + nt * 8 + l2;
            float b0 = bias[col], b1 = bias[col + 1];
#pragma unroll
            for (int half = 0; half < 2; half++) {
                size_t row = (size_t)(bm + wm * 64 + mt * 16 + l4 + half * 8);
                float v0 = acc[mt][nt][half * 2 + 0] + b0;
                float v1 = acc[mt][nt][half * 2 + 1] + b1;
                if (EPI == 2) {
                    v0 += res[row * N + col];
                    v1 += res[row * N + col + 1];
                }
                if (EPI == 1) {
                    v0 = 0.5f * v0 * (1.0f + erff(v0 * 0.70710678118654752f));
                    v1 = 0.5f * v1 * (1.0f + erff(v1 * 0.70710678118654752f));
                    *(__half2*)&Ch[row * N + col] = __floats2half2_rn(v0, v1);
                } else {
                    *(float2*)&C[row * N + col] = make_float2(v0, v1);
                }
            }
        }
#undef LOAD_STAGE
}

// ---------------- HMMA flash attention (2-pass Q/P, single K/V) ----------------
// grid (S/64, B*H), 128 threads. smem: Qh Ql [r][d], Kh [t][d], Vh [d][t] = 32KB.
__global__ void __launch_bounds__(128) attn_kernel(const float* __restrict__ qkv,
                                                   __half* __restrict__ oh) {
    extern __shared__ char smc[];
    uint32_t sb = (uint32_t)__cvta_generic_to_shared(smc);
    uint32_t Qh = sb, Ql = sb + 8192;
    uint32_t Kh = sb + 16384, Vh = sb + 24576;

    int qt = blockIdx.x, bh = blockIdx.y;
    int b = bh / HH, h = bh % HH;
    int tid = threadIdx.x, lane = tid & 31, w = tid >> 5;
    size_t base = (size_t)b * SS * QKV_N;
    int hoff = h * DD;

    for (int i = tid; i < 4096; i += 128) {
        int r = i >> 6, d = i & 63;
        float v = qkv[base + (size_t)(qt * 64 + r) * QKV_N + hoff + d] * 0.125f;
        __half hi, lo;
        split_f16(v, &hi, &lo);
        uint32_t off = swz(r * 128 + d * 2);
        *(__half*)(smc + off) = hi;
        *(__half*)(smc + 8192 + off) = lo;
    }

    int ra = (lane & 7) + ((lane & 8) ? 8 : 0);
    int ka = (lane & 16) ? 8 : 0;
    int rbn = (lane & 7) + ((lane & 16) ? 8 : 0);
    int kbn = (lane & 8) ? 8 : 0;
    int r0 = lane >> 2, c0 = (lane & 3) * 2;

    float m0 = -1e30f, m1 = -1e30f, l0 = 0.f, l1 = 0.f;
    float o[8][4];
#pragma unroll
    for (int i = 0; i < 8; i++)
#pragma unroll
        for (int j = 0; j < 4; j++) o[i][j] = 0.f;

    for (int kt = 0; kt <= qt; kt++) {
        __syncthreads();
        for (int i = tid; i < 4096; i += 128) {
            int r = i >> 6, d = i & 63;
            size_t off = base + (size_t)(kt * 64 + r) * QKV_N + hoff + d;
            *(__half*)(smc + 16384 + swz(r * 128 + d * 2)) = __float2half_rn(qkv[off + EE]);
            *(__half*)(smc + 24576 + swz(d * 128 + r * 2)) = __float2half_rn(qkv[off + 2 * EE]);
        }
        __syncthreads();

        float s[8][4];
#pragma unroll
        for (int i = 0; i < 8; i++)
#pragma unroll
            for (int j = 0; j < 4; j++) s[i][j] = 0.f;
#pragma unroll
        for (int kc = 0; kc < 4; kc++) {
            uint32_t qh[4], ql[4], kh[4][4];
            uint32_t aoff = swz((w * 16 + ra) * 128 + (kc * 16 + ka) * 2);
            ldm4(qh, Qh + aoff);
            ldm4(ql, Ql + aoff);
#pragma unroll
            for (int tg = 0; tg < 4; tg++) {
                uint32_t boff = swz((tg * 16 + rbn) * 128 + (kc * 16 + kbn) * 2);
                ldm4(kh[tg], Kh + boff);
            }
#pragma unroll
            for (int nt = 0; nt < 8; nt++) {
                int pr = nt >> 1, oo = (nt & 1) * 2;
                mma16816(s[nt], qh, kh[pr][oo], kh[pr][oo + 1]);
                mma16816(s[nt], ql, kh[pr][oo], kh[pr][oo + 1]);
            }
        }

        if (kt == qt) {
            int row0 = w * 16 + r0, row1 = row0 + 8;
#pragma unroll
            for (int nt = 0; nt < 8; nt++) {
                int c = nt * 8 + c0;
                if (c > row0) s[nt][0] = -1e30f;
                if (c + 1 > row0) s[nt][1] = -1e30f;
                if (c > row1) s[nt][2] = -1e30f;
                if (c + 1 > row1) s[nt][3] = -1e30f;
            }
        }

        float mt0 = -1e30f, mt1 = -1e30f;
#pragma unroll
        for (int nt = 0; nt < 8; nt++) {
            mt0 = fmaxf(mt0, fmaxf(s[nt][0], s[nt][1]));
            mt1 = fmaxf(mt1, fmaxf(s[nt][2], s[nt][3]));
        }
#pragma unroll
        for (int off = 1; off <= 2; off <<= 1) {
            mt0 = fmaxf(mt0, __shfl_xor_sync(0xffffffffu, mt0, off));
            mt1 = fmaxf(mt1, __shfl_xor_sync(0xffffffffu, mt1, off));
        }
        float mn0 = fmaxf(m0, mt0), mn1 = fmaxf(m1, mt1);
        float sc0 = __expf(m0 - mn0), sc1 = __expf(m1 - mn1);
        float rs0 = 0.f, rs1 = 0.f;
#pragma unroll
        for (int nt = 0; nt < 8; nt++) {
            s[nt][0] = __expf(s[nt][0] - mn0);
            s[nt][1] = __expf(s[nt][1] - mn0);
            s[nt][2] = __expf(s[nt][2] - mn1);
            s[nt][3] = __expf(s[nt][3] - mn1);
            rs0 += s[nt][0] + s[nt][1];
            rs1 += s[nt][2] + s[nt][3];
        }
#pragma unroll
        for (int off = 1; off <= 2; off <<= 1) {
            rs0 += __shfl_xor_sync(0xffffffffu, rs0, off);
            rs1 += __shfl_xor_sync(0xffffffffu, rs1, off);
        }
        l0 = l0 * sc0 + rs0;
        l1 = l1 * sc1 + rs1;
        m0 = mn0;
        m1 = mn1;
#pragma unroll
        for (int i = 0; i < 8; i++) {
            o[i][0] *= sc0; o[i][1] *= sc0;
            o[i][2] *= sc1; o[i][3] *= sc1;
        }

#pragma unroll
        for (int kc = 0; kc < 4; kc++) {
            float p00 = s[2 * kc][0], p01 = s[2 * kc][1];
            float p02 = s[2 * kc][2], p03 = s[2 * kc][3];
            float p10 = s[2 * kc + 1][0], p11 = s[2 * kc + 1][1];
            float p12 = s[2 * kc + 1][2], p13 = s[2 * kc + 1][3];
            uint32_t aph[4], apl[4];
            aph[0] = pack2(p00, p01);
            aph[1] = pack2(p02, p03);
            aph[2] = pack2(p10, p11);
            aph[3] = pack2(p12, p13);
            __half2 t0 = *(__half2*)&aph[0];
            __half2 t1 = *(__half2*)&aph[1];
            __half2 t2 = *(__half2*)&aph[2];
            __half2 t3 = *(__half2*)&aph[3];
            apl[0] = pack2(p00 - __half2float(t0.x), p01 - __half2float(t0.y));
            apl[1] = pack2(p02 - __half2float(t1.x), p03 - __half2float(t1.y));
            apl[2] = pack2(p10 - __half2float(t2.x), p11 - __half2float(t2.y));
            apl[3] = pack2(p12 - __half2float(t3.x), p13 - __half2float(t3.y));
            uint32_t vh[4][4];
#pragma unroll
            for (int dg = 0; dg < 4; dg++) {
                uint32_t boff = swz((dg * 16 + rbn) * 128 + (kc * 16 + kbn) * 2);
                ldm4(vh[dg], Vh + boff);
            }
#pragma unroll
            for (int dt = 0; dt < 8; dt++) {
                int pr = dt >> 1, oo = (dt & 1) * 2;
                mma16816(o[dt], aph, vh[pr][oo], vh[pr][oo + 1]);
                mma16816(o[dt], apl, vh[pr][oo], vh[pr][oo + 1]);
            }
        }
    }

    float inv0 = 1.f / l0, inv1 = 1.f / l1;
    size_t row0 = (size_t)b * SS + qt * 64 + w * 16 + r0;
    size_t row1 = row0 + 8;
#pragma unroll
    for (int dt = 0; dt < 8; dt++) {
        int d = hoff + dt * 8 + c0;
        *(__half2*)&oh[row0 * EE + d] = __floats2half2_rn(o[dt][0] * inv0, o[dt][1] * inv0);
        *(__half2*)&oh[row1 * EE + d] = __floats2half2_rn(o[dt][2] * inv1, o[dt][3] * inv1);
    }
}

// ---------------- launch ----------------
extern "C" void kernel_launch(void* const* d_in, const int* in_sizes, int n_in,
                              void* d_out, int out_size) {
    const float* x = (const float*)d_in[0];
    const float* Wq = (const float*)d_in[1];
    const float* bq = (const float*)d_in[2];
    const float* Wk = (const float*)d_in[3];
    const float* bk = (const float*)d_in[4];
    const float* Wv = (const float*)d_in[5];
    const float* bv = (const float*)d_in[6];
    const float* Wp = (const float*)d_in[7];
    const float* bp = (const float*)d_in[8];
    const float* ln1_g = (const float*)d_in[9];
    const float* ln1_b = (const float*)d_in[10];
    const float* ln2_g = (const float*)d_in[11];
    const float* ln2_b = (const float*)d_in[12];
    const float* W1 = (const float*)d_in[13];
    const float* b1 = (const float*)d_in[14];
    const float* W2 = (const float*)d_in[15];
    const float* b2 = (const float*)d_in[16];
    const float* lnf_g = (const float*)d_in[17];
    const float* lnf_b = (const float*)d_in[18];
    float* out = (float*)d_out;

    __half *p_ah, *p_fh, *p_wq, *p_wp, *p_w1, *p_w2;
    float *p_bqkv, *p_qkv, *p_x1, *p_f2;
    cudaGetSymbolAddress((void**)&p_ah, g_ah);
    cudaGetSymbolAddress((void**)&p_fh, g_fh);
    cudaGetSymbolAddress((void**)&p_wq, g_wqkvt);
    cudaGetSymbolAddress((void**)&p_wp, g_wpt);
    cudaGetSymbolAddress((void**)&p_w1, g_w1t);
    cudaGetSymbolAddress((void**)&p_w2, g_w2t);
    cudaGetSymbolAddress((void**)&p_bqkv, g_bqkv);
    cudaGetSymbolAddress((void**)&p_qkv, g_qkv);
    cudaGetSymbolAddress((void**)&p_x1, g_x1);
    cudaGetSymbolAddress((void**)&p_f2, g_f2);

    int gsmem = 4 * STG;  // 131072
    cudaFuncSetAttribute(tcgemm<0>, cudaFuncAttributeMaxDynamicSharedMemorySize, gsmem);
    cudaFuncSetAttribute(tcgemm<1>, cudaFuncAttributeMaxDynamicSharedMemorySize, gsmem);
    cudaFuncSetAttribute(tcgemm<2>, cudaFuncAttributeMaxDynamicSharedMemorySize, gsmem);
    int asmem = 32768;
    cudaFuncSetAttribute(attn_kernel, cudaFuncAttributeMaxDynamicSharedMemorySize, asmem);

    pack_wqkv_kernel<<<(QKV_N * EE + 255) / 256, 256>>>(Wq, Wk, Wv, bq, bk, bv);
    transpose_h_kernel<<<(EE * EE + 255) / 256, 256>>>(Wp, p_wp, EE, EE);
    transpose_h_kernel<<<(EE * FF + 255) / 256, 256>>>(W1, p_w1, EE, FF);
    transpose_h_kernel<<<(FF * EE + 255) / 256, 256>>>(W2, p_w2, FF, EE);

    ln_h_kernel<<<ROWS, 256>>>(x, ln1_g, ln1_b, p_ah);
    tcgemm<0><<<dim3(QKV_N / 128, ROWS / 128), 256, gsmem>>>(
        p_ah, p_wq, p_bqkv, nullptr, p_qkv, nullptr, QKV_N, EE);
    attn_kernel<<<dim3(SS / 64, BB * HH), 128, asmem>>>(p_qkv, p_ah);
    tcgemm<2><<<dim3(EE / 128, ROWS / 128), 256, gsmem>>>(
        p_ah, p_wp, bp, x, p_x1, nullptr, EE, EE);
    ln_h_kernel<<<ROWS, 256>>>(p_x1, ln2_g, ln2_b, p_ah);
    tcgemm<1><<<dim3(FF / 128, ROWS / 128), 256, gsmem>>>(
        p_ah, p_w1, b1, nullptr, nullptr, p_fh, FF, EE);
    tcgemm<0><<<dim3(EE / 128, ROWS / 128), 256, gsmem>>>(
        p_fh, p_w2, b2, nullptr, p_f2, nullptr, EE, FF);
    ln_final_kernel<<<ROWS, 256>>>(p_f2, lnf_g, lnf_b, p_x1, out);
}

// round 9
// speedup vs baseline: 9.2746x; 1.2205x over previous
#include <cuda_runtime.h>
#include <cuda_fp16.h>
#include <math.h>
#include <stdint.h>

#define BB 16
#define SS 1024
#define EE 768
#define HH 12
#define DD 64
#define FF 3072
#define ROWS (BB * SS)
#define QKV_N (3 * EE)

// scratch
__device__ __half g_ah[ROWS * EE];          // activation fp16 (LN out / attn out)
__device__ __half g_fh[ROWS * FF];          // ffn1 out fp16
__device__ __half g_qkvh[ROWS * QKV_N];     // fused qkv, fp16 (q pre-scaled by 1/8)
__device__ __half g_wqkvt[QKV_N * EE];      // weights fp16, [N][K]
__device__ __half g_wpt[EE * EE];
__device__ __half g_w1t[FF * EE];
__device__ __half g_w2t[EE * FF];
__device__ float g_bqkv[QKV_N];
__device__ float g_x1[ROWS * EE];
__device__ float g_f2[ROWS * EE];

__device__ __forceinline__ uint32_t swz(uint32_t o) { return o ^ ((o >> 3) & 0x70); }
__device__ __forceinline__ uint32_t pack2(float x, float y) {
    __half2 t = __floats2half2_rn(x, y);
    return *(uint32_t*)&t;
}

// ---------------- weight prep ----------------
__global__ void pack_wqkv_kernel(const float* __restrict__ Wq, const float* __restrict__ Wk,
                                 const float* __restrict__ Wv, const float* __restrict__ bq,
                                 const float* __restrict__ bk, const float* __restrict__ bv) {
    int idx = blockIdx.x * blockDim.x + threadIdx.x;
    if (idx < QKV_N * EE) {
        int n = idx / EE, e = idx % EE;
        int sec = n / 768;
        int hd = n % 768;
        const float* W = (sec == 0) ? Wq : (sec == 1) ? Wk : Wv;
        float v = W[((hd >> 6) * EE + e) * DD + (hd & 63)];
        if (sec == 0) v *= 0.125f;            // fold 1/sqrt(D) into q projection
        g_wqkvt[idx] = __float2half_rn(v);
    }
    if (idx < QKV_N) {
        int sec = idx / 768;
        const float* bsrc = (sec == 0) ? bq : (sec == 1) ? bk : bv;
        float v = bsrc[idx % 768];
        if (sec == 0) v *= 0.125f;
        g_bqkv[idx] = v;
    }
}

__global__ void transpose_h_kernel(const float* __restrict__ in,
                                   __half* __restrict__ oh, int K, int N) {
    int idx = blockIdx.x * blockDim.x + threadIdx.x;
    if (idx >= N * K) return;
    int n = idx / K, k = idx % K;
    oh[idx] = __float2half_rn(in[(size_t)k * N + n]);
}

// ---------------- LN ----------------
__device__ __forceinline__ float block_reduce_sum_256(float v, float* sbuf) {
    int lane = threadIdx.x & 31, wid = threadIdx.x >> 5;
#pragma unroll
    for (int m = 16; m; m >>= 1) v += __shfl_xor_sync(0xffffffffu, v, m);
    if (lane == 0) sbuf[wid] = v;
    __syncthreads();
    if (wid == 0) {
        v = (lane < 8) ? sbuf[lane] : 0.f;
#pragma unroll
        for (int m = 4; m; m >>= 1) v += __shfl_xor_sync(0xffffffffu, v, m);
        if (lane == 0) sbuf[0] = v;
    }
    __syncthreads();
    float r = sbuf[0];
    __syncthreads();
    return r;
}

__global__ void __launch_bounds__(256) ln_h_kernel(const float* __restrict__ in,
                                                   const float* __restrict__ gam,
                                                   const float* __restrict__ bet,
                                                   __half* __restrict__ oh) {
    __shared__ float sbuf[8];
    size_t row = blockIdx.x;
    const float* x = in + row * EE;
    float s = 0.f;
    for (int i = threadIdx.x; i < EE; i += 256) s += x[i];
    float mu = block_reduce_sum_256(s, sbuf) * (1.f / EE);
    float v = 0.f;
    for (int i = threadIdx.x; i < EE; i += 256) { float d = x[i] - mu; v += d * d; }
    float rstd = rsqrtf(block_reduce_sum_256(v, sbuf) * (1.f / EE) + 1e-5f);
    for (int i = threadIdx.x; i < EE; i += 256)
        oh[row * EE + i] = __float2half_rn((x[i] - mu) * rstd * gam[i] + bet[i]);
}

__global__ void __launch_bounds__(256) ln_final_kernel(const float* __restrict__ in,
                                                       const float* __restrict__ gam,
                                                       const float* __restrict__ bet,
                                                       const float* __restrict__ res,
                                                       float* __restrict__ out) {
    __shared__ float sbuf[8];
    size_t row = blockIdx.x;
    const float* x = in + row * EE;
    float s = 0.f;
    for (int i = threadIdx.x; i < EE; i += 256) s += x[i];
    float mu = block_reduce_sum_256(s, sbuf) * (1.f / EE);
    float v = 0.f;
    for (int i = threadIdx.x; i < EE; i += 256) { float d = x[i] - mu; v += d * d; }
    float rstd = rsqrtf(block_reduce_sum_256(v, sbuf) * (1.f / EE) + 1e-5f);
    for (int i = threadIdx.x; i < EE; i += 256)
        out[row * EE + i] = (x[i] - mu) * rstd * gam[i] + bet[i] + res[row * EE + i];
}

// ---------------- HMMA primitives (fp16) ----------------
__device__ __forceinline__ void cpasync16(uint32_t dst, const void* src) {
    asm volatile("cp.async.cg.shared.global [%0], [%1], 16;" :: "r"(dst), "l"(src));
}
__device__ __forceinline__ void ldm4(uint32_t* r, uint32_t addr) {
    asm volatile("ldmatrix.sync.aligned.m8n8.x4.shared.b16 {%0,%1,%2,%3}, [%4];"
                 : "=r"(r[0]), "=r"(r[1]), "=r"(r[2]), "=r"(r[3]) : "r"(addr));
}
__device__ __forceinline__ void ldm4t(uint32_t* r, uint32_t addr) {
    asm volatile("ldmatrix.sync.aligned.m8n8.x4.trans.shared.b16 {%0,%1,%2,%3}, [%4];"
                 : "=r"(r[0]), "=r"(r[1]), "=r"(r[2]), "=r"(r[3]) : "r"(addr));
}
__device__ __forceinline__ void mma16816(float* d, const uint32_t* a, uint32_t b0, uint32_t b1) {
    asm volatile(
        "mma.sync.aligned.m16n8k16.row.col.f32.f16.f16.f32 "
        "{%0,%1,%2,%3}, {%4,%5,%6,%7}, {%8,%9}, {%0,%1,%2,%3};"
        : "+f"(d[0]), "+f"(d[1]), "+f"(d[2]), "+f"(d[3])
        : "r"(a[0]), "r"(a[1]), "r"(a[2]), "r"(a[3]), "r"(b0), "r"(b1));
}

// ---------------- HMMA GEMM (single-pass fp16) ----------------
// C[M,N] = A[M,K] @ B[N,K]^T. 128x128 tile, BK=64, 4-stage cp.async pipeline.
// EPI: 0 bias->f32, 1 bias+gelu->fp16, 2 bias+res->f32, 3 bias->fp16
#define STG 32768

template <int EPI>
__global__ void __launch_bounds__(256, 1) tcgemm(const __half* __restrict__ Ah,
                                                 const __half* __restrict__ Bh,
                                                 const float* __restrict__ bias,
                                                 const float* __restrict__ res,
                                                 float* __restrict__ C,
                                                 __half* __restrict__ Ch,
                                                 int N, int K) {
    extern __shared__ char sm[];
    uint32_t sbase = (uint32_t)__cvta_generic_to_shared(sm);
    int tid = threadIdx.x;
    int lane = tid & 31, w = tid >> 5;
    int wm = w >> 2, wn = w & 3;
    int bn = blockIdx.x * 128, bm = blockIdx.y * 128;

    float acc[4][4][4];
#pragma unroll
    for (int i = 0; i < 4; i++)
#pragma unroll
        for (int j = 0; j < 4; j++)
#pragma unroll
            for (int q = 0; q < 4; q++) acc[i][j][q] = 0.f;

    int nk = K >> 6;

#define LOAD_STAGE(kc, buf)                                                        \
    {                                                                              \
        uint32_t sb_ = sbase + (buf) * STG;                                        \
        _Pragma("unroll")                                                          \
        for (int ii = 0; ii < 8; ii++) {                                           \
            int i = tid + ii * 256;                                                \
            int t = i >> 10, wrd = i & 1023, r = wrd >> 3, c = wrd & 7;            \
            int rb = t ? bn : bm;                                                  \
            const __half* sp = (t ? Bh : Ah) + (size_t)(rb + r) * K + (kc) * 64 + c * 8; \
            cpasync16(sb_ + t * 16384 + swz(r * 128 + c * 16), sp);                \
        }                                                                          \
        asm volatile("cp.async.commit_group;" ::: "memory");                       \
    }

    LOAD_STAGE(0, 0);
    LOAD_STAGE(1, 1);
    LOAD_STAGE(2, 2);

    int ra = (lane & 7) + ((lane & 8) ? 8 : 0);
    int ka = (lane & 16) ? 8 : 0;
    int rb_n = (lane & 7) + ((lane & 16) ? 8 : 0);
    int kb_n = (lane & 8) ? 8 : 0;

    int buf = 0;
    for (int kc = 0; kc < nk; kc++) {
        if (kc + 3 < nk) {
            int nb = buf + 3;
            if (nb >= 4) nb -= 4;
            LOAD_STAGE(kc + 3, nb);
            asm volatile("cp.async.wait_group 3;" ::: "memory");
        } else if (kc + 2 < nk) {
            asm volatile("cp.async.wait_group 2;" ::: "memory");
        } else if (kc + 1 < nk) {
            asm volatile("cp.async.wait_group 1;" ::: "memory");
        } else {
            asm volatile("cp.async.wait_group 0;" ::: "memory");
        }
        __syncthreads();
        uint32_t sb = sbase + buf * STG;
#pragma unroll
        for (int ks = 0; ks < 4; ks++) {
            uint32_t Af[4][4], Bf[2][4];
#pragma unroll
            for (int mt = 0; mt < 4; mt++) {
                int row = wm * 64 + mt * 16 + ra;
                ldm4(Af[mt], sb + swz(row * 128 + (ks * 16 + ka) * 2));
            }
#pragma unroll
            for (int pr = 0; pr < 2; pr++) {
                int row = wn * 32 + pr * 16 + rb_n;
                ldm4(Bf[pr], sb + 16384 + swz(row * 128 + (ks * 16 + kb_n) * 2));
            }
#pragma unroll
            for (int mt = 0; mt < 4; mt++)
#pragma unroll
                for (int nt = 0; nt < 4; nt++) {
                    int pr = nt >> 1, o = (nt & 1) * 2;
                    mma16816(acc[mt][nt], Af[mt], Bf[pr][o], Bf[pr][o + 1]);
                }
        }
        __syncthreads();
        if (++buf == 4) buf = 0;
    }

    int l4 = lane >> 2, l2 = (lane & 3) * 2;
#pragma unroll
    for (int mt = 0; mt < 4; mt++)
#pragma unroll
        for (int nt = 0; nt < 4; nt++) {
            int col = bn + wn * 32 + nt * 8 + l2;
            float b0 = bias[col], b1 = bias[col + 1];
#pragma unroll
            for (int half = 0; half < 2; half++) {
                size_t row = (size_t)(bm + wm * 64 + mt * 16 + l4 + half * 8);
                float v0 = acc[mt][nt][half * 2 + 0] + b0;
                float v1 = acc[mt][nt][half * 2 + 1] + b1;
                if (EPI == 2) {
                    v0 += res[row * N + col];
                    v1 += res[row * N + col + 1];
                }
                if (EPI == 1) {
                    v0 = 0.5f * v0 * (1.0f + erff(v0 * 0.70710678118654752f));
                    v1 = 0.5f * v1 * (1.0f + erff(v1 * 0.70710678118654752f));
                }
                if (EPI == 1 || EPI == 3) {
                    *(__half2*)&Ch[row * N + col] = __floats2half2_rn(v0, v1);
                } else {
                    *(float2*)&C[row * N + col] = make_float2(v0, v1);
                }
            }
        }
#undef LOAD_STAGE
}

// ---------------- HMMA flash attention (single-pass fp16) ----------------
// grid (S/64, B*H), 128 threads. smem: Q 8K | KV0 16K | KV1 16K = 40KB.
// qkvh fp16, q pre-scaled. K [t][d]; V [t][d] read with ldmatrix.trans for PV.
__global__ void __launch_bounds__(128) attn_kernel(const __half* __restrict__ qkvh,
                                                   __half* __restrict__ oh) {
    extern __shared__ char smc[];
    uint32_t sb = (uint32_t)__cvta_generic_to_shared(smc);
    uint32_t Qs = sb;

    int qt = blockIdx.x, bh = blockIdx.y;
    int b = bh / HH, h = bh % HH;
    int tid = threadIdx.x, lane = tid & 31, w = tid >> 5;
    size_t base = (size_t)b * SS * QKV_N;
    int hoff = h * DD;

    // Q tile: 64 rows x 128B, cp.async
#pragma unroll
    for (int ii = 0; ii < 4; ii++) {
        int i = tid + ii * 128;
        int r = i >> 3, c = i & 7;
        cpasync16(Qs + swz(r * 128 + c * 16),
                  qkvh + base + (size_t)(qt * 64 + r) * QKV_N + hoff + c * 8);
    }

#define ISSUE_KV(kt, bufo)                                                          \
    {                                                                               \
        _Pragma("unroll")                                                           \
        for (int ii = 0; ii < 8; ii++) {                                            \
            int i = tid + ii * 128;                                                 \
            int ts = i >> 9, wrd = i & 511, r = wrd >> 3, c = wrd & 7;              \
            cpasync16(sb + (bufo) + ts * 8192 + swz(r * 128 + c * 16),              \
                      qkvh + base + (size_t)((kt) * 64 + r) * QKV_N + hoff +        \
                          (ts ? 2 * EE : EE) + c * 8);                              \
        }                                                                           \
        asm volatile("cp.async.commit_group;" ::: "memory");                        \
    }

    ISSUE_KV(0, 8192);

    int ra = (lane & 7) + ((lane & 8) ? 8 : 0);
    int ka = (lane & 16) ? 8 : 0;
    int rbn = (lane & 7) + ((lane & 16) ? 8 : 0);
    int kbn = (lane & 8) ? 8 : 0;
    // trans (V) lane mapping: bit3 -> k-row, bit4 -> n-col
    int vkr = (lane & 7) + ((lane & 8) ? 8 : 0);
    int vnc = (lane & 16) ? 8 : 0;
    int r0 = lane >> 2, c0 = (lane & 3) * 2;

    float m0 = -1e30f, m1 = -1e30f, l0 = 0.f, l1 = 0.f;
    float o[8][4];
#pragma unroll
    for (int i = 0; i < 8; i++)
#pragma unroll
        for (int j = 0; j < 4; j++) o[i][j] = 0.f;

    for (int kt = 0; kt <= qt; kt++) {
        asm volatile("cp.async.wait_group 0;" ::: "memory");
        __syncthreads();
        uint32_t kvo = 8192 + (kt & 1) * 16384;
        if (kt < qt) ISSUE_KV(kt + 1, 8192 + ((kt + 1) & 1) * 16384);
        uint32_t Kh = sb + kvo, Vh = sb + kvo + 8192;

        float s[8][4];
#pragma unroll
        for (int i = 0; i < 8; i++)
#pragma unroll
            for (int j = 0; j < 4; j++) s[i][j] = 0.f;
#pragma unroll
        for (int kc = 0; kc < 4; kc++) {
            uint32_t qh[4], kh[4][4];
            ldm4(qh, Qs + swz((w * 16 + ra) * 128 + (kc * 16 + ka) * 2));
#pragma unroll
            for (int tg = 0; tg < 4; tg++)
                ldm4(kh[tg], Kh + swz((tg * 16 + rbn) * 128 + (kc * 16 + kbn) * 2));
#pragma unroll
            for (int nt = 0; nt < 8; nt++) {
                int pr = nt >> 1, oo = (nt & 1) * 2;
                mma16816(s[nt], qh, kh[pr][oo], kh[pr][oo + 1]);
            }
        }

        if (kt == qt) {
            int row0 = w * 16 + r0, row1 = row0 + 8;
#pragma unroll
            for (int nt = 0; nt < 8; nt++) {
                int c = nt * 8 + c0;
                if (c > row0) s[nt][0] = -1e30f;
                if (c + 1 > row0) s[nt][1] = -1e30f;
                if (c > row1) s[nt][2] = -1e30f;
                if (c + 1 > row1) s[nt][3] = -1e30f;
            }
        }

        float mt0 = -1e30f, mt1 = -1e30f;
#pragma unroll
        for (int nt = 0; nt < 8; nt++) {
            mt0 = fmaxf(mt0, fmaxf(s[nt][0], s[nt][1]));
            mt1 = fmaxf(mt1, fmaxf(s[nt][2], s[nt][3]));
        }
#pragma unroll
        for (int off = 1; off <= 2; off <<= 1) {
            mt0 = fmaxf(mt0, __shfl_xor_sync(0xffffffffu, mt0, off));
            mt1 = fmaxf(mt1, __shfl_xor_sync(0xffffffffu, mt1, off));
        }
        float mn0 = fmaxf(m0, mt0), mn1 = fmaxf(m1, mt1);
        float sc0 = __expf(m0 - mn0), sc1 = __expf(m1 - mn1);
        float rs0 = 0.f, rs1 = 0.f;
#pragma unroll
        for (int nt = 0; nt < 8; nt++) {
            s[nt][0] = __expf(s[nt][0] - mn0);
            s[nt][1] = __expf(s[nt][1] - mn0);
            s[nt][2] = __expf(s[nt][2] - mn1);
            s[nt][3] = __expf(s[nt][3] - mn1);
            rs0 += s[nt][0] + s[nt][1];
            rs1 += s[nt][2] + s[nt][3];
        }
#pragma unroll
        for (int off = 1; off <= 2; off <<= 1) {
            rs0 += __shfl_xor_sync(0xffffffffu, rs0, off);
            rs1 += __shfl_xor_sync(0xffffffffu, rs1, off);
        }
        l0 = l0 * sc0 + rs0;
        l1 = l1 * sc1 + rs1;
        m0 = mn0;
        m1 = mn1;
#pragma unroll
        for (int i = 0; i < 8; i++) {
            o[i][0] *= sc0; o[i][1] *= sc0;
            o[i][2] *= sc1; o[i][3] *= sc1;
        }

        // O += P V : P fp16 from regs, V via ldmatrix.trans on [t][d]
#pragma unroll
        for (int kc = 0; kc < 4; kc++) {
            uint32_t aph[4];
            aph[0] = pack2(s[2 * kc][0], s[2 * kc][1]);
            aph[1] = pack2(s[2 * kc][2], s[2 * kc][3]);
            aph[2] = pack2(s[2 * kc + 1][0], s[2 * kc + 1][1]);
            aph[3] = pack2(s[2 * kc + 1][2], s[2 * kc + 1][3]);
            uint32_t vh[4][4];
#pragma unroll
            for (int dg = 0; dg < 4; dg++)
                ldm4t(vh[dg], Vh + swz((kc * 16 + vkr) * 128 + (dg * 16 + vnc) * 2));
#pragma unroll
            for (int dt = 0; dt < 8; dt++) {
                int pr = dt >> 1, oo = (dt & 1) * 2;
                mma16816(o[dt], aph, vh[pr][oo], vh[pr][oo + 1]);
            }
        }
        __syncthreads();
    }

    float inv0 = 1.f / l0, inv1 = 1.f / l1;
    size_t row0 = (size_t)b * SS + qt * 64 + w * 16 + r0;
    size_t row1 = row0 + 8;
#pragma unroll
    for (int dt = 0; dt < 8; dt++) {
        int d = hoff + dt * 8 + c0;
        *(__half2*)&oh[row0 * EE + d] = __floats2half2_rn(o[dt][0] * inv0, o[dt][1] * inv0);
        *(__half2*)&oh[row1 * EE + d] = __floats2half2_rn(o[dt][2] * inv1, o[dt][3] * inv1);
    }
#undef ISSUE_KV
}

// ---------------- launch ----------------
extern "C" void kernel_launch(void* const* d_in, const int* in_sizes, int n_in,
                              void* d_out, int out_size) {
    const float* x = (const float*)d_in[0];
    const float* Wq = (const float*)d_in[1];
    const float* bq = (const float*)d_in[2];
    const float* Wk = (const float*)d_in[3];
    const float* bk = (const float*)d_in[4];
    const float* Wv = (const float*)d_in[5];
    const float* bv = (const float*)d_in[6];
    const float* Wp = (const float*)d_in[7];
    const float* bp = (const float*)d_in[8];
    const float* ln1_g = (const float*)d_in[9];
    const float* ln1_b = (const float*)d_in[10];
    const float* ln2_g = (const float*)d_in[11];
    const float* ln2_b = (const float*)d_in[12];
    const float* W1 = (const float*)d_in[13];
    const float* b1 = (const float*)d_in[14];
    const float* W2 = (const float*)d_in[15];
    const float* b2 = (const float*)d_in[16];
    const float* lnf_g = (const float*)d_in[17];
    const float* lnf_b = (const float*)d_in[18];
    float* out = (float*)d_out;

    __half *p_ah, *p_fh, *p_qkvh, *p_wq, *p_wp, *p_w1, *p_w2;
    float *p_bqkv, *p_x1, *p_f2;
    cudaGetSymbolAddress((void**)&p_ah, g_ah);
    cudaGetSymbolAddress((void**)&p_fh, g_fh);
    cudaGetSymbolAddress((void**)&p_qkvh, g_qkvh);
    cudaGetSymbolAddress((void**)&p_wq, g_wqkvt);
    cudaGetSymbolAddress((void**)&p_wp, g_wpt);
    cudaGetSymbolAddress((void**)&p_w1, g_w1t);
    cudaGetSymbolAddress((void**)&p_w2, g_w2t);
    cudaGetSymbolAddress((void**)&p_bqkv, g_bqkv);
    cudaGetSymbolAddress((void**)&p_x1, g_x1);
    cudaGetSymbolAddress((void**)&p_f2, g_f2);

    int gsmem = 4 * STG;  // 131072
    cudaFuncSetAttribute(tcgemm<0>, cudaFuncAttributeMaxDynamicSharedMemorySize, gsmem);
    cudaFuncSetAttribute(tcgemm<1>, cudaFuncAttributeMaxDynamicSharedMemorySize, gsmem);
    cudaFuncSetAttribute(tcgemm<2>, cudaFuncAttributeMaxDynamicSharedMemorySize, gsmem);
    cudaFuncSetAttribute(tcgemm<3>, cudaFuncAttributeMaxDynamicSharedMemorySize, gsmem);
    int asmem = 40960;
    cudaFuncSetAttribute(attn_kernel, cudaFuncAttributeMaxDynamicSharedMemorySize, asmem);

    pack_wqkv_kernel<<<(QKV_N * EE + 255) / 256, 256>>>(Wq, Wk, Wv, bq, bk, bv);
    transpose_h_kernel<<<(EE * EE + 255) / 256, 256>>>(Wp, p_wp, EE, EE);
    transpose_h_kernel<<<(EE * FF + 255) / 256, 256>>>(W1, p_w1, EE, FF);
    transpose_h_kernel<<<(FF * EE + 255) / 256, 256>>>(W2, p_w2, FF, EE);

    ln_h_kernel<<<ROWS, 256>>>(x, ln1_g, ln1_b, p_ah);
    tcgemm<3><<<dim3(QKV_N / 128, ROWS / 128), 256, gsmem>>>(
        p_ah, p_wq, p_bqkv, nullptr, nullptr, p_qkvh, QKV_N, EE);
    attn_kernel<<<dim3(SS / 64, BB * HH), 128, asmem>>>(p_qkvh, p_ah);
    tcgemm<2><<<dim3(EE / 128, ROWS / 128), 256, gsmem>>>(
        p_ah, p_wp, bp, x, p_x1, nullptr, EE, EE);
    ln_h_kernel<<<ROWS, 256>>>(p_x1, ln2_g, ln2_b, p_ah);
    tcgemm<1><<<dim3(FF / 128, ROWS / 128), 256, gsmem>>>(
        p_ah, p_w1, b1, nullptr, nullptr, p_fh, FF, EE);
    tcgemm<0><<<dim3(EE / 128, ROWS / 128), 256, gsmem>>>(
        p_fh, p_w2, b2, nullptr, p_f2, nullptr, EE, FF);
    ln_final_kernel<<<ROWS, 256>>>(p_f2, lnf_g, lnf_b, p_x1, out);
}

// round 10
// speedup vs baseline: 9.9015x; 1.0676x over previous
#include <cuda_runtime.h>
#include <cuda_fp16.h>
#include <math.h>
#include <stdint.h>

#define BB 16
#define SS 1024
#define EE 768
#define HH 12
#define DD 64
#define FF 3072
#define ROWS (BB * SS)
#define QKV_N (3 * EE)

// scratch
__device__ __half g_ah[ROWS * EE];
__device__ __half g_fh[ROWS * FF];
__device__ __half g_qkvh[ROWS * QKV_N];
__device__ __half g_wqkvt[QKV_N * EE];
__device__ __half g_wpt[EE * EE];
__device__ __half g_w1t[FF * EE];
__device__ __half g_w2t[EE * FF];
__device__ float g_bqkv[QKV_N];
__device__ float g_x1[ROWS * EE];
__device__ float g_f2[ROWS * EE];

__device__ __forceinline__ uint32_t swz(uint32_t o) { return o ^ ((o >> 3) & 0x70); }
__device__ __forceinline__ uint32_t pack2(float x, float y) {
    __half2 t = __floats2half2_rn(x, y);
    return *(uint32_t*)&t;
}

// ---------------- weight prep ----------------
__global__ void pack_wqkv_kernel(const float* __restrict__ Wq, const float* __restrict__ Wk,
                                 const float* __restrict__ Wv, const float* __restrict__ bq,
                                 const float* __restrict__ bk, const float* __restrict__ bv) {
    int idx = blockIdx.x * blockDim.x + threadIdx.x;
    if (idx < QKV_N * EE) {
        int n = idx / EE, e = idx % EE;
        int sec = n / 768;
        int hd = n % 768;
        const float* W = (sec == 0) ? Wq : (sec == 1) ? Wk : Wv;
        float v = W[((hd >> 6) * EE + e) * DD + (hd & 63)];
        if (sec == 0) v *= 0.125f;
        g_wqkvt[idx] = __float2half_rn(v);
    }
    if (idx < QKV_N) {
        int sec = idx / 768;
        const float* bsrc = (sec == 0) ? bq : (sec == 1) ? bk : bv;
        float v = bsrc[idx % 768];
        if (sec == 0) v *= 0.125f;
        g_bqkv[idx] = v;
    }
}

__global__ void transpose_h_kernel(const float* __restrict__ in,
                                   __half* __restrict__ oh, int K, int N) {
    int idx = blockIdx.x * blockDim.x + threadIdx.x;
    if (idx >= N * K) return;
    int n = idx / K, k = idx % K;
    oh[idx] = __float2half_rn(in[(size_t)k * N + n]);
}

// ---------------- LN ----------------
__device__ __forceinline__ float block_reduce_sum_256(float v, float* sbuf) {
    int lane = threadIdx.x & 31, wid = threadIdx.x >> 5;
#pragma unroll
    for (int m = 16; m; m >>= 1) v += __shfl_xor_sync(0xffffffffu, v, m);
    if (lane == 0) sbuf[wid] = v;
    __syncthreads();
    if (wid == 0) {
        v = (lane < 8) ? sbuf[lane] : 0.f;
#pragma unroll
        for (int m = 4; m; m >>= 1) v += __shfl_xor_sync(0xffffffffu, v, m);
        if (lane == 0) sbuf[0] = v;
    }
    __syncthreads();
    float r = sbuf[0];
    __syncthreads();
    return r;
}

__global__ void __launch_bounds__(256) ln_h_kernel(const float* __restrict__ in,
                                                   const float* __restrict__ gam,
                                                   const float* __restrict__ bet,
                                                   __half* __restrict__ oh) {
    __shared__ float sbuf[8];
    size_t row = blockIdx.x;
    const float* x = in + row * EE;
    float s = 0.f;
    for (int i = threadIdx.x; i < EE; i += 256) s += x[i];
    float mu = block_reduce_sum_256(s, sbuf) * (1.f / EE);
    float v = 0.f;
    for (int i = threadIdx.x; i < EE; i += 256) { float d = x[i] - mu; v += d * d; }
    float rstd = rsqrtf(block_reduce_sum_256(v, sbuf) * (1.f / EE) + 1e-5f);
    for (int i = threadIdx.x; i < EE; i += 256)
        oh[row * EE + i] = __float2half_rn((x[i] - mu) * rstd * gam[i] + bet[i]);
}

__global__ void __launch_bounds__(256) ln_final_kernel(const float* __restrict__ in,
                                                       const float* __restrict__ gam,
                                                       const float* __restrict__ bet,
                                                       const float* __restrict__ res,
                                                       float* __restrict__ out) {
    __shared__ float sbuf[8];
    size_t row = blockIdx.x;
    const float* x = in + row * EE;
    float s = 0.f;
    for (int i = threadIdx.x; i < EE; i += 256) s += x[i];
    float mu = block_reduce_sum_256(s, sbuf) * (1.f / EE);
    float v = 0.f;
    for (int i = threadIdx.x; i < EE; i += 256) { float d = x[i] - mu; v += d * d; }
    float rstd = rsqrtf(block_reduce_sum_256(v, sbuf) * (1.f / EE) + 1e-5f);
    for (int i = threadIdx.x; i < EE; i += 256)
        out[row * EE + i] = (x[i] - mu) * rstd * gam[i] + bet[i] + res[row * EE + i];
}

// ---------------- HMMA primitives (fp16) ----------------
__device__ __forceinline__ void cpasync16(uint32_t dst, const void* src) {
    asm volatile("cp.async.cg.shared.global [%0], [%1], 16;" :: "r"(dst), "l"(src));
}
__device__ __forceinline__ void ldm4(uint32_t* r, uint32_t addr) {
    asm volatile("ldmatrix.sync.aligned.m8n8.x4.shared.b16 {%0,%1,%2,%3}, [%4];"
                 : "=r"(r[0]), "=r"(r[1]), "=r"(r[2]), "=r"(r[3]) : "r"(addr));
}
__device__ __forceinline__ void ldm4t(uint32_t* r, uint32_t addr) {
    asm volatile("ldmatrix.sync.aligned.m8n8.x4.trans.shared.b16 {%0,%1,%2,%3}, [%4];"
                 : "=r"(r[0]), "=r"(r[1]), "=r"(r[2]), "=r"(r[3]) : "r"(addr));
}
__device__ __forceinline__ void mma16816(float* d, const uint32_t* a, uint32_t b0, uint32_t b1) {
    asm volatile(
        "mma.sync.aligned.m16n8k16.row.col.f32.f16.f16.f32 "
        "{%0,%1,%2,%3}, {%4,%5,%6,%7}, {%8,%9}, {%0,%1,%2,%3};"
        : "+f"(d[0]), "+f"(d[1]), "+f"(d[2]), "+f"(d[3])
        : "r"(a[0]), "r"(a[1]), "r"(a[2]), "r"(a[3]), "r"(b0), "r"(b1));
}

// ---------------- HMMA GEMM: 256x128 CTA, 64x64 warp, BK=64, 4-stage ----------
// EPI: 0 bias->f32, 1 bias+gelu->fp16, 2 bias+res->f32, 3 bias->fp16
#define STG 49152   // A 32K | B 16K

template <int EPI>
__global__ void __launch_bounds__(256, 1) tcgemm(const __half* __restrict__ Ah,
                                                 const __half* __restrict__ Bh,
                                                 const float* __restrict__ bias,
                                                 const float* __restrict__ res,
                                                 float* __restrict__ C,
                                                 __half* __restrict__ Ch,
                                                 int N, int K) {
    extern __shared__ char sm[];
    uint32_t sbase = (uint32_t)__cvta_generic_to_shared(sm);
    int tid = threadIdx.x;
    int lane = tid & 31, w = tid >> 5;
    int wm = w >> 1, wn = w & 1;                  // 4x2 warp grid, 64x64 tiles
    int bn = blockIdx.x * 128, bm = blockIdx.y * 256;

    float acc[4][8][4];
#pragma unroll
    for (int i = 0; i < 4; i++)
#pragma unroll
        for (int j = 0; j < 8; j++)
#pragma unroll
            for (int q = 0; q < 4; q++) acc[i][j][q] = 0.f;

    int nk = K >> 6;

#define LOAD_STAGE(kc, buf)                                                          \
    {                                                                                \
        uint32_t sb_ = sbase + (buf) * STG;                                          \
        _Pragma("unroll")                                                            \
        for (int ii = 0; ii < 12; ii++) {                                            \
            int i = tid + ii * 256;                                                  \
            if (i < 2048) {                                                          \
                int r = i >> 3, c = i & 7;                                           \
                cpasync16(sb_ + swz(r * 128 + c * 16),                               \
                          Ah + (size_t)(bm + r) * K + (kc) * 64 + c * 8);            \
            } else {                                                                 \
                int j = i - 2048, r = j >> 3, c = j & 7;                             \
                cpasync16(sb_ + 32768 + swz(r * 128 + c * 16),                       \
                          Bh + (size_t)(bn + r) * K + (kc) * 64 + c * 8);            \
            }                                                                        \
        }                                                                            \
        asm volatile("cp.async.commit_group;" ::: "memory");                         \
    }

    LOAD_STAGE(0, 0);
    LOAD_STAGE(1, 1);
    LOAD_STAGE(2, 2);

    int ra = (lane & 7) + ((lane & 8) ? 8 : 0);
    int ka = (lane & 16) ? 8 : 0;
    int rb_n = (lane & 7) + ((lane & 16) ? 8 : 0);
    int kb_n = (lane & 8) ? 8 : 0;

    int buf = 0;
    for (int kc = 0; kc < nk; kc++) {
        if (kc + 3 < nk) {
            int nb = buf + 3;
            if (nb >= 4) nb -= 4;
            LOAD_STAGE(kc + 3, nb);
            asm volatile("cp.async.wait_group 3;" ::: "memory");
        } else if (kc + 2 < nk) {
            asm volatile("cp.async.wait_group 2;" ::: "memory");
        } else if (kc + 1 < nk) {
            asm volatile("cp.async.wait_group 1;" ::: "memory");
        } else {
            asm volatile("cp.async.wait_group 0;" ::: "memory");
        }
        __syncthreads();
        uint32_t sb = sbase + buf * STG;
#pragma unroll
        for (int ks = 0; ks < 4; ks++) {
            uint32_t Af[4][4], Bf[4][4];
#pragma unroll
            for (int mt = 0; mt < 4; mt++) {
                int row = wm * 64 + mt * 16 + ra;
                ldm4(Af[mt], sb + swz(row * 128 + (ks * 16 + ka) * 2));
            }
#pragma unroll
            for (int pr = 0; pr < 4; pr++) {
                int row = wn * 64 + pr * 16 + rb_n;
                ldm4(Bf[pr], sb + 32768 + swz(row * 128 + (ks * 16 + kb_n) * 2));
            }
#pragma unroll
            for (int mt = 0; mt < 4; mt++)
#pragma unroll
                for (int nt = 0; nt < 8; nt++) {
                    int pr = nt >> 1, o = (nt & 1) * 2;
                    mma16816(acc[mt][nt], Af[mt], Bf[pr][o], Bf[pr][o + 1]);
                }
        }
        __syncthreads();
        if (++buf == 4) buf = 0;
    }

    int l4 = lane >> 2, l2 = (lane & 3) * 2;
#pragma unroll
    for (int mt = 0; mt < 4; mt++)
#pragma unroll
        for (int nt = 0; nt < 8; nt++) {
            int col = bn + wn * 64 + nt * 8 + l2;
            float b0 = bias[col], b1 = bias[col + 1];
#pragma unroll
            for (int half = 0; half < 2; half++) {
                size_t row = (size_t)(bm + wm * 64 + mt * 16 + l4 + half * 8);
                float v0 = acc[mt][nt][half * 2 + 0] + b0;
                float v1 = acc[mt][nt][half * 2 + 1] + b1;
                if (EPI == 2) {
                    v0 += res[row * N + col];
                    v1 += res[row * N + col + 1];
                }
                if (EPI == 1) {
                    v0 = 0.5f * v0 * (1.0f + erff(v0 * 0.70710678118654752f));
                    v1 = 0.5f * v1 * (1.0f + erff(v1 * 0.70710678118654752f));
                }
                if (EPI == 1 || EPI == 3) {
                    *(__half2*)&Ch[row * N + col] = __floats2half2_rn(v0, v1);
                } else {
                    *(float2*)&C[row * N + col] = make_float2(v0, v1);
                }
            }
        }
#undef LOAD_STAGE
}

// ---------------- HMMA flash attention: 128-row Q tile, 256 threads ----------
// smem: Q 16K | KV0 16K | KV1 16K = 48KB. K [t][d]; V [t][d] via ldmatrix.trans.
__global__ void __launch_bounds__(256) attn_kernel(const __half* __restrict__ qkvh,
                                                   __half* __restrict__ oh) {
    extern __shared__ char smc[];
    uint32_t sb = (uint32_t)__cvta_generic_to_shared(smc);
    uint32_t Qs = sb;

    int qt = blockIdx.x, bh = blockIdx.y;
    int b = bh / HH, h = bh % HH;
    int tid = threadIdx.x, lane = tid & 31, w = tid >> 5;
    size_t base = (size_t)b * SS * QKV_N;
    int hoff = h * DD;

    // Q tile: 128 rows x 128B
#pragma unroll
    for (int ii = 0; ii < 4; ii++) {
        int i = tid + ii * 256;
        int r = i >> 3, c = i & 7;
        cpasync16(Qs + swz(r * 128 + c * 16),
                  qkvh + base + (size_t)(qt * 128 + r) * QKV_N + hoff + c * 8);
    }

#define ISSUE_KV(kt, bufo)                                                          \
    {                                                                               \
        _Pragma("unroll")                                                           \
        for (int ii = 0; ii < 4; ii++) {                                            \
            int i = tid + ii * 256;                                                 \
            int ts = i >> 9, wrd = i & 511, r = wrd >> 3, c = wrd & 7;              \
            cpasync16(sb + (bufo) + ts * 8192 + swz(r * 128 + c * 16),              \
                      qkvh + base + (size_t)((kt) * 64 + r) * QKV_N + hoff +        \
                          (ts ? 2 * EE : EE) + c * 8);                              \
        }                                                                           \
        asm volatile("cp.async.commit_group;" ::: "memory");                        \
    }

    ISSUE_KV(0, 16384);

    int ra = (lane & 7) + ((lane & 8) ? 8 : 0);
    int ka = (lane & 16) ? 8 : 0;
    int rbn = (lane & 7) + ((lane & 16) ? 8 : 0);
    int kbn = (lane & 8) ? 8 : 0;
    int vkr = (lane & 7) + ((lane & 8) ? 8 : 0);
    int vnc = (lane & 16) ? 8 : 0;
    int r0 = lane >> 2, c0 = (lane & 3) * 2;

    int qrow = qt * 128 + w * 16;   // warp's first global q row
    int ktmax = 2 * qt + 1;

    float m0 = -1e30f, m1 = -1e30f, l0 = 0.f, l1 = 0.f;
    float o[8][4];
#pragma unroll
    for (int i = 0; i < 8; i++)
#pragma unroll
        for (int j = 0; j < 4; j++) o[i][j] = 0.f;

    for (int kt = 0; kt <= ktmax; kt++) {
        asm volatile("cp.async.wait_group 0;" ::: "memory");
        __syncthreads();
        uint32_t kvo = 16384 + (kt & 1) * 16384;
        if (kt < ktmax) ISSUE_KV(kt + 1, 16384 + ((kt + 1) & 1) * 16384);
        uint32_t Kh = sb + kvo, Vh = sb + kvo + 8192;

        if (kt * 64 <= qrow + 15) {   // not fully masked for this warp
            float s[8][4];
#pragma unroll
            for (int i = 0; i < 8; i++)
#pragma unroll
                for (int j = 0; j < 4; j++) s[i][j] = 0.f;
#pragma unroll
            for (int kc = 0; kc < 4; kc++) {
                uint32_t qh[4], kh[4][4];
                ldm4(qh, Qs + swz((w * 16 + ra) * 128 + (kc * 16 + ka) * 2));
#pragma unroll
                for (int tg = 0; tg < 4; tg++)
                    ldm4(kh[tg], Kh + swz((tg * 16 + rbn) * 128 + (kc * 16 + kbn) * 2));
#pragma unroll
                for (int nt = 0; nt < 8; nt++) {
                    int pr = nt >> 1, oo = (nt & 1) * 2;
                    mma16816(s[nt], qh, kh[pr][oo], kh[pr][oo + 1]);
                }
            }

            if (kt * 64 + 63 > qrow) {   // diagonal: elementwise causal mask
                int row0 = qrow + r0, row1 = row0 + 8;
#pragma unroll
                for (int nt = 0; nt < 8; nt++) {
                    int c = kt * 64 + nt * 8 + c0;
                    if (c > row0) s[nt][0] = -1e30f;
                    if (c + 1 > row0) s[nt][1] = -1e30f;
                    if (c > row1) s[nt][2] = -1e30f;
                    if (c + 1 > row1) s[nt][3] = -1e30f;
                }
            }

            float mt0 = -1e30f, mt1 = -1e30f;
#pragma unroll
            for (int nt = 0; nt < 8; nt++) {
                mt0 = fmaxf(mt0, fmaxf(s[nt][0], s[nt][1]));
                mt1 = fmaxf(mt1, fmaxf(s[nt][2], s[nt][3]));
            }
#pragma unroll
            for (int off = 1; off <= 2; off <<= 1) {
                mt0 = fmaxf(mt0, __shfl_xor_sync(0xffffffffu, mt0, off));
                mt1 = fmaxf(mt1, __shfl_xor_sync(0xffffffffu, mt1, off));
            }
            float mn0 = fmaxf(m0, mt0), mn1 = fmaxf(m1, mt1);
            float sc0 = __expf(m0 - mn0), sc1 = __expf(m1 - mn1);
            float rs0 = 0.f, rs1 = 0.f;
#pragma unroll
            for (int nt = 0; nt < 8; nt++) {
                s[nt][0] = __expf(s[nt][0] - mn0);
                s[nt][1] = __expf(s[nt][1] - mn0);
                s[nt][2] = __expf(s[nt][2] - mn1);
                s[nt][3] = __expf(s[nt][3] - mn1);
                rs0 += s[nt][0] + s[nt][1];
                rs1 += s[nt][2] + s[nt][3];
            }
#pragma unroll
            for (int off = 1; off <= 2; off <<= 1) {
                rs0 += __shfl_xor_sync(0xffffffffu, rs0, off);
                rs1 += __shfl_xor_sync(0xffffffffu, rs1, off);
            }
            l0 = l0 * sc0 + rs0;
            l1 = l1 * sc1 + rs1;
            m0 = mn0;
            m1 = mn1;
#pragma unroll
            for (int i = 0; i < 8; i++) {
                o[i][0] *= sc0; o[i][1] *= sc0;
                o[i][2] *= sc1; o[i][3] *= sc1;
            }

#pragma unroll
            for (int kc = 0; kc < 4; kc++) {
                uint32_t aph[4];
                aph[0] = pack2(s[2 * kc][0], s[2 * kc][1]);
                aph[1] = pack2(s[2 * kc][2], s[2 * kc][3]);
                aph[2] = pack2(s[2 * kc + 1][0], s[2 * kc + 1][1]);
                aph[3] = pack2(s[2 * kc + 1][2], s[2 * kc + 1][3]);
                uint32_t vh[4][4];
#pragma unroll
                for (int dg = 0; dg < 4; dg++)
                    ldm4t(vh[dg], Vh + swz((kc * 16 + vkr) * 128 + (dg * 16 + vnc) * 2));
#pragma unroll
                for (int dt = 0; dt < 8; dt++) {
                    int pr = dt >> 1, oo = (dt & 1) * 2;
                    mma16816(o[dt], aph, vh[pr][oo], vh[pr][oo + 1]);
                }
            }
        }
        __syncthreads();
    }

    float inv0 = 1.f / l0, inv1 = 1.f / l1;
    size_t row0 = (size_t)b * SS + qrow + r0;
    size_t row1 = row0 + 8;
#pragma unroll
    for (int dt = 0; dt < 8; dt++) {
        int d = hoff + dt * 8 + c0;
        *(__half2*)&oh[row0 * EE + d] = __floats2half2_rn(o[dt][0] * inv0, o[dt][1] * inv0);
        *(__half2*)&oh[row1 * EE + d] = __floats2half2_rn(o[dt][2] * inv1, o[dt][3] * inv1);
    }
#undef ISSUE_KV
}

// ---------------- launch ----------------
extern "C" void kernel_launch(void* const* d_in, const int* in_sizes, int n_in,
                              void* d_out, int out_size) {
    const float* x = (const float*)d_in[0];
    const float* Wq = (const float*)d_in[1];
    const float* bq = (const float*)d_in[2];
    const float* Wk = (const float*)d_in[3];
    const float* bk = (const float*)d_in[4];
    const float* Wv = (const float*)d_in[5];
    const float* bv = (const float*)d_in[6];
    const float* Wp = (const float*)d_in[7];
    const float* bp = (const float*)d_in[8];
    const float* ln1_g = (const float*)d_in[9];
    const float* ln1_b = (const float*)d_in[10];
    const float* ln2_g = (const float*)d_in[11];
    const float* ln2_b = (const float*)d_in[12];
    const float* W1 = (const float*)d_in[13];
    const float* b1 = (const float*)d_in[14];
    const float* W2 = (const float*)d_in[15];
    const float* b2 = (const float*)d_in[16];
    const float* lnf_g = (const float*)d_in[17];
    const float* lnf_b = (const float*)d_in[18];
    float* out = (float*)d_out;

    __half *p_ah, *p_fh, *p_qkvh, *p_wq, *p_wp, *p_w1, *p_w2;
    float *p_bqkv, *p_x1, *p_f2;
    cudaGetSymbolAddress((void**)&p_ah, g_ah);
    cudaGetSymbolAddress((void**)&p_fh, g_fh);
    cudaGetSymbolAddress((void**)&p_qkvh, g_qkvh);
    cudaGetSymbolAddress((void**)&p_wq, g_wqkvt);
    cudaGetSymbolAddress((void**)&p_wp, g_wpt);
    cudaGetSymbolAddress((void**)&p_w1, g_w1t);
    cudaGetSymbolAddress((void**)&p_w2, g_w2t);
    cudaGetSymbolAddress((void**)&p_bqkv, g_bqkv);
    cudaGetSymbolAddress((void**)&p_x1, g_x1);
    cudaGetSymbolAddress((void**)&p_f2, g_f2);

    int gsmem = 4 * STG;  // 196608
    cudaFuncSetAttribute(tcgemm<0>, cudaFuncAttributeMaxDynamicSharedMemorySize, gsmem);
    cudaFuncSetAttribute(tcgemm<1>, cudaFuncAttributeMaxDynamicSharedMemorySize, gsmem);
    cudaFuncSetAttribute(tcgemm<2>, cudaFuncAttributeMaxDynamicSharedMemorySize, gsmem);
    cudaFuncSetAttribute(tcgemm<3>, cudaFuncAttributeMaxDynamicSharedMemorySize, gsmem);
    int asmem = 49152;
    cudaFuncSetAttribute(attn_kernel, cudaFuncAttributeMaxDynamicSharedMemorySize, asmem);

    pack_wqkv_kernel<<<(QKV_N * EE + 255) / 256, 256>>>(Wq, Wk, Wv, bq, bk, bv);
    transpose_h_kernel<<<(EE * EE + 255) / 256, 256>>>(Wp, p_wp, EE, EE);
    transpose_h_kernel<<<(EE * FF + 255) / 256, 256>>>(W1, p_w1, EE, FF);
    transpose_h_kernel<<<(FF * EE + 255) / 256, 256>>>(W2, p_w2, FF, EE);

    ln_h_kernel<<<ROWS, 256>>>(x, ln1_g, ln1_b, p_ah);
    tcgemm<3><<<dim3(QKV_N / 128, ROWS / 256), 256, gsmem>>>(
        p_ah, p_wq, p_bqkv, nullptr, nullptr, p_qkvh, QKV_N, EE);
    attn_kernel<<<dim3(SS / 128, BB * HH), 256, asmem>>>(p_qkvh, p_ah);
    tcgemm<2><<<dim3(EE / 128, ROWS / 256), 256, gsmem>>>(
        p_ah, p_wp, bp, x, p_x1, nullptr, EE, EE);
    ln_h_kernel<<<ROWS, 256>>>(p_x1, ln2_g, ln2_b, p_ah);
    tcgemm<1><<<dim3(FF / 128, ROWS / 256), 256, gsmem>>>(
        p_ah, p_w1, b1, nullptr, nullptr, p_fh, FF, EE);
    tcgemm<0><<<dim3(EE / 128, ROWS / 256), 256, gsmem>>>(
        p_fh, p_w2, b2, nullptr, p_f2, nullptr, EE, FF);
    ln_final_kernel<<<ROWS, 256>>>(p_f2, lnf_g, lnf_b, p_x1, out);
}

// round 11
// speedup vs baseline: 10.7837x; 1.0891x over previous
#include <cuda_runtime.h>
#include <cuda_fp16.h>
#include <math.h>
#include <stdint.h>

#define BB 16
#define SS 1024
#define EE 768
#define HH 12
#define DD 64
#define FF 3072
#define ROWS (BB * SS)
#define QKV_N (3 * EE)

// scratch
__device__ __half g_ah[ROWS * EE];
__device__ __half g_fh[ROWS * FF];
__device__ __half g_qkvh[ROWS * QKV_N];
__device__ __half g_wqkvt[QKV_N * EE];
__device__ __half g_wpt[EE * EE];
__device__ __half g_w1t[FF * EE];
__device__ __half g_w2t[EE * FF];
__device__ float g_bqkv[QKV_N];
__device__ float g_x1[ROWS * EE];
__device__ float g_f2[ROWS * EE];

__device__ __forceinline__ uint32_t swz(uint32_t o) { return o ^ ((o >> 3) & 0x70); }
__device__ __forceinline__ uint32_t pack2(float x, float y) {
    __half2 t = __floats2half2_rn(x, y);
    return *(uint32_t*)&t;
}

// ---------------- weight prep (tiled, coalesced) ----------------
// grid (2, 24, 36): x = d-tile (64/32), y = e-tile (768/32), z = sec*12+h. block 32x8.
__global__ void pack_wqkv_tiled(const float* __restrict__ Wq, const float* __restrict__ Wk,
                                const float* __restrict__ Wv) {
    __shared__ float t[32][33];
    int z = blockIdx.z, sec = z / 12, h = z % 12;
    const float* W = (sec == 0) ? Wq : (sec == 1) ? Wk : Wv;
    float sc = (sec == 0) ? 0.125f : 1.0f;
    int d0 = blockIdx.x * 32, e0 = blockIdx.y * 32;
    int tx = threadIdx.x, ty = threadIdx.y;
#pragma unroll
    for (int j = ty; j < 32; j += 8)
        t[j][tx] = W[((size_t)h * EE + e0 + j) * DD + d0 + tx] * sc;
    __syncthreads();
#pragma unroll
    for (int j = ty; j < 32; j += 8)
        g_wqkvt[(size_t)(sec * 768 + h * 64 + d0 + j) * EE + e0 + tx] =
            __float2half_rn(t[tx][j]);
}

__global__ void pack_bias_kernel(const float* __restrict__ bq, const float* __restrict__ bk,
                                 const float* __restrict__ bv) {
    int idx = blockIdx.x * blockDim.x + threadIdx.x;
    if (idx >= QKV_N) return;
    int sec = idx / 768;
    const float* bsrc = (sec == 0) ? bq : (sec == 1) ? bk : bv;
    float v = bsrc[idx % 768];
    g_bqkv[idx] = (sec == 0) ? v * 0.125f : v;
}

// in [K,N] f32 -> oh [N,K] fp16. grid (N/32, K/32), block 32x8.
__global__ void transpose_h_tiled(const float* __restrict__ in,
                                  __half* __restrict__ oh, int K, int N) {
    __shared__ float t[32][33];
    int n0 = blockIdx.x * 32, k0 = blockIdx.y * 32;
    int tx = threadIdx.x, ty = threadIdx.y;
#pragma unroll
    for (int j = ty; j < 32; j += 8)
        t[j][tx] = in[(size_t)(k0 + j) * N + n0 + tx];
    __syncthreads();
#pragma unroll
    for (int j = ty; j < 32; j += 8)
        oh[(size_t)(n0 + j) * K + k0 + tx] = __float2half_rn(t[tx][j]);
}

// ---------------- LN (vectorized, 192 threads = 768/4) ----------------
__device__ __forceinline__ float brs192(float v, float* sbuf) {
    int lane = threadIdx.x & 31, wid = threadIdx.x >> 5;   // 6 warps
#pragma unroll
    for (int m = 16; m; m >>= 1) v += __shfl_xor_sync(0xffffffffu, v, m);
    if (lane == 0) sbuf[wid] = v;
    __syncthreads();
    if (wid == 0) {
        v = (lane < 6) ? sbuf[lane] : 0.f;
#pragma unroll
        for (int m = 4; m; m >>= 1) v += __shfl_xor_sync(0xffffffffu, v, m);
        if (lane == 0) sbuf[0] = v;
    }
    __syncthreads();
    float r = sbuf[0];
    __syncthreads();
    return r;
}

__global__ void __launch_bounds__(192) ln_h_kernel(const float* __restrict__ in,
                                                   const float* __restrict__ gam,
                                                   const float* __restrict__ bet,
                                                   __half* __restrict__ oh) {
    __shared__ float sbuf[6];
    size_t row = blockIdx.x;
    int tid = threadIdx.x;
    float4 xv = ((const float4*)(in + row * EE))[tid];
    float s = xv.x + xv.y + xv.z + xv.w;
    float mu = brs192(s, sbuf) * (1.f / EE);
    float dx = xv.x - mu, dy = xv.y - mu, dz = xv.z - mu, dw = xv.w - mu;
    float v = dx * dx + dy * dy + dz * dz + dw * dw;
    float rstd = rsqrtf(brs192(v, sbuf) * (1.f / EE) + 1e-5f);
    float4 g = ((const float4*)gam)[tid];
    float4 be = ((const float4*)bet)[tid];
    uint2 o;
    o.x = pack2(dx * rstd * g.x + be.x, dy * rstd * g.y + be.y);
    o.y = pack2(dz * rstd * g.z + be.z, dw * rstd * g.w + be.w);
    *(uint2*)(oh + row * EE + tid * 4) = o;
}

__global__ void __launch_bounds__(192) ln_final_kernel(const float* __restrict__ in,
                                                       const float* __restrict__ gam,
                                                       const float* __restrict__ bet,
                                                       const float* __restrict__ res,
                                                       float* __restrict__ out) {
    __shared__ float sbuf[6];
    size_t row = blockIdx.x;
    int tid = threadIdx.x;
    float4 xv = ((const float4*)(in + row * EE))[tid];
    float s = xv.x + xv.y + xv.z + xv.w;
    float mu = brs192(s, sbuf) * (1.f / EE);
    float dx = xv.x - mu, dy = xv.y - mu, dz = xv.z - mu, dw = xv.w - mu;
    float v = dx * dx + dy * dy + dz * dz + dw * dw;
    float rstd = rsqrtf(brs192(v, sbuf) * (1.f / EE) + 1e-5f);
    float4 g = ((const float4*)gam)[tid];
    float4 be = ((const float4*)bet)[tid];
    float4 r = ((const float4*)(res + row * EE))[tid];
    float4 o;
    o.x = dx * rstd * g.x + be.x + r.x;
    o.y = dy * rstd * g.y + be.y + r.y;
    o.z = dz * rstd * g.z + be.z + r.z;
    o.w = dw * rstd * g.w + be.w + r.w;
    ((float4*)(out + row * EE))[tid] = o;
}

// ---------------- HMMA primitives (fp16) ----------------
__device__ __forceinline__ void cpasync16(uint32_t dst, const void* src) {
    asm volatile("cp.async.cg.shared.global [%0], [%1], 16;" :: "r"(dst), "l"(src));
}
__device__ __forceinline__ void ldm4(uint32_t* r, uint32_t addr) {
    asm volatile("ldmatrix.sync.aligned.m8n8.x4.shared.b16 {%0,%1,%2,%3}, [%4];"
                 : "=r"(r[0]), "=r"(r[1]), "=r"(r[2]), "=r"(r[3]) : "r"(addr));
}
__device__ __forceinline__ void ldm4t(uint32_t* r, uint32_t addr) {
    asm volatile("ldmatrix.sync.aligned.m8n8.x4.trans.shared.b16 {%0,%1,%2,%3}, [%4];"
                 : "=r"(r[0]), "=r"(r[1]), "=r"(r[2]), "=r"(r[3]) : "r"(addr));
}
__device__ __forceinline__ void mma16816(float* d, const uint32_t* a, uint32_t b0, uint32_t b1) {
    asm volatile(
        "mma.sync.aligned.m16n8k16.row.col.f32.f16.f16.f32 "
        "{%0,%1,%2,%3}, {%4,%5,%6,%7}, {%8,%9}, {%0,%1,%2,%3};"
        : "+f"(d[0]), "+f"(d[1]), "+f"(d[2]), "+f"(d[3])
        : "r"(a[0]), "r"(a[1]), "r"(a[2]), "r"(a[3]), "r"(b0), "r"(b1));
}

// ---------------- HMMA GEMM: 256x128 CTA, 64x64 warp, BK=64, 4-stage ----------
// EPI: 0 bias->f32, 1 bias+gelu->fp16, 2 bias+res->f32, 3 bias->fp16
#define STG 49152   // A 32K | B 16K

template <int EPI>
__global__ void __launch_bounds__(256, 1) tcgemm(const __half* __restrict__ Ah,
                                                 const __half* __restrict__ Bh,
                                                 const float* __restrict__ bias,
                                                 const float* __restrict__ res,
                                                 float* __restrict__ C,
                                                 __half* __restrict__ Ch,
                                                 int N, int K) {
    extern __shared__ char sm[];
    uint32_t sbase = (uint32_t)__cvta_generic_to_shared(sm);
    int tid = threadIdx.x;
    int lane = tid & 31, w = tid >> 5;
    int wm = w >> 1, wn = w & 1;
    int bn = blockIdx.x * 128, bm = blockIdx.y * 256;

    float acc[4][8][4];
#pragma unroll
    for (int i = 0; i < 4; i++)
#pragma unroll
        for (int j = 0; j < 8; j++)
#pragma unroll
            for (int q = 0; q < 4; q++) acc[i][j][q] = 0.f;

    int nk = K >> 6;

#define LOAD_STAGE(kc, buf)                                                          \
    {                                                                                \
        uint32_t sb_ = sbase + (buf) * STG;                                          \
        _Pragma("unroll")                                                            \
        for (int ii = 0; ii < 12; ii++) {                                            \
            int i = tid + ii * 256;                                                  \
            if (i < 2048) {                                                          \
                int r = i >> 3, c = i & 7;                                           \
                cpasync16(sb_ + swz(r * 128 + c * 16),                               \
                          Ah + (size_t)(bm + r) * K + (kc) * 64 + c * 8);            \
            } else {                                                                 \
                int j = i - 2048, r = j >> 3, c = j & 7;                             \
                cpasync16(sb_ + 32768 + swz(r * 128 + c * 16),                       \
                          Bh + (size_t)(bn + r) * K + (kc) * 64 + c * 8);            \
            }                                                                        \
        }                                                                            \
        asm volatile("cp.async.commit_group;" ::: "memory");                         \
    }

    LOAD_STAGE(0, 0);
    LOAD_STAGE(1, 1);
    LOAD_STAGE(2, 2);

    int ra = (lane & 7) + ((lane & 8) ? 8 : 0);
    int ka = (lane & 16) ? 8 : 0;
    int rb_n = (lane & 7) + ((lane & 16) ? 8 : 0);
    int kb_n = (lane & 8) ? 8 : 0;

    int buf = 0;
    for (int kc = 0; kc < nk; kc++) {
        if (kc + 3 < nk) {
            int nb = buf + 3;
            if (nb >= 4) nb -= 4;
            LOAD_STAGE(kc + 3, nb);
            asm volatile("cp.async.wait_group 3;" ::: "memory");
        } else if (kc + 2 < nk) {
            asm volatile("cp.async.wait_group 2;" ::: "memory");
        } else if (kc + 1 < nk) {
            asm volatile("cp.async.wait_group 1;" ::: "memory");
        } else {
            asm volatile("cp.async.wait_group 0;" ::: "memory");
        }
        __syncthreads();
        uint32_t sb = sbase + buf * STG;
#pragma unroll
        for (int ks = 0; ks < 4; ks++) {
            uint32_t Af[4][4], Bf[4][4];
#pragma unroll
            for (int mt = 0; mt < 4; mt++) {
                int row = wm * 64 + mt * 16 + ra;
                ldm4(Af[mt], sb + swz(row * 128 + (ks * 16 + ka) * 2));
            }
#pragma unroll
            for (int pr = 0; pr < 4; pr++) {
                int row = wn * 64 + pr * 16 + rb_n;
                ldm4(Bf[pr], sb + 32768 + swz(row * 128 + (ks * 16 + kb_n) * 2));
            }
#pragma unroll
            for (int mt = 0; mt < 4; mt++)
#pragma unroll
                for (int nt = 0; nt < 8; nt++) {
                    int pr = nt >> 1, o = (nt & 1) * 2;
                    mma16816(acc[mt][nt], Af[mt], Bf[pr][o], Bf[pr][o + 1]);
                }
        }
        __syncthreads();
        if (++buf == 4) buf = 0;
    }

    int l4 = lane >> 2, l2 = (lane & 3) * 2;
#pragma unroll
    for (int mt = 0; mt < 4; mt++)
#pragma unroll
        for (int nt = 0; nt < 8; nt++) {
            int col = bn + wn * 64 + nt * 8 + l2;
            float b0 = bias[col], b1 = bias[col + 1];
#pragma unroll
            for (int half = 0; half < 2; half++) {
                size_t row = (size_t)(bm + wm * 64 + mt * 16 + l4 + half * 8);
                float v0 = acc[mt][nt][half * 2 + 0] + b0;
                float v1 = acc[mt][nt][half * 2 + 1] + b1;
                if (EPI == 2) {
                    v0 += res[row * N + col];
                    v1 += res[row * N + col + 1];
                }
                if (EPI == 1) {
                    v0 = 0.5f * v0 * (1.0f + erff(v0 * 0.70710678118654752f));
                    v1 = 0.5f * v1 * (1.0f + erff(v1 * 0.70710678118654752f));
                }
                if (EPI == 1 || EPI == 3) {
                    *(__half2*)&Ch[row * N + col] = __floats2half2_rn(v0, v1);
                } else {
                    *(float2*)&C[row * N + col] = make_float2(v0, v1);
                }
            }
        }
#undef LOAD_STAGE
}

// ---------------- HMMA flash attention: 128-row Q tile, 256 threads ----------
__global__ void __launch_bounds__(256) attn_kernel(const __half* __restrict__ qkvh,
                                                   __half* __restrict__ oh) {
    extern __shared__ char smc[];
    uint32_t sb = (uint32_t)__cvta_generic_to_shared(smc);
    uint32_t Qs = sb;

    int qt = blockIdx.x, bh = blockIdx.y;
    int b = bh / HH, h = bh % HH;
    int tid = threadIdx.x, lane = tid & 31, w = tid >> 5;
    size_t base = (size_t)b * SS * QKV_N;
    int hoff = h * DD;

#pragma unroll
    for (int ii = 0; ii < 4; ii++) {
        int i = tid + ii * 256;
        int r = i >> 3, c = i & 7;
        cpasync16(Qs + swz(r * 128 + c * 16),
                  qkvh + base + (size_t)(qt * 128 + r) * QKV_N + hoff + c * 8);
    }

#define ISSUE_KV(kt, bufo)                                                          \
    {                                                                               \
        _Pragma("unroll")                                                           \
        for (int ii = 0; ii < 4; ii++) {                                            \
            int i = tid + ii * 256;                                                 \
            int ts = i >> 9, wrd = i & 511, r = wrd >> 3, c = wrd & 7;              \
            cpasync16(sb + (bufo) + ts * 8192 + swz(r * 128 + c * 16),              \
                      qkvh + base + (size_t)((kt) * 64 + r) * QKV_N + hoff +        \
                          (ts ? 2 * EE : EE) + c * 8);                              \
        }                                                                           \
        asm volatile("cp.async.commit_group;" ::: "memory");                        \
    }

    ISSUE_KV(0, 16384);

    int ra = (lane & 7) + ((lane & 8) ? 8 : 0);
    int ka = (lane & 16) ? 8 : 0;
    int rbn = (lane & 7) + ((lane & 16) ? 8 : 0);
    int kbn = (lane & 8) ? 8 : 0;
    int vkr = (lane & 7) + ((lane & 8) ? 8 : 0);
    int vnc = (lane & 16) ? 8 : 0;
    int r0 = lane >> 2, c0 = (lane & 3) * 2;

    int qrow = qt * 128 + w * 16;
    int ktmax = 2 * qt + 1;

    float m0 = -1e30f, m1 = -1e30f, l0 = 0.f, l1 = 0.f;
    float o[8][4];
#pragma unroll
    for (int i = 0; i < 8; i++)
#pragma unroll
        for (int j = 0; j < 4; j++) o[i][j] = 0.f;

    for (int kt = 0; kt <= ktmax; kt++) {
        asm volatile("cp.async.wait_group 0;" ::: "memory");
        __syncthreads();
        uint32_t kvo = 16384 + (kt & 1) * 16384;
        if (kt < ktmax) ISSUE_KV(kt + 1, 16384 + ((kt + 1) & 1) * 16384);
        uint32_t Kh = sb + kvo, Vh = sb + kvo + 8192;

        if (kt * 64 <= qrow + 15) {
            float s[8][4];
#pragma unroll
            for (int i = 0; i < 8; i++)
#pragma unroll
                for (int j = 0; j < 4; j++) s[i][j] = 0.f;
#pragma unroll
            for (int kc = 0; kc < 4; kc++) {
                uint32_t qh[4], kh[4][4];
                ldm4(qh, Qs + swz((w * 16 + ra) * 128 + (kc * 16 + ka) * 2));
#pragma unroll
                for (int tg = 0; tg < 4; tg++)
                    ldm4(kh[tg], Kh + swz((tg * 16 + rbn) * 128 + (kc * 16 + kbn) * 2));
#pragma unroll
                for (int nt = 0; nt < 8; nt++) {
                    int pr = nt >> 1, oo = (nt & 1) * 2;
                    mma16816(s[nt], qh, kh[pr][oo], kh[pr][oo + 1]);
                }
            }

            if (kt * 64 + 63 > qrow) {
                int row0 = qrow + r0, row1 = row0 + 8;
#pragma unroll
                for (int nt = 0; nt < 8; nt++) {
                    int c = kt * 64 + nt * 8 + c0;
                    if (c > row0) s[nt][0] = -1e30f;
                    if (c + 1 > row0) s[nt][1] = -1e30f;
                    if (c > row1) s[nt][2] = -1e30f;
                    if (c + 1 > row1) s[nt][3] = -1e30f;
                }
            }

            float mt0 = -1e30f, mt1 = -1e30f;
#pragma unroll
            for (int nt = 0; nt < 8; nt++) {
                mt0 = fmaxf(mt0, fmaxf(s[nt][0], s[nt][1]));
                mt1 = fmaxf(mt1, fmaxf(s[nt][2], s[nt][3]));
            }
#pragma unroll
            for (int off = 1; off <= 2; off <<= 1) {
                mt0 = fmaxf(mt0, __shfl_xor_sync(0xffffffffu, mt0, off));
                mt1 = fmaxf(mt1, __shfl_xor_sync(0xffffffffu, mt1, off));
            }
            float mn0 = fmaxf(m0, mt0), mn1 = fmaxf(m1, mt1);
            float sc0 = __expf(m0 - mn0), sc1 = __expf(m1 - mn1);
            float rs0 = 0.f, rs1 = 0.f;
#pragma unroll
            for (int nt = 0; nt < 8; nt++) {
                s[nt][0] = __expf(s[nt][0] - mn0);
                s[nt][1] = __expf(s[nt][1] - mn0);
                s[nt][2] = __expf(s[nt][2] - mn1);
                s[nt][3] = __expf(s[nt][3] - mn1);
                rs0 += s[nt][0] + s[nt][1];
                rs1 += s[nt][2] + s[nt][3];
            }
#pragma unroll
            for (int off = 1; off <= 2; off <<= 1) {
                rs0 += __shfl_xor_sync(0xffffffffu, rs0, off);
                rs1 += __shfl_xor_sync(0xffffffffu, rs1, off);
            }
            l0 = l0 * sc0 + rs0;
            l1 = l1 * sc1 + rs1;
            m0 = mn0;
            m1 = mn1;
#pragma unroll
            for (int i = 0; i < 8; i++) {
                o[i][0] *= sc0; o[i][1] *= sc0;
                o[i][2] *= sc1; o[i][3] *= sc1;
            }

#pragma unroll
            for (int kc = 0; kc < 4; kc++) {
                uint32_t aph[4];
                aph[0] = pack2(s[2 * kc][0], s[2 * kc][1]);
                aph[1] = pack2(s[2 * kc][2], s[2 * kc][3]);
                aph[2] = pack2(s[2 * kc + 1][0], s[2 * kc + 1][1]);
                aph[3] = pack2(s[2 * kc + 1][2], s[2 * kc + 1][3]);
                uint32_t vh[4][4];
#pragma unroll
                for (int dg = 0; dg < 4; dg++)
                    ldm4t(vh[dg], Vh + swz((kc * 16 + vkr) * 128 + (dg * 16 + vnc) * 2));
#pragma unroll
                for (int dt = 0; dt < 8; dt++) {
                    int pr = dt >> 1, oo = (dt & 1) * 2;
                    mma16816(o[dt], aph, vh[pr][oo], vh[pr][oo + 1]);
                }
            }
        }
        __syncthreads();
    }

    float inv0 = 1.f / l0, inv1 = 1.f / l1;
    size_t row0 = (size_t)b * SS + qrow + r0;
    size_t row1 = row0 + 8;
#pragma unroll
    for (int dt = 0; dt < 8; dt++) {
        int d = hoff + dt * 8 + c0;
        *(__half2*)&oh[row0 * EE + d] = __floats2half2_rn(o[dt][0] * inv0, o[dt][1] * inv0);
        *(__half2*)&oh[row1 * EE + d] = __floats2half2_rn(o[dt][2] * inv1, o[dt][3] * inv1);
    }
#undef ISSUE_KV
}

// ---------------- launch ----------------
extern "C" void kernel_launch(void* const* d_in, const int* in_sizes, int n_in,
                              void* d_out, int out_size) {
    const float* x = (const float*)d_in[0];
    const float* Wq = (const float*)d_in[1];
    const float* bq = (const float*)d_in[2];
    const float* Wk = (const float*)d_in[3];
    const float* bk = (const float*)d_in[4];
    const float* Wv = (const float*)d_in[5];
    const float* bv = (const float*)d_in[6];
    const float* Wp = (const float*)d_in[7];
    const float* bp = (const float*)d_in[8];
    const float* ln1_g = (const float*)d_in[9];
    const float* ln1_b = (const float*)d_in[10];
    const float* ln2_g = (const float*)d_in[11];
    const float* ln2_b = (const float*)d_in[12];
    const float* W1 = (const float*)d_in[13];
    const float* b1 = (const float*)d_in[14];
    const float* W2 = (const float*)d_in[15];
    const float* b2 = (const float*)d_in[16];
    const float* lnf_g = (const float*)d_in[17];
    const float* lnf_b = (const float*)d_in[18];
    float* out = (float*)d_out;

    __half *p_ah, *p_fh, *p_qkvh, *p_wq, *p_wp, *p_w1, *p_w2;
    float *p_bqkv, *p_x1, *p_f2;
    cudaGetSymbolAddress((void**)&p_ah, g_ah);
    cudaGetSymbolAddress((void**)&p_fh, g_fh);
    cudaGetSymbolAddress((void**)&p_qkvh, g_qkvh);
    cudaGetSymbolAddress((void**)&p_wq, g_wqkvt);
    cudaGetSymbolAddress((void**)&p_wp, g_wpt);
    cudaGetSymbolAddress((void**)&p_w1, g_w1t);
    cudaGetSymbolAddress((void**)&p_w2, g_w2t);
    cudaGetSymbolAddress((void**)&p_bqkv, g_bqkv);
    cudaGetSymbolAddress((void**)&p_x1, g_x1);
    cudaGetSymbolAddress((void**)&p_f2, g_f2);

    int gsmem = 4 * STG;  // 196608
    cudaFuncSetAttribute(tcgemm<0>, cudaFuncAttributeMaxDynamicSharedMemorySize, gsmem);
    cudaFuncSetAttribute(tcgemm<1>, cudaFuncAttributeMaxDynamicSharedMemorySize, gsmem);
    cudaFuncSetAttribute(tcgemm<2>, cudaFuncAttributeMaxDynamicSharedMemorySize, gsmem);
    cudaFuncSetAttribute(tcgemm<3>, cudaFuncAttributeMaxDynamicSharedMemorySize, gsmem);
    int asmem = 49152;
    cudaFuncSetAttribute(attn_kernel, cudaFuncAttributeMaxDynamicSharedMemorySize, asmem);

    dim3 tb(32, 8);
    pack_wqkv_tiled<<<dim3(2, 24, 36), tb>>>(Wq, Wk, Wv);
    pack_bias_kernel<<<9, 256>>>(bq, bk, bv);
    transpose_h_tiled<<<dim3(EE / 32, EE / 32), tb>>>(Wp, p_wp, EE, EE);
    transpose_h_tiled<<<dim3(FF / 32, EE / 32), tb>>>(W1, p_w1, EE, FF);
    transpose_h_tiled<<<dim3(EE / 32, FF / 32), tb>>>(W2, p_w2, FF, EE);

    ln_h_kernel<<<ROWS, 192>>>(x, ln1_g, ln1_b, p_ah);
    tcgemm<3><<<dim3(QKV_N / 128, ROWS / 256), 256, gsmem>>>(
        p_ah, p_wq, p_bqkv, nullptr, nullptr, p_qkvh, QKV_N, EE);
    attn_kernel<<<dim3(SS / 128, BB * HH), 256, asmem>>>(p_qkvh, p_ah);
    tcgemm<2><<<dim3(EE / 128, ROWS / 256), 256, gsmem>>>(
        p_ah, p_wp, bp, x, p_x1, nullptr, EE, EE);
    ln_h_kernel<<<ROWS, 192>>>(p_x1, ln2_g, ln2_b, p_ah);
    tcgemm<1><<<dim3(FF / 128, ROWS / 256), 256, gsmem>>>(
        p_ah, p_w1, b1, nullptr, nullptr, p_fh, FF, EE);
    tcgemm<0><<<dim3(EE / 128, ROWS / 256), 256, gsmem>>>(
        p_fh, p_w2, b2, nullptr, p_f2, nullptr, EE, FF);
    ln_final_kernel<<<ROWS, 192>>>(p_f2, lnf_g, lnf_b, p_x1, out);
}

// round 12
// speedup vs baseline: 11.0994x; 1.0293x over previous
#include <cuda_runtime.h>
#include <cuda_fp16.h>
#include <math.h>
#include <stdint.h>

#define BB 16
#define SS 1024
#define EE 768
#define HH 12
#define DD 64
#define FF 3072
#define ROWS (BB * SS)
#define QKV_N (3 * EE)

// scratch
__device__ __half g_ah[ROWS * EE];
__device__ __half g_fh[ROWS * FF];
__device__ __half g_qkvh[ROWS * QKV_N];
__device__ __half g_wqkvt[QKV_N * EE];
__device__ __half g_wpt[EE * EE];
__device__ __half g_w1t[FF * EE];
__device__ __half g_w2t[EE * FF];
__device__ float g_bqkv[QKV_N];
__device__ float g_x1[ROWS * EE];
__device__ float g_f2[ROWS * EE];

__device__ __forceinline__ uint32_t swz(uint32_t o) { return o ^ ((o >> 3) & 0x70); }
__device__ __forceinline__ uint32_t pack2(float x, float y) {
    __half2 t = __floats2half2_rn(x, y);
    return *(uint32_t*)&t;
}

// ---------------- weight prep (tiled, coalesced) ----------------
__global__ void pack_wqkv_tiled(const float* __restrict__ Wq, const float* __restrict__ Wk,
                                const float* __restrict__ Wv) {
    __shared__ float t[32][33];
    int z = blockIdx.z, sec = z / 12, h = z % 12;
    const float* W = (sec == 0) ? Wq : (sec == 1) ? Wk : Wv;
    float sc = (sec == 0) ? 0.125f : 1.0f;
    int d0 = blockIdx.x * 32, e0 = blockIdx.y * 32;
    int tx = threadIdx.x, ty = threadIdx.y;
#pragma unroll
    for (int j = ty; j < 32; j += 8)
        t[j][tx] = W[((size_t)h * EE + e0 + j) * DD + d0 + tx] * sc;
    __syncthreads();
#pragma unroll
    for (int j = ty; j < 32; j += 8)
        g_wqkvt[(size_t)(sec * 768 + h * 64 + d0 + j) * EE + e0 + tx] =
            __float2half_rn(t[tx][j]);
}

__global__ void pack_bias_kernel(const float* __restrict__ bq, const float* __restrict__ bk,
                                 const float* __restrict__ bv) {
    int idx = blockIdx.x * blockDim.x + threadIdx.x;
    if (idx >= QKV_N) return;
    int sec = idx / 768;
    const float* bsrc = (sec == 0) ? bq : (sec == 1) ? bk : bv;
    float v = bsrc[idx % 768];
    g_bqkv[idx] = (sec == 0) ? v * 0.125f : v;
}

__global__ void transpose_h_tiled(const float* __restrict__ in,
                                  __half* __restrict__ oh, int K, int N) {
    __shared__ float t[32][33];
    int n0 = blockIdx.x * 32, k0 = blockIdx.y * 32;
    int tx = threadIdx.x, ty = threadIdx.y;
#pragma unroll
    for (int j = ty; j < 32; j += 8)
        t[j][tx] = in[(size_t)(k0 + j) * N + n0 + tx];
    __syncthreads();
#pragma unroll
    for (int j = ty; j < 32; j += 8)
        oh[(size_t)(n0 + j) * K + k0 + tx] = __float2half_rn(t[tx][j]);
}

// ---------------- LN: warp-per-row, 8 rows/block, no block barriers ----------
__device__ __forceinline__ float wsum(float v) {
#pragma unroll
    for (int m = 16; m; m >>= 1) v += __shfl_xor_sync(0xffffffffu, v, m);
    return v;
}

__global__ void __launch_bounds__(256) ln_h_kernel(const float* __restrict__ in,
                                                   const float* __restrict__ gam,
                                                   const float* __restrict__ bet,
                                                   __half* __restrict__ oh) {
    int w = threadIdx.x >> 5, lane = threadIdx.x & 31;
    size_t row = (size_t)blockIdx.x * 8 + w;
    const float4* xp = (const float4*)(in + row * EE);
    float4 xv[6];
    float s = 0.f;
#pragma unroll
    for (int i = 0; i < 6; i++) {
        xv[i] = xp[lane + 32 * i];
        s += xv[i].x + xv[i].y + xv[i].z + xv[i].w;
    }
    float mu = wsum(s) * (1.f / EE);
    float v = 0.f;
#pragma unroll
    for (int i = 0; i < 6; i++) {
        xv[i].x -= mu; xv[i].y -= mu; xv[i].z -= mu; xv[i].w -= mu;
        v += xv[i].x * xv[i].x + xv[i].y * xv[i].y + xv[i].z * xv[i].z + xv[i].w * xv[i].w;
    }
    float rstd = rsqrtf(wsum(v) * (1.f / EE) + 1e-5f);
    uint2* op = (uint2*)(oh + row * EE);
#pragma unroll
    for (int i = 0; i < 6; i++) {
        float4 g = ((const float4*)gam)[lane + 32 * i];
        float4 be = ((const float4*)bet)[lane + 32 * i];
        uint2 o;
        o.x = pack2(xv[i].x * rstd * g.x + be.x, xv[i].y * rstd * g.y + be.y);
        o.y = pack2(xv[i].z * rstd * g.z + be.z, xv[i].w * rstd * g.w + be.w);
        op[lane + 32 * i] = o;
    }
}

__global__ void __launch_bounds__(256) ln_final_kernel(const float* __restrict__ in,
                                                       const float* __restrict__ gam,
                                                       const float* __restrict__ bet,
                                                       const float* __restrict__ res,
                                                       float* __restrict__ out) {
    int w = threadIdx.x >> 5, lane = threadIdx.x & 31;
    size_t row = (size_t)blockIdx.x * 8 + w;
    const float4* xp = (const float4*)(in + row * EE);
    float4 xv[6];
    float s = 0.f;
#pragma unroll
    for (int i = 0; i < 6; i++) {
        xv[i] = xp[lane + 32 * i];
        s += xv[i].x + xv[i].y + xv[i].z + xv[i].w;
    }
    float mu = wsum(s) * (1.f / EE);
    float v = 0.f;
#pragma unroll
    for (int i = 0; i < 6; i++) {
        xv[i].x -= mu; xv[i].y -= mu; xv[i].z -= mu; xv[i].w -= mu;
        v += xv[i].x * xv[i].x + xv[i].y * xv[i].y + xv[i].z * xv[i].z + xv[i].w * xv[i].w;
    }
    float rstd = rsqrtf(wsum(v) * (1.f / EE) + 1e-5f);
    float4* op = (float4*)(out + row * EE);
    const float4* rp = (const float4*)(res + row * EE);
#pragma unroll
    for (int i = 0; i < 6; i++) {
        float4 g = ((const float4*)gam)[lane + 32 * i];
        float4 be = ((const float4*)bet)[lane + 32 * i];
        float4 r = rp[lane + 32 * i];
        float4 o;
        o.x = xv[i].x * rstd * g.x + be.x + r.x;
        o.y = xv[i].y * rstd * g.y + be.y + r.y;
        o.z = xv[i].z * rstd * g.z + be.z + r.z;
        o.w = xv[i].w * rstd * g.w + be.w + r.w;
        op[lane + 32 * i] = o;
    }
}

// ---------------- HMMA primitives (fp16) ----------------
__device__ __forceinline__ void cpasync16(uint32_t dst, const void* src) {
    asm volatile("cp.async.cg.shared.global [%0], [%1], 16;" :: "r"(dst), "l"(src));
}
__device__ __forceinline__ void ldm4(uint32_t* r, uint32_t addr) {
    asm volatile("ldmatrix.sync.aligned.m8n8.x4.shared.b16 {%0,%1,%2,%3}, [%4];"
                 : "=r"(r[0]), "=r"(r[1]), "=r"(r[2]), "=r"(r[3]) : "r"(addr));
}
__device__ __forceinline__ void ldm4t(uint32_t* r, uint32_t addr) {
    asm volatile("ldmatrix.sync.aligned.m8n8.x4.trans.shared.b16 {%0,%1,%2,%3}, [%4];"
                 : "=r"(r[0]), "=r"(r[1]), "=r"(r[2]), "=r"(r[3]) : "r"(addr));
}
__device__ __forceinline__ void mma16816(float* d, const uint32_t* a, uint32_t b0, uint32_t b1) {
    asm volatile(
        "mma.sync.aligned.m16n8k16.row.col.f32.f16.f16.f32 "
        "{%0,%1,%2,%3}, {%4,%5,%6,%7}, {%8,%9}, {%0,%1,%2,%3};"
        : "+f"(d[0]), "+f"(d[1]), "+f"(d[2]), "+f"(d[3])
        : "r"(a[0]), "r"(a[1]), "r"(a[2]), "r"(a[3]), "r"(b0), "r"(b1));
}

// ---------------- HMMA GEMM: 256x128 CTA, 64x64 warp, BK=64, 4-stage ----------
// Single __syncthreads per chunk: wait -> sync -> issue(kc+3) -> compute.
// EPI: 0 bias->f32, 1 bias+gelu->fp16, 2 bias+res->f32, 3 bias->fp16
#define STG 49152

template <int EPI>
__global__ void __launch_bounds__(256, 1) tcgemm(const __half* __restrict__ Ah,
                                                 const __half* __restrict__ Bh,
                                                 const float* __restrict__ bias,
                                                 const float* __restrict__ res,
                                                 float* __restrict__ C,
                                                 __half* __restrict__ Ch,
                                                 int N, int K) {
    extern __shared__ char sm[];
    uint32_t sbase = (uint32_t)__cvta_generic_to_shared(sm);
    int tid = threadIdx.x;
    int lane = tid & 31, w = tid >> 5;
    int wm = w >> 1, wn = w & 1;
    int bn = blockIdx.x * 128, bm = blockIdx.y * 256;

    float acc[4][8][4];
#pragma unroll
    for (int i = 0; i < 4; i++)
#pragma unroll
        for (int j = 0; j < 8; j++)
#pragma unroll
            for (int q = 0; q < 4; q++) acc[i][j][q] = 0.f;

    int nk = K >> 6;

#define LOAD_STAGE(kc, buf)                                                          \
    {                                                                                \
        uint32_t sb_ = sbase + (buf) * STG;                                          \
        _Pragma("unroll")                                                            \
        for (int ii = 0; ii < 12; ii++) {                                            \
            int i = tid + ii * 256;                                                  \
            if (i < 2048) {                                                          \
                int r = i >> 3, c = i & 7;                                           \
                cpasync16(sb_ + swz(r * 128 + c * 16),                               \
                          Ah + (size_t)(bm + r) * K + (kc) * 64 + c * 8);            \
            } else {                                                                 \
                int j = i - 2048, r = j >> 3, c = j & 7;                             \
                cpasync16(sb_ + 32768 + swz(r * 128 + c * 16),                       \
                          Bh + (size_t)(bn + r) * K + (kc) * 64 + c * 8);            \
            }                                                                        \
        }                                                                            \
        asm volatile("cp.async.commit_group;" ::: "memory");                         \
    }

    LOAD_STAGE(0, 0);
    LOAD_STAGE(1, 1);
    LOAD_STAGE(2, 2);

    int ra = (lane & 7) + ((lane & 8) ? 8 : 0);
    int ka = (lane & 16) ? 8 : 0;
    int rb_n = (lane & 7) + ((lane & 16) ? 8 : 0);
    int kb_n = (lane & 8) ? 8 : 0;

    int buf = 0;
    for (int kc = 0; kc < nk; kc++) {
        // wait until chunk kc's group is complete (pending = kc..min(kc+2,nk-1))
        if (kc + 2 < nk) {
            asm volatile("cp.async.wait_group 2;" ::: "memory");
        } else if (kc + 1 < nk) {
            asm volatile("cp.async.wait_group 1;" ::: "memory");
        } else {
            asm volatile("cp.async.wait_group 0;" ::: "memory");
        }
        __syncthreads();   // all warps done with chunk kc-1's buffer; kc data visible
        if (kc + 3 < nk) {
            int nb = buf + 3;
            if (nb >= 4) nb -= 4;
            LOAD_STAGE(kc + 3, nb);
        }
        uint32_t sb = sbase + buf * STG;
#pragma unroll
        for (int ks = 0; ks < 4; ks++) {
            uint32_t Af[4][4], Bf[4][4];
#pragma unroll
            for (int mt = 0; mt < 4; mt++) {
                int row = wm * 64 + mt * 16 + ra;
                ldm4(Af[mt], sb + swz(row * 128 + (ks * 16 + ka) * 2));
            }
#pragma unroll
            for (int pr = 0; pr < 4; pr++) {
                int row = wn * 64 + pr * 16 + rb_n;
                ldm4(Bf[pr], sb + 32768 + swz(row * 128 + (ks * 16 + kb_n) * 2));
            }
#pragma unroll
            for (int mt = 0; mt < 4; mt++)
#pragma unroll
                for (int nt = 0; nt < 8; nt++) {
                    int pr = nt >> 1, o = (nt & 1) * 2;
                    mma16816(acc[mt][nt], Af[mt], Bf[pr][o], Bf[pr][o + 1]);
                }
        }
        if (++buf == 4) buf = 0;
    }

    int l4 = lane >> 2, l2 = (lane & 3) * 2;
#pragma unroll
    for (int mt = 0; mt < 4; mt++)
#pragma unroll
        for (int nt = 0; nt < 8; nt++) {
            int col = bn + wn * 64 + nt * 8 + l2;
            float b0 = bias[col], b1 = bias[col + 1];
#pragma unroll
            for (int half = 0; half < 2; half++) {
                size_t row = (size_t)(bm + wm * 64 + mt * 16 + l4 + half * 8);
                float v0 = acc[mt][nt][half * 2 + 0] + b0;
                float v1 = acc[mt][nt][half * 2 + 1] + b1;
                if (EPI == 2) {
                    v0 += res[row * N + col];
                    v1 += res[row * N + col + 1];
                }
                if (EPI == 1) {
                    v0 = 0.5f * v0 * (1.0f + erff(v0 * 0.70710678118654752f));
                    v1 = 0.5f * v1 * (1.0f + erff(v1 * 0.70710678118654752f));
                }
                if (EPI == 1 || EPI == 3) {
                    *(__half2*)&Ch[row * N + col] = __floats2half2_rn(v0, v1);
                } else {
                    *(float2*)&C[row * N + col] = make_float2(v0, v1);
                }
            }
        }
#undef LOAD_STAGE
}

// ---------------- HMMA flash attention: 128-row Q tile, 256 threads ----------
__global__ void __launch_bounds__(256) attn_kernel(const __half* __restrict__ qkvh,
                                                   __half* __restrict__ oh) {
    extern __shared__ char smc[];
    uint32_t sb = (uint32_t)__cvta_generic_to_shared(smc);
    uint32_t Qs = sb;

    int qt = blockIdx.x, bh = blockIdx.y;
    int b = bh / HH, h = bh % HH;
    int tid = threadIdx.x, lane = tid & 31, w = tid >> 5;
    size_t base = (size_t)b * SS * QKV_N;
    int hoff = h * DD;

#pragma unroll
    for (int ii = 0; ii < 4; ii++) {
        int i = tid + ii * 256;
        int r = i >> 3, c = i & 7;
        cpasync16(Qs + swz(r * 128 + c * 16),
                  qkvh + base + (size_t)(qt * 128 + r) * QKV_N + hoff + c * 8);
    }

#define ISSUE_KV(kt, bufo)                                                          \
    {                                                                               \
        _Pragma("unroll")                                                           \
        for (int ii = 0; ii < 4; ii++) {                                            \
            int i = tid + ii * 256;                                                 \
            int ts = i >> 9, wrd = i & 511, r = wrd >> 3, c = wrd & 7;              \
            cpasync16(sb + (bufo) + ts * 8192 + swz(r * 128 + c * 16),              \
                      qkvh + base + (size_t)((kt) * 64 + r) * QKV_N + hoff +        \
                          (ts ? 2 * EE : EE) + c * 8);                              \
        }                                                                           \
        asm volatile("cp.async.commit_group;" ::: "memory");                        \
    }

    ISSUE_KV(0, 16384);

    int ra = (lane & 7) + ((lane & 8) ? 8 : 0);
    int ka = (lane & 16) ? 8 : 0;
    int rbn = (lane & 7) + ((lane & 16) ? 8 : 0);
    int kbn = (lane & 8) ? 8 : 0;
    int vkr = (lane & 7) + ((lane & 8) ? 8 : 0);
    int vnc = (lane & 16) ? 8 : 0;
    int r0 = lane >> 2, c0 = (lane & 3) * 2;

    int qrow = qt * 128 + w * 16;
    int ktmax = 2 * qt + 1;

    float m0 = -1e30f, m1 = -1e30f, l0 = 0.f, l1 = 0.f;
    float o[8][4];
#pragma unroll
    for (int i = 0; i < 8; i++)
#pragma unroll
        for (int j = 0; j < 4; j++) o[i][j] = 0.f;

    for (int kt = 0; kt <= ktmax; kt++) {
        asm volatile("cp.async.wait_group 0;" ::: "memory");
        __syncthreads();   // also proves all warps done with buffer (kt+1)&1 from kt-1
        uint32_t kvo = 16384 + (kt & 1) * 16384;
        if (kt < ktmax) ISSUE_KV(kt + 1, 16384 + ((kt + 1) & 1) * 16384);
        uint32_t Kh = sb + kvo, Vh = sb + kvo + 8192;

        if (kt * 64 <= qrow + 15) {
            float s[8][4];
#pragma unroll
            for (int i = 0; i < 8; i++)
#pragma unroll
                for (int j = 0; j < 4; j++) s[i][j] = 0.f;
#pragma unroll
            for (int kc = 0; kc < 4; kc++) {
                uint32_t qh[4], kh[4][4];
                ldm4(qh, Qs + swz((w * 16 + ra) * 128 + (kc * 16 + ka) * 2));
#pragma unroll
                for (int tg = 0; tg < 4; tg++)
                    ldm4(kh[tg], Kh + swz((tg * 16 + rbn) * 128 + (kc * 16 + kbn) * 2));
#pragma unroll
                for (int nt = 0; nt < 8; nt++) {
                    int pr = nt >> 1, oo = (nt & 1) * 2;
                    mma16816(s[nt], qh, kh[pr][oo], kh[pr][oo + 1]);
                }
            }

            if (kt * 64 + 63 > qrow) {
                int row0 = qrow + r0, row1 = row0 + 8;
#pragma unroll
                for (int nt = 0; nt < 8; nt++) {
                    int c = kt * 64 + nt * 8 + c0;
                    if (c > row0) s[nt][0] = -1e30f;
                    if (c + 1 > row0) s[nt][1] = -1e30f;
                    if (c > row1) s[nt][2] = -1e30f;
                    if (c + 1 > row1) s[nt][3] = -1e30f;
                }
            }

            float mt0 = -1e30f, mt1 = -1e30f;
#pragma unroll
            for (int nt = 0; nt < 8; nt++) {
                mt0 = fmaxf(mt0, fmaxf(s[nt][0], s[nt][1]));
                mt1 = fmaxf(mt1, fmaxf(s[nt][2], s[nt][3]));
            }
#pragma unroll
            for (int off = 1; off <= 2; off <<= 1) {
                mt0 = fmaxf(mt0, __shfl_xor_sync(0xffffffffu, mt0, off));
                mt1 = fmaxf(mt1, __shfl_xor_sync(0xffffffffu, mt1, off));
            }
            float mn0 = fmaxf(m0, mt0), mn1 = fmaxf(m1, mt1);
            float sc0 = __expf(m0 - mn0), sc1 = __expf(m1 - mn1);
            float rs0 = 0.f, rs1 = 0.f;
#pragma unroll
            for (int nt = 0; nt < 8; nt++) {
                s[nt][0] = __expf(s[nt][0] - mn0);
                s[nt][1] = __expf(s[nt][1] - mn0);
                s[nt][2] = __expf(s[nt][2] - mn1);
                s[nt][3] = __expf(s[nt][3] - mn1);
                rs0 += s[nt][0] + s[nt][1];
                rs1 += s[nt][2] + s[nt][3];
            }
#pragma unroll
            for (int off = 1; off <= 2; off <<= 1) {
                rs0 += __shfl_xor_sync(0xffffffffu, rs0, off);
                rs1 += __shfl_xor_sync(0xffffffffu, rs1, off);
            }
            l0 = l0 * sc0 + rs0;
            l1 = l1 * sc1 + rs1;
            m0 = mn0;
            m1 = mn1;
#pragma unroll
            for (int i = 0; i < 8; i++) {
                o[i][0] *= sc0; o[i][1] *= sc0;
                o[i][2] *= sc1; o[i][3] *= sc1;
            }

#pragma unroll
            for (int kc = 0; kc < 4; kc++) {
                uint32_t aph[4];
                aph[0] = pack2(s[2 * kc][0], s[2 * kc][1]);
                aph[1] = pack2(s[2 * kc][2], s[2 * kc][3]);
                aph[2] = pack2(s[2 * kc + 1][0], s[2 * kc + 1][1]);
                aph[3] = pack2(s[2 * kc + 1][2], s[2 * kc + 1][3]);
                uint32_t vh[4][4];
#pragma unroll
                for (int dg = 0; dg < 4; dg++)
                    ldm4t(vh[dg], Vh + swz((kc * 16 + vkr) * 128 + (dg * 16 + vnc) * 2));
#pragma unroll
                for (int dt = 0; dt < 8; dt++) {
                    int pr = dt >> 1, oo = (dt & 1) * 2;
                    mma16816(o[dt], aph, vh[pr][oo], vh[pr][oo + 1]);
                }
            }
        }
    }

    float inv0 = 1.f / l0, inv1 = 1.f / l1;
    size_t row0 = (size_t)b * SS + qrow + r0;
    size_t row1 = row0 + 8;
#pragma unroll
    for (int dt = 0; dt < 8; dt++) {
        int d = hoff + dt * 8 + c0;
        *(__half2*)&oh[row0 * EE + d] = __floats2half2_rn(o[dt][0] * inv0, o[dt][1] * inv0);
        *(__half2*)&oh[row1 * EE + d] = __floats2half2_rn(o[dt][2] * inv1, o[dt][3] * inv1);
    }
#undef ISSUE_KV
}

// ---------------- launch ----------------
extern "C" void kernel_launch(void* const* d_in, const int* in_sizes, int n_in,
                              void* d_out, int out_size) {
    const float* x = (const float*)d_in[0];
    const float* Wq = (const float*)d_in[1];
    const float* bq = (const float*)d_in[2];
    const float* Wk = (const float*)d_in[3];
    const float* bk = (const float*)d_in[4];
    const float* Wv = (const float*)d_in[5];
    const float* bv = (const float*)d_in[6];
    const float* Wp = (const float*)d_in[7];
    const float* bp = (const float*)d_in[8];
    const float* ln1_g = (const float*)d_in[9];
    const float* ln1_b = (const float*)d_in[10];
    const float* ln2_g = (const float*)d_in[11];
    const float* ln2_b = (const float*)d_in[12];
    const float* W1 = (const float*)d_in[13];
    const float* b1 = (const float*)d_in[14];
    const float* W2 = (const float*)d_in[15];
    const float* b2 = (const float*)d_in[16];
    const float* lnf_g = (const float*)d_in[17];
    const float* lnf_b = (const float*)d_in[18];
    float* out = (float*)d_out;

    __half *p_ah, *p_fh, *p_qkvh, *p_wq, *p_wp, *p_w1, *p_w2;
    float *p_bqkv, *p_x1, *p_f2;
    cudaGetSymbolAddress((void**)&p_ah, g_ah);
    cudaGetSymbolAddress((void**)&p_fh, g_fh);
    cudaGetSymbolAddress((void**)&p_qkvh, g_qkvh);
    cudaGetSymbolAddress((void**)&p_wq, g_wqkvt);
    cudaGetSymbolAddress((void**)&p_wp, g_wpt);
    cudaGetSymbolAddress((void**)&p_w1, g_w1t);
    cudaGetSymbolAddress((void**)&p_w2, g_w2t);
    cudaGetSymbolAddress((void**)&p_bqkv, g_bqkv);
    cudaGetSymbolAddress((void**)&p_x1, g_x1);
    cudaGetSymbolAddress((void**)&p_f2, g_f2);

    int gsmem = 4 * STG;  // 196608
    cudaFuncSetAttribute(tcgemm<0>, cudaFuncAttributeMaxDynamicSharedMemorySize, gsmem);
    cudaFuncSetAttribute(tcgemm<1>, cudaFuncAttributeMaxDynamicSharedMemorySize, gsmem);
    cudaFuncSetAttribute(tcgemm<2>, cudaFuncAttributeMaxDynamicSharedMemorySize, gsmem);
    cudaFuncSetAttribute(tcgemm<3>, cudaFuncAttributeMaxDynamicSharedMemorySize, gsmem);
    int asmem = 49152;
    cudaFuncSetAttribute(attn_kernel, cudaFuncAttributeMaxDynamicSharedMemorySize, asmem);

    dim3 tb(32, 8);
    pack_wqkv_tiled<<<dim3(2, 24, 36), tb>>>(Wq, Wk, Wv);
    pack_bias_kernel<<<9, 256>>>(bq, bk, bv);
    transpose_h_tiled<<<dim3(EE / 32, EE / 32), tb>>>(Wp, p_wp, EE, EE);
    transpose_h_tiled<<<dim3(FF / 32, EE / 32), tb>>>(W1, p_w1, EE, FF);
    transpose_h_tiled<<<dim3(EE / 32, FF / 32), tb>>>(W2, p_w2, FF, EE);

    ln_h_kernel<<<ROWS / 8, 256>>>(x, ln1_g, ln1_b, p_ah);
    tcgemm<3><<<dim3(QKV_N / 128, ROWS / 256), 256, gsmem>>>(
        p_ah, p_wq, p_bqkv, nullptr, nullptr, p_qkvh, QKV_N, EE);
    attn_kernel<<<dim3(SS / 128, BB * HH), 256, asmem>>>(p_qkvh, p_ah);
    tcgemm<2><<<dim3(EE / 128, ROWS / 256), 256, gsmem>>>(
        p_ah, p_wp, bp, x, p_x1, nullptr, EE, EE);
    ln_h_kernel<<<ROWS / 8, 256>>>(p_x1, ln2_g, ln2_b, p_ah);
    tcgemm<1><<<dim3(FF / 128, ROWS / 256), 256, gsmem>>>(
        p_ah, p_w1, b1, nullptr, nullptr, p_fh, FF, EE);
    tcgemm<0><<<dim3(EE / 128, ROWS / 256), 256, gsmem>>>(
        p_fh, p_w2, b2, nullptr, p_f2, nullptr, EE, FF);
    ln_final_kernel<<<ROWS / 8, 256>>>(p_f2, lnf_g, lnf_b, p_x1, out);
}

// round 13
// speedup vs baseline: 11.9021x; 1.0723x over previous
#include <cuda_runtime.h>
#include <cuda_fp16.h>
#include <math.h>
#include <stdint.h>

#define BB 16
#define SS 1024
#define EE 768
#define HH 12
#define DD 64
#define FF 3072
#define ROWS (BB * SS)
#define QKV_N (3 * EE)

// scratch
__device__ __half g_ah[ROWS * EE];
__device__ __half g_fh[ROWS * FF];
__device__ __half g_qkvh[ROWS * QKV_N];
__device__ __half g_wqkvt[QKV_N * EE];
__device__ __half g_wpt[EE * EE];
__device__ __half g_w1t[FF * EE];
__device__ __half g_w2t[EE * FF];
__device__ float g_bqkv[QKV_N];
__device__ float g_x1[ROWS * EE];
__device__ float g_f2[ROWS * EE];

__device__ __forceinline__ uint32_t swz(uint32_t o) { return o ^ ((o >> 3) & 0x70); }
__device__ __forceinline__ uint32_t pack2(float x, float y) {
    __half2 t = __floats2half2_rn(x, y);
    return *(uint32_t*)&t;
}

// ---------------- weight prep (tiled, coalesced) ----------------
__global__ void pack_wqkv_tiled(const float* __restrict__ Wq, const float* __restrict__ Wk,
                                const float* __restrict__ Wv) {
    __shared__ float t[32][33];
    int z = blockIdx.z, sec = z / 12, h = z % 12;
    const float* W = (sec == 0) ? Wq : (sec == 1) ? Wk : Wv;
    float sc = (sec == 0) ? 0.125f : 1.0f;
    int d0 = blockIdx.x * 32, e0 = blockIdx.y * 32;
    int tx = threadIdx.x, ty = threadIdx.y;
#pragma unroll
    for (int j = ty; j < 32; j += 8)
        t[j][tx] = W[((size_t)h * EE + e0 + j) * DD + d0 + tx] * sc;
    __syncthreads();
#pragma unroll
    for (int j = ty; j < 32; j += 8)
        g_wqkvt[(size_t)(sec * 768 + h * 64 + d0 + j) * EE + e0 + tx] =
            __float2half_rn(t[tx][j]);
}

__global__ void pack_bias_kernel(const float* __restrict__ bq, const float* __restrict__ bk,
                                 const float* __restrict__ bv) {
    int idx = blockIdx.x * blockDim.x + threadIdx.x;
    if (idx >= QKV_N) return;
    int sec = idx / 768;
    const float* bsrc = (sec == 0) ? bq : (sec == 1) ? bk : bv;
    float v = bsrc[idx % 768];
    g_bqkv[idx] = (sec == 0) ? v * 0.125f : v;
}

__global__ void transpose_h_tiled(const float* __restrict__ in,
                                  __half* __restrict__ oh, int K, int N) {
    __shared__ float t[32][33];
    int n0 = blockIdx.x * 32, k0 = blockIdx.y * 32;
    int tx = threadIdx.x, ty = threadIdx.y;
#pragma unroll
    for (int j = ty; j < 32; j += 8)
        t[j][tx] = in[(size_t)(k0 + j) * N + n0 + tx];
    __syncthreads();
#pragma unroll
    for (int j = ty; j < 32; j += 8)
        oh[(size_t)(n0 + j) * K + k0 + tx] = __float2half_rn(t[tx][j]);
}

// ---------------- LN: warp-per-row, 8 rows/block ----------------
__device__ __forceinline__ float wsum(float v) {
#pragma unroll
    for (int m = 16; m; m >>= 1) v += __shfl_xor_sync(0xffffffffu, v, m);
    return v;
}

__global__ void __launch_bounds__(256) ln_h_kernel(const float* __restrict__ in,
                                                   const float* __restrict__ gam,
                                                   const float* __restrict__ bet,
                                                   __half* __restrict__ oh) {
    int w = threadIdx.x >> 5, lane = threadIdx.x & 31;
    size_t row = (size_t)blockIdx.x * 8 + w;
    const float4* xp = (const float4*)(in + row * EE);
    float4 xv[6];
    float s = 0.f;
#pragma unroll
    for (int i = 0; i < 6; i++) {
        xv[i] = xp[lane + 32 * i];
        s += xv[i].x + xv[i].y + xv[i].z + xv[i].w;
    }
    float mu = wsum(s) * (1.f / EE);
    float v = 0.f;
#pragma unroll
    for (int i = 0; i < 6; i++) {
        xv[i].x -= mu; xv[i].y -= mu; xv[i].z -= mu; xv[i].w -= mu;
        v += xv[i].x * xv[i].x + xv[i].y * xv[i].y + xv[i].z * xv[i].z + xv[i].w * xv[i].w;
    }
    float rstd = rsqrtf(wsum(v) * (1.f / EE) + 1e-5f);
    uint2* op = (uint2*)(oh + row * EE);
#pragma unroll
    for (int i = 0; i < 6; i++) {
        float4 g = ((const float4*)gam)[lane + 32 * i];
        float4 be = ((const float4*)bet)[lane + 32 * i];
        uint2 o;
        o.x = pack2(xv[i].x * rstd * g.x + be.x, xv[i].y * rstd * g.y + be.y);
        o.y = pack2(xv[i].z * rstd * g.z + be.z, xv[i].w * rstd * g.w + be.w);
        op[lane + 32 * i] = o;
    }
}

__global__ void __launch_bounds__(256) ln_final_kernel(const float* __restrict__ in,
                                                       const float* __restrict__ gam,
                                                       const float* __restrict__ bet,
                                                       const float* __restrict__ res,
                                                       float* __restrict__ out) {
    int w = threadIdx.x >> 5, lane = threadIdx.x & 31;
    size_t row = (size_t)blockIdx.x * 8 + w;
    const float4* xp = (const float4*)(in + row * EE);
    float4 xv[6];
    float s = 0.f;
#pragma unroll
    for (int i = 0; i < 6; i++) {
        xv[i] = xp[lane + 32 * i];
        s += xv[i].x + xv[i].y + xv[i].z + xv[i].w;
    }
    float mu = wsum(s) * (1.f / EE);
    float v = 0.f;
#pragma unroll
    for (int i = 0; i < 6; i++) {
        xv[i].x -= mu; xv[i].y -= mu; xv[i].z -= mu; xv[i].w -= mu;
        v += xv[i].x * xv[i].x + xv[i].y * xv[i].y + xv[i].z * xv[i].z + xv[i].w * xv[i].w;
    }
    float rstd = rsqrtf(wsum(v) * (1.f / EE) + 1e-5f);
    float4* op = (float4*)(out + row * EE);
    const float4* rp = (const float4*)(res + row * EE);
#pragma unroll
    for (int i = 0; i < 6; i++) {
        float4 g = ((const float4*)gam)[lane + 32 * i];
        float4 be = ((const float4*)bet)[lane + 32 * i];
        float4 r = rp[lane + 32 * i];
        float4 o;
        o.x = xv[i].x * rstd * g.x + be.x + r.x;
        o.y = xv[i].y * rstd * g.y + be.y + r.y;
        o.z = xv[i].z * rstd * g.z + be.z + r.z;
        o.w = xv[i].w * rstd * g.w + be.w + r.w;
        op[lane + 32 * i] = o;
    }
}

// ---------------- HMMA primitives (fp16) ----------------
__device__ __forceinline__ void cpasync16(uint32_t dst, const void* src) {
    asm volatile("cp.async.cg.shared.global [%0], [%1], 16;" :: "r"(dst), "l"(src));
}
__device__ __forceinline__ void ldm4(uint32_t* r, uint32_t addr) {
    asm volatile("ldmatrix.sync.aligned.m8n8.x4.shared.b16 {%0,%1,%2,%3}, [%4];"
                 : "=r"(r[0]), "=r"(r[1]), "=r"(r[2]), "=r"(r[3]) : "r"(addr));
}
__device__ __forceinline__ void ldm4t(uint32_t* r, uint32_t addr) {
    asm volatile("ldmatrix.sync.aligned.m8n8.x4.trans.shared.b16 {%0,%1,%2,%3}, [%4];"
                 : "=r"(r[0]), "=r"(r[1]), "=r"(r[2]), "=r"(r[3]) : "r"(addr));
}
__device__ __forceinline__ void mma16816(float* d, const uint32_t* a, uint32_t b0, uint32_t b1) {
    asm volatile(
        "mma.sync.aligned.m16n8k16.row.col.f32.f16.f16.f32 "
        "{%0,%1,%2,%3}, {%4,%5,%6,%7}, {%8,%9}, {%0,%1,%2,%3};"
        : "+f"(d[0]), "+f"(d[1]), "+f"(d[2]), "+f"(d[3])
        : "r"(a[0]), "r"(a[1]), "r"(a[2]), "r"(a[3]), "r"(b0), "r"(b1));
}

// ---------------- HMMA GEMM: 128x128 CTA, 128 thr, 64x64 warp, 3-stage ------
// 2 CTAs/SM. EPI: 0 bias->f32, 1 bias+gelu->fp16, 2 bias+res->f32, 3 bias->fp16
#define STG 32768   // A 16K | B 16K

template <int EPI>
__global__ void __launch_bounds__(128, 2) tcgemm(const __half* __restrict__ Ah,
                                                 const __half* __restrict__ Bh,
                                                 const float* __restrict__ bias,
                                                 const float* __restrict__ res,
                                                 float* __restrict__ C,
                                                 __half* __restrict__ Ch,
                                                 int N, int K) {
    extern __shared__ char sm[];
    uint32_t sbase = (uint32_t)__cvta_generic_to_shared(sm);
    int tid = threadIdx.x;
    int lane = tid & 31, w = tid >> 5;
    int wm = w >> 1, wn = w & 1;                 // 2x2 warp grid, 64x64 tiles
    int bn = blockIdx.x * 128, bm = blockIdx.y * 128;

    float acc[4][8][4];
#pragma unroll
    for (int i = 0; i < 4; i++)
#pragma unroll
        for (int j = 0; j < 8; j++)
#pragma unroll
            for (int q = 0; q < 4; q++) acc[i][j][q] = 0.f;

    int nk = K >> 6;

#define LOAD_STAGE(kc, buf)                                                        \
    {                                                                              \
        uint32_t sb_ = sbase + (buf) * STG;                                        \
        _Pragma("unroll")                                                          \
        for (int ii = 0; ii < 16; ii++) {                                          \
            int i = tid + ii * 128;                                                \
            int t = i >> 10, wrd = i & 1023, r = wrd >> 3, c = wrd & 7;            \
            int rb = t ? bn : bm;                                                  \
            const __half* sp = (t ? Bh : Ah) + (size_t)(rb + r) * K + (kc) * 64 + c * 8; \
            cpasync16(sb_ + t * 16384 + swz(r * 128 + c * 16), sp);                \
        }                                                                          \
        asm volatile("cp.async.commit_group;" ::: "memory");                       \
    }

    LOAD_STAGE(0, 0);
    LOAD_STAGE(1, 1);

    int ra = (lane & 7) + ((lane & 8) ? 8 : 0);
    int ka = (lane & 16) ? 8 : 0;
    int rb_n = (lane & 7) + ((lane & 16) ? 8 : 0);
    int kb_n = (lane & 8) ? 8 : 0;

    int buf = 0;
    for (int kc = 0; kc < nk; kc++) {
        if (kc + 1 < nk) {
            asm volatile("cp.async.wait_group 1;" ::: "memory");
        } else {
            asm volatile("cp.async.wait_group 0;" ::: "memory");
        }
        __syncthreads();   // chunk kc visible; all warps done with chunk kc-1's buffer
        if (kc + 2 < nk) {
            int nb = buf + 2;
            if (nb >= 3) nb -= 3;
            LOAD_STAGE(kc + 2, nb);
        }
        uint32_t sb = sbase + buf * STG;
#pragma unroll
        for (int ks = 0; ks < 4; ks++) {
            uint32_t Af[4][4], Bf[4][4];
#pragma unroll
            for (int mt = 0; mt < 4; mt++) {
                int row = wm * 64 + mt * 16 + ra;
                ldm4(Af[mt], sb + swz(row * 128 + (ks * 16 + ka) * 2));
            }
#pragma unroll
            for (int pr = 0; pr < 4; pr++) {
                int row = wn * 64 + pr * 16 + rb_n;
                ldm4(Bf[pr], sb + 16384 + swz(row * 128 + (ks * 16 + kb_n) * 2));
            }
#pragma unroll
            for (int mt = 0; mt < 4; mt++)
#pragma unroll
                for (int nt = 0; nt < 8; nt++) {
                    int pr = nt >> 1, o = (nt & 1) * 2;
                    mma16816(acc[mt][nt], Af[mt], Bf[pr][o], Bf[pr][o + 1]);
                }
        }
        if (++buf == 3) buf = 0;
    }

    int l4 = lane >> 2, l2 = (lane & 3) * 2;
#pragma unroll
    for (int mt = 0; mt < 4; mt++)
#pragma unroll
        for (int nt = 0; nt < 8; nt++) {
            int col = bn + wn * 64 + nt * 8 + l2;
            float b0 = bias[col], b1 = bias[col + 1];
#pragma unroll
            for (int half = 0; half < 2; half++) {
                size_t row = (size_t)(bm + wm * 64 + mt * 16 + l4 + half * 8);
                float v0 = acc[mt][nt][half * 2 + 0] + b0;
                float v1 = acc[mt][nt][half * 2 + 1] + b1;
                if (EPI == 2) {
                    v0 += res[row * N + col];
                    v1 += res[row * N + col + 1];
                }
                if (EPI == 1) {
                    v0 = 0.5f * v0 * (1.0f + erff(v0 * 0.70710678118654752f));
                    v1 = 0.5f * v1 * (1.0f + erff(v1 * 0.70710678118654752f));
                }
                if (EPI == 1 || EPI == 3) {
                    *(__half2*)&Ch[row * N + col] = __floats2half2_rn(v0, v1);
                } else {
                    *(float2*)&C[row * N + col] = make_float2(v0, v1);
                }
            }
        }
#undef LOAD_STAGE
}

// ---------------- HMMA flash attention: 128-row Q tile, 256 threads ----------
__global__ void __launch_bounds__(256, 2) attn_kernel(const __half* __restrict__ qkvh,
                                                      __half* __restrict__ oh) {
    extern __shared__ char smc[];
    uint32_t sb = (uint32_t)__cvta_generic_to_shared(smc);
    uint32_t Qs = sb;

    int qt = blockIdx.x, bh = blockIdx.y;
    int b = bh / HH, h = bh % HH;
    int tid = threadIdx.x, lane = tid & 31, w = tid >> 5;
    size_t base = (size_t)b * SS * QKV_N;
    int hoff = h * DD;

#pragma unroll
    for (int ii = 0; ii < 4; ii++) {
        int i = tid + ii * 256;
        int r = i >> 3, c = i & 7;
        cpasync16(Qs + swz(r * 128 + c * 16),
                  qkvh + base + (size_t)(qt * 128 + r) * QKV_N + hoff + c * 8);
    }

#define ISSUE_KV(kt, bufo)                                                          \
    {                                                                               \
        _Pragma("unroll")                                                           \
        for (int ii = 0; ii < 4; ii++) {                                            \
            int i = tid + ii * 256;                                                 \
            int ts = i >> 9, wrd = i & 511, r = wrd >> 3, c = wrd & 7;              \
            cpasync16(sb + (bufo) + ts * 8192 + swz(r * 128 + c * 16),              \
                      qkvh + base + (size_t)((kt) * 64 + r) * QKV_N + hoff +        \
                          (ts ? 2 * EE : EE) + c * 8);                              \
        }                                                                           \
        asm volatile("cp.async.commit_group;" ::: "memory");                        \
    }

    ISSUE_KV(0, 16384);

    int ra = (lane & 7) + ((lane & 8) ? 8 : 0);
    int ka = (lane & 16) ? 8 : 0;
    int rbn = (lane & 7) + ((lane & 16) ? 8 : 0);
    int kbn = (lane & 8) ? 8 : 0;
    int vkr = (lane & 7) + ((lane & 8) ? 8 : 0);
    int vnc = (lane & 16) ? 8 : 0;
    int r0 = lane >> 2, c0 = (lane & 3) * 2;

    int qrow = qt * 128 + w * 16;
    int ktmax = 2 * qt + 1;

    float m0 = -1e30f, m1 = -1e30f, l0 = 0.f, l1 = 0.f;
    float o[8][4];
#pragma unroll
    for (int i = 0; i < 8; i++)
#pragma unroll
        for (int j = 0; j < 4; j++) o[i][j] = 0.f;

    for (int kt = 0; kt <= ktmax; kt++) {
        asm volatile("cp.async.wait_group 0;" ::: "memory");
        __syncthreads();
        uint32_t kvo = 16384 + (kt & 1) * 16384;
        if (kt < ktmax) ISSUE_KV(kt + 1, 16384 + ((kt + 1) & 1) * 16384);
        uint32_t Kh = sb + kvo, Vh = sb + kvo + 8192;

        if (kt * 64 <= qrow + 15) {
            float s[8][4];
#pragma unroll
            for (int i = 0; i < 8; i++)
#pragma unroll
                for (int j = 0; j < 4; j++) s[i][j] = 0.f;
#pragma unroll
            for (int kc = 0; kc < 4; kc++) {
                uint32_t qh[4], kh[4][4];
                ldm4(qh, Qs + swz((w * 16 + ra) * 128 + (kc * 16 + ka) * 2));
#pragma unroll
                for (int tg = 0; tg < 4; tg++)
                    ldm4(kh[tg], Kh + swz((tg * 16 + rbn) * 128 + (kc * 16 + kbn) * 2));
#pragma unroll
                for (int nt = 0; nt < 8; nt++) {
                    int pr = nt >> 1, oo = (nt & 1) * 2;
                    mma16816(s[nt], qh, kh[pr][oo], kh[pr][oo + 1]);
                }
            }

            if (kt * 64 + 63 > qrow) {
                int row0 = qrow + r0, row1 = row0 + 8;
#pragma unroll
                for (int nt = 0; nt < 8; nt++) {
                    int c = kt * 64 + nt * 8 + c0;
                    if (c > row0) s[nt][0] = -1e30f;
                    if (c + 1 > row0) s[nt][1] = -1e30f;
                    if (c > row1) s[nt][2] = -1e30f;
                    if (c + 1 > row1) s[nt][3] = -1e30f;
                }
            }

            float mt0 = -1e30f, mt1 = -1e30f;
#pragma unroll
            for (int nt = 0; nt < 8; nt++) {
                mt0 = fmaxf(mt0, fmaxf(s[nt][0], s[nt][1]));
                mt1 = fmaxf(mt1, fmaxf(s[nt][2], s[nt][3]));
            }
#pragma unroll
            for (int off = 1; off <= 2; off <<= 1) {
                mt0 = fmaxf(mt0, __shfl_xor_sync(0xffffffffu, mt0, off));
                mt1 = fmaxf(mt1, __shfl_xor_sync(0xffffffffu, mt1, off));
            }
            float mn0 = fmaxf(m0, mt0), mn1 = fmaxf(m1, mt1);
            float sc0 = __expf(m0 - mn0), sc1 = __expf(m1 - mn1);
            float rs0 = 0.f, rs1 = 0.f;
#pragma unroll
            for (int nt = 0; nt < 8; nt++) {
                s[nt][0] = __expf(s[nt][0] - mn0);
                s[nt][1] = __expf(s[nt][1] - mn0);
                s[nt][2] = __expf(s[nt][2] - mn1);
                s[nt][3] = __expf(s[nt][3] - mn1);
                rs0 += s[nt][0] + s[nt][1];
                rs1 += s[nt][2] + s[nt][3];
            }
#pragma unroll
            for (int off = 1; off <= 2; off <<= 1) {
                rs0 += __shfl_xor_sync(0xffffffffu, rs0, off);
                rs1 += __shfl_xor_sync(0xffffffffu, rs1, off);
            }
            l0 = l0 * sc0 + rs0;
            l1 = l1 * sc1 + rs1;
            m0 = mn0;
            m1 = mn1;
#pragma unroll
            for (int i = 0; i < 8; i++) {
                o[i][0] *= sc0; o[i][1] *= sc0;
                o[i][2] *= sc1; o[i][3] *= sc1;
            }

#pragma unroll
            for (int kc = 0; kc < 4; kc++) {
                uint32_t aph[4];
                aph[0] = pack2(s[2 * kc][0], s[2 * kc][1]);
                aph[1] = pack2(s[2 * kc][2], s[2 * kc][3]);
                aph[2] = pack2(s[2 * kc + 1][0], s[2 * kc + 1][1]);
                aph[3] = pack2(s[2 * kc + 1][2], s[2 * kc + 1][3]);
                uint32_t vh[4][4];
#pragma unroll
                for (int dg = 0; dg < 4; dg++)
                    ldm4t(vh[dg], Vh + swz((kc * 16 + vkr) * 128 + (dg * 16 + vnc) * 2));
#pragma unroll
                for (int dt = 0; dt < 8; dt++) {
                    int pr = dt >> 1, oo = (dt & 1) * 2;
                    mma16816(o[dt], aph, vh[pr][oo], vh[pr][oo + 1]);
                }
            }
        }
    }

    float inv0 = 1.f / l0, inv1 = 1.f / l1;
    size_t row0 = (size_t)b * SS + qrow + r0;
    size_t row1 = row0 + 8;
#pragma unroll
    for (int dt = 0; dt < 8; dt++) {
        int d = hoff + dt * 8 + c0;
        *(__half2*)&oh[row0 * EE + d] = __floats2half2_rn(o[dt][0] * inv0, o[dt][1] * inv0);
        *(__half2*)&oh[row1 * EE + d] = __floats2half2_rn(o[dt][2] * inv1, o[dt][3] * inv1);
    }
#undef ISSUE_KV
}

// ---------------- launch ----------------
extern "C" void kernel_launch(void* const* d_in, const int* in_sizes, int n_in,
                              void* d_out, int out_size) {
    const float* x = (const float*)d_in[0];
    const float* Wq = (const float*)d_in[1];
    const float* bq = (const float*)d_in[2];
    const float* Wk = (const float*)d_in[3];
    const float* bk = (const float*)d_in[4];
    const float* Wv = (const float*)d_in[5];
    const float* bv = (const float*)d_in[6];
    const float* Wp = (const float*)d_in[7];
    const float* bp = (const float*)d_in[8];
    const float* ln1_g = (const float*)d_in[9];
    const float* ln1_b = (const float*)d_in[10];
    const float* ln2_g = (const float*)d_in[11];
    const float* ln2_b = (const float*)d_in[12];
    const float* W1 = (const float*)d_in[13];
    const float* b1 = (const float*)d_in[14];
    const float* W2 = (const float*)d_in[15];
    const float* b2 = (const float*)d_in[16];
    const float* lnf_g = (const float*)d_in[17];
    const float* lnf_b = (const float*)d_in[18];
    float* out = (float*)d_out;

    __half *p_ah, *p_fh, *p_qkvh, *p_wq, *p_wp, *p_w1, *p_w2;
    float *p_bqkv, *p_x1, *p_f2;
    cudaGetSymbolAddress((void**)&p_ah, g_ah);
    cudaGetSymbolAddress((void**)&p_fh, g_fh);
    cudaGetSymbolAddress((void**)&p_qkvh, g_qkvh);
    cudaGetSymbolAddress((void**)&p_wq, g_wqkvt);
    cudaGetSymbolAddress((void**)&p_wp, g_wpt);
    cudaGetSymbolAddress((void**)&p_w1, g_w1t);
    cudaGetSymbolAddress((void**)&p_w2, g_w2t);
    cudaGetSymbolAddress((void**)&p_bqkv, g_bqkv);
    cudaGetSymbolAddress((void**)&p_x1, g_x1);
    cudaGetSymbolAddress((void**)&p_f2, g_f2);

    int gsmem = 3 * STG;  // 98304
    cudaFuncSetAttribute(tcgemm<0>, cudaFuncAttributeMaxDynamicSharedMemorySize, gsmem);
    cudaFuncSetAttribute(tcgemm<1>, cudaFuncAttributeMaxDynamicSharedMemorySize, gsmem);
    cudaFuncSetAttribute(tcgemm<2>, cudaFuncAttributeMaxDynamicSharedMemorySize, gsmem);
    cudaFuncSetAttribute(tcgemm<3>, cudaFuncAttributeMaxDynamicSharedMemorySize, gsmem);
    int asmem = 49152;
    cudaFuncSetAttribute(attn_kernel, cudaFuncAttributeMaxDynamicSharedMemorySize, asmem);

    dim3 tb(32, 8);
    pack_wqkv_tiled<<<dim3(2, 24, 36), tb>>>(Wq, Wk, Wv);
    pack_bias_kernel<<<9, 256>>>(bq, bk, bv);
    transpose_h_tiled<<<dim3(EE / 32, EE / 32), tb>>>(Wp, p_wp, EE, EE);
    transpose_h_tiled<<<dim3(FF / 32, EE / 32), tb>>>(W1, p_w1, EE, FF);
    transpose_h_tiled<<<dim3(EE / 32, FF / 32), tb>>>(W2, p_w2, FF, EE);

    ln_h_kernel<<<ROWS / 8, 256>>>(x, ln1_g, ln1_b, p_ah);
    tcgemm<3><<<dim3(QKV_N / 128, ROWS / 128), 128, gsmem>>>(
        p_ah, p_wq, p_bqkv, nullptr, nullptr, p_qkvh, QKV_N, EE);
    attn_kernel<<<dim3(SS / 128, BB * HH), 256, asmem>>>(p_qkvh, p_ah);
    tcgemm<2><<<dim3(EE / 128, ROWS / 128), 128, gsmem>>>(
        p_ah, p_wp, bp, x, p_x1, nullptr, EE, EE);
    ln_h_kernel<<<ROWS / 8, 256>>>(p_x1, ln2_g, ln2_b, p_ah);
    tcgemm<1><<<dim3(FF / 128, ROWS / 128), 128, gsmem>>>(
        p_ah, p_w1, b1, nullptr, nullptr, p_fh, FF, EE);
    tcgemm<0><<<dim3(EE / 128, ROWS / 128), 128, gsmem>>>(
        p_fh, p_w2, b2, nullptr, p_f2, nullptr, EE, FF);
    ln_final_kernel<<<ROWS / 8, 256>>>(p_f2, lnf_g, lnf_b, p_x1, out);
}

// round 14
// speedup vs baseline: 11.9815x; 1.0067x over previous
#include <cuda_runtime.h>
#include <cuda_fp16.h>
#include <math.h>
#include <stdint.h>

#define BB 16
#define SS 1024
#define EE 768
#define HH 12
#define DD 64
#define FF 3072
#define ROWS (BB * SS)
#define QKV_N (3 * EE)

// scratch
__device__ __half g_ah[ROWS * EE];
__device__ __half g_fh[ROWS * FF];
__device__ __half g_qkvh[ROWS * QKV_N];
__device__ __half g_wqkvt[QKV_N * EE];
__device__ __half g_wpt[EE * EE];
__device__ __half g_w1t[FF * EE];
__device__ __half g_w2t[EE * FF];
__device__ float g_bqkv[QKV_N];
__device__ float g_x1[ROWS * EE];
__device__ float g_f2[ROWS * EE];

__device__ __forceinline__ uint32_t swz(uint32_t o) { return o ^ ((o >> 3) & 0x70); }
__device__ __forceinline__ uint32_t pack2(float x, float y) {
    __half2 t = __floats2half2_rn(x, y);
    return *(uint32_t*)&t;
}

// ---------------- weight prep (tiled, coalesced) ----------------
__global__ void pack_wqkv_tiled(const float* __restrict__ Wq, const float* __restrict__ Wk,
                                const float* __restrict__ Wv) {
    __shared__ float t[32][33];
    int z = blockIdx.z, sec = z / 12, h = z % 12;
    const float* W = (sec == 0) ? Wq : (sec == 1) ? Wk : Wv;
    float sc = (sec == 0) ? 0.125f : 1.0f;
    int d0 = blockIdx.x * 32, e0 = blockIdx.y * 32;
    int tx = threadIdx.x, ty = threadIdx.y;
#pragma unroll
    for (int j = ty; j < 32; j += 8)
        t[j][tx] = W[((size_t)h * EE + e0 + j) * DD + d0 + tx] * sc;
    __syncthreads();
#pragma unroll
    for (int j = ty; j < 32; j += 8)
        g_wqkvt[(size_t)(sec * 768 + h * 64 + d0 + j) * EE + e0 + tx] =
            __float2half_rn(t[tx][j]);
}

__global__ void pack_bias_kernel(const float* __restrict__ bq, const float* __restrict__ bk,
                                 const float* __restrict__ bv) {
    int idx = blockIdx.x * blockDim.x + threadIdx.x;
    if (idx >= QKV_N) return;
    int sec = idx / 768;
    const float* bsrc = (sec == 0) ? bq : (sec == 1) ? bk : bv;
    float v = bsrc[idx % 768];
    g_bqkv[idx] = (sec == 0) ? v * 0.125f : v;
}

__global__ void transpose_h_tiled(const float* __restrict__ in,
                                  __half* __restrict__ oh, int K, int N) {
    __shared__ float t[32][33];
    int n0 = blockIdx.x * 32, k0 = blockIdx.y * 32;
    int tx = threadIdx.x, ty = threadIdx.y;
#pragma unroll
    for (int j = ty; j < 32; j += 8)
        t[j][tx] = in[(size_t)(k0 + j) * N + n0 + tx];
    __syncthreads();
#pragma unroll
    for (int j = ty; j < 32; j += 8)
        oh[(size_t)(n0 + j) * K + k0 + tx] = __float2half_rn(t[tx][j]);
}

// ---------------- LN: warp-per-row, 8 rows/block ----------------
__device__ __forceinline__ float wsum(float v) {
#pragma unroll
    for (int m = 16; m; m >>= 1) v += __shfl_xor_sync(0xffffffffu, v, m);
    return v;
}

__global__ void __launch_bounds__(256) ln_h_kernel(const float* __restrict__ in,
                                                   const float* __restrict__ gam,
                                                   const float* __restrict__ bet,
                                                   __half* __restrict__ oh) {
    int w = threadIdx.x >> 5, lane = threadIdx.x & 31;
    size_t row = (size_t)blockIdx.x * 8 + w;
    const float4* xp = (const float4*)(in + row * EE);
    float4 xv[6];
    float s = 0.f;
#pragma unroll
    for (int i = 0; i < 6; i++) {
        xv[i] = xp[lane + 32 * i];
        s += xv[i].x + xv[i].y + xv[i].z + xv[i].w;
    }
    float mu = wsum(s) * (1.f / EE);
    float v = 0.f;
#pragma unroll
    for (int i = 0; i < 6; i++) {
        xv[i].x -= mu; xv[i].y -= mu; xv[i].z -= mu; xv[i].w -= mu;
        v += xv[i].x * xv[i].x + xv[i].y * xv[i].y + xv[i].z * xv[i].z + xv[i].w * xv[i].w;
    }
    float rstd = rsqrtf(wsum(v) * (1.f / EE) + 1e-5f);
    uint2* op = (uint2*)(oh + row * EE);
#pragma unroll
    for (int i = 0; i < 6; i++) {
        float4 g = __ldg(&((const float4*)gam)[lane + 32 * i]);
        float4 be = __ldg(&((const float4*)bet)[lane + 32 * i]);
        uint2 o;
        o.x = pack2(xv[i].x * rstd * g.x + be.x, xv[i].y * rstd * g.y + be.y);
        o.y = pack2(xv[i].z * rstd * g.z + be.z, xv[i].w * rstd * g.w + be.w);
        op[lane + 32 * i] = o;
    }
}

__global__ void __launch_bounds__(256) ln_final_kernel(const float* __restrict__ in,
                                                       const float* __restrict__ gam,
                                                       const float* __restrict__ bet,
                                                       const float* __restrict__ res,
                                                       float* __restrict__ out) {
    int w = threadIdx.x >> 5, lane = threadIdx.x & 31;
    size_t row = (size_t)blockIdx.x * 8 + w;
    const float4* xp = (const float4*)(in + row * EE);
    float4 xv[6];
    float s = 0.f;
#pragma unroll
    for (int i = 0; i < 6; i++) {
        xv[i] = xp[lane + 32 * i];
        s += xv[i].x + xv[i].y + xv[i].z + xv[i].w;
    }
    float mu = wsum(s) * (1.f / EE);
    float v = 0.f;
#pragma unroll
    for (int i = 0; i < 6; i++) {
        xv[i].x -= mu; xv[i].y -= mu; xv[i].z -= mu; xv[i].w -= mu;
        v += xv[i].x * xv[i].x + xv[i].y * xv[i].y + xv[i].z * xv[i].z + xv[i].w * xv[i].w;
    }
    float rstd = rsqrtf(wsum(v) * (1.f / EE) + 1e-5f);
    float4* op = (float4*)(out + row * EE);
    const float4* rp = (const float4*)(res + row * EE);
#pragma unroll
    for (int i = 0; i < 6; i++) {
        float4 g = __ldg(&((const float4*)gam)[lane + 32 * i]);
        float4 be = __ldg(&((const float4*)bet)[lane + 32 * i]);
        float4 r = rp[lane + 32 * i];
        float4 o;
        o.x = xv[i].x * rstd * g.x + be.x + r.x;
        o.y = xv[i].y * rstd * g.y + be.y + r.y;
        o.z = xv[i].z * rstd * g.z + be.z + r.z;
        o.w = xv[i].w * rstd * g.w + be.w + r.w;
        op[lane + 32 * i] = o;
    }
}

// ---------------- HMMA primitives (fp16) ----------------
__device__ __forceinline__ void cpasync16(uint32_t dst, const void* src) {
    asm volatile("cp.async.cg.shared.global [%0], [%1], 16;" :: "r"(dst), "l"(src));
}
__device__ __forceinline__ void ldm4(uint32_t* r, uint32_t addr) {
    asm volatile("ldmatrix.sync.aligned.m8n8.x4.shared.b16 {%0,%1,%2,%3}, [%4];"
                 : "=r"(r[0]), "=r"(r[1]), "=r"(r[2]), "=r"(r[3]) : "r"(addr));
}
__device__ __forceinline__ void ldm4t(uint32_t* r, uint32_t addr) {
    asm volatile("ldmatrix.sync.aligned.m8n8.x4.trans.shared.b16 {%0,%1,%2,%3}, [%4];"
                 : "=r"(r[0]), "=r"(r[1]), "=r"(r[2]), "=r"(r[3]) : "r"(addr));
}
__device__ __forceinline__ void mma16816(float* d, const uint32_t* a, uint32_t b0, uint32_t b1) {
    asm volatile(
        "mma.sync.aligned.m16n8k16.row.col.f32.f16.f16.f32 "
        "{%0,%1,%2,%3}, {%4,%5,%6,%7}, {%8,%9}, {%0,%1,%2,%3};"
        : "+f"(d[0]), "+f"(d[1]), "+f"(d[2]), "+f"(d[3])
        : "r"(a[0]), "r"(a[1]), "r"(a[2]), "r"(a[3]), "r"(b0), "r"(b1));
}

// ---------------- HMMA GEMM: 128x128 CTA, 128 thr, 64x64 warp, 3-stage ------
// 2 CTAs/SM. EPI: 0 bias->f32, 1 bias+gelu->fp16, 2 bias+res->f32, 3 bias->fp16
#define STG 32768   // A 16K | B 16K

template <int EPI>
__global__ void __launch_bounds__(128, 2) tcgemm(const __half* __restrict__ Ah,
                                                 const __half* __restrict__ Bh,
                                                 const float* __restrict__ bias,
                                                 const float* __restrict__ res,
                                                 float* __restrict__ C,
                                                 __half* __restrict__ Ch,
                                                 int N, int K) {
    extern __shared__ char sm[];
    uint32_t sbase = (uint32_t)__cvta_generic_to_shared(sm);
    int tid = threadIdx.x;
    int lane = tid & 31, w = tid >> 5;
    int wm = w >> 1, wn = w & 1;
    int bn = blockIdx.x * 128, bm = blockIdx.y * 128;

    float acc[4][8][4];
#pragma unroll
    for (int i = 0; i < 4; i++)
#pragma unroll
        for (int j = 0; j < 8; j++)
#pragma unroll
            for (int q = 0; q < 4; q++) acc[i][j][q] = 0.f;

    int nk = K >> 6;

#define LOAD_STAGE(kc, buf)                                                        \
    {                                                                              \
        uint32_t sb_ = sbase + (buf) * STG;                                        \
        _Pragma("unroll")                                                          \
        for (int ii = 0; ii < 16; ii++) {                                          \
            int i = tid + ii * 128;                                                \
            int t = i >> 10, wrd = i & 1023, r = wrd >> 3, c = wrd & 7;            \
            int rb = t ? bn : bm;                                                  \
            const __half* sp = (t ? Bh : Ah) + (size_t)(rb + r) * K + (kc) * 64 + c * 8; \
            cpasync16(sb_ + t * 16384 + swz(r * 128 + c * 16), sp);                \
        }                                                                          \
        asm volatile("cp.async.commit_group;" ::: "memory");                       \
    }

    LOAD_STAGE(0, 0);
    LOAD_STAGE(1, 1);

    int ra = (lane & 7) + ((lane & 8) ? 8 : 0);
    int ka = (lane & 16) ? 8 : 0;
    int rb_n = (lane & 7) + ((lane & 16) ? 8 : 0);
    int kb_n = (lane & 8) ? 8 : 0;

    int buf = 0;
    for (int kc = 0; kc < nk; kc++) {
        if (kc + 1 < nk) {
            asm volatile("cp.async.wait_group 1;" ::: "memory");
        } else {
            asm volatile("cp.async.wait_group 0;" ::: "memory");
        }
        __syncthreads();
        if (kc + 2 < nk) {
            int nb = buf + 2;
            if (nb >= 3) nb -= 3;
            LOAD_STAGE(kc + 2, nb);
        }
        uint32_t sb = sbase + buf * STG;
#pragma unroll
        for (int ks = 0; ks < 4; ks++) {
            uint32_t Af[4][4], Bf[4][4];
#pragma unroll
            for (int mt = 0; mt < 4; mt++) {
                int row = wm * 64 + mt * 16 + ra;
                ldm4(Af[mt], sb + swz(row * 128 + (ks * 16 + ka) * 2));
            }
#pragma unroll
            for (int pr = 0; pr < 4; pr++) {
                int row = wn * 64 + pr * 16 + rb_n;
                ldm4(Bf[pr], sb + 16384 + swz(row * 128 + (ks * 16 + kb_n) * 2));
            }
#pragma unroll
            for (int mt = 0; mt < 4; mt++)
#pragma unroll
                for (int nt = 0; nt < 8; nt++) {
                    int pr = nt >> 1, o = (nt & 1) * 2;
                    mma16816(acc[mt][nt], Af[mt], Bf[pr][o], Bf[pr][o + 1]);
                }
        }
        if (++buf == 3) buf = 0;
    }

    int l4 = lane >> 2, l2 = (lane & 3) * 2;
#pragma unroll
    for (int mt = 0; mt < 4; mt++)
#pragma unroll
        for (int nt = 0; nt < 8; nt++) {
            int col = bn + wn * 64 + nt * 8 + l2;
            float b0 = __ldg(&bias[col]), b1 = __ldg(&bias[col + 1]);
#pragma unroll
            for (int half = 0; half < 2; half++) {
                size_t row = (size_t)(bm + wm * 64 + mt * 16 + l4 + half * 8);
                float v0 = acc[mt][nt][half * 2 + 0] + b0;
                float v1 = acc[mt][nt][half * 2 + 1] + b1;
                if (EPI == 2) {
                    float2 rr = __ldg((const float2*)&res[row * N + col]);
                    v0 += rr.x;
                    v1 += rr.y;
                }
                if (EPI == 1) {
                    v0 = 0.5f * v0 * (1.0f + erff(v0 * 0.70710678118654752f));
                    v1 = 0.5f * v1 * (1.0f + erff(v1 * 0.70710678118654752f));
                }
                if (EPI == 1 || EPI == 3) {
                    *(__half2*)&Ch[row * N + col] = __floats2half2_rn(v0, v1);
                } else {
                    *(float2*)&C[row * N + col] = make_float2(v0, v1);
                }
            }
        }
#undef LOAD_STAGE
}

// ---------------- HMMA flash attention: 128-row Q tile, 256 threads ----------
// Heavy tiles scheduled first: qt = gridDim.x-1-blockIdx.x (LPT wave balance).
__global__ void __launch_bounds__(256, 2) attn_kernel(const __half* __restrict__ qkvh,
                                                      __half* __restrict__ oh) {
    extern __shared__ char smc[];
    uint32_t sb = (uint32_t)__cvta_generic_to_shared(smc);
    uint32_t Qs = sb;

    int qt = gridDim.x - 1 - blockIdx.x;   // heavy (large qt) first
    int bh = blockIdx.y;
    int b = bh / HH, h = bh % HH;
    int tid = threadIdx.x, lane = tid & 31, w = tid >> 5;
    size_t base = (size_t)b * SS * QKV_N;
    int hoff = h * DD;

#pragma unroll
    for (int ii = 0; ii < 4; ii++) {
        int i = tid + ii * 256;
        int r = i >> 3, c = i & 7;
        cpasync16(Qs + swz(r * 128 + c * 16),
                  qkvh + base + (size_t)(qt * 128 + r) * QKV_N + hoff + c * 8);
    }

#define ISSUE_KV(kt, bufo)                                                          \
    {                                                                               \
        _Pragma("unroll")                                                           \
        for (int ii = 0; ii < 4; ii++) {                                            \
            int i = tid + ii * 256;                                                 \
            int ts = i >> 9, wrd = i & 511, r = wrd >> 3, c = wrd & 7;              \
            cpasync16(sb + (bufo) + ts * 8192 + swz(r * 128 + c * 16),              \
                      qkvh + base + (size_t)((kt) * 64 + r) * QKV_N + hoff +        \
                          (ts ? 2 * EE : EE) + c * 8);                              \
        }                                                                           \
        asm volatile("cp.async.commit_group;" ::: "memory");                        \
    }

    ISSUE_KV(0, 16384);

    int ra = (lane & 7) + ((lane & 8) ? 8 : 0);
    int ka = (lane & 16) ? 8 : 0;
    int rbn = (lane & 7) + ((lane & 16) ? 8 : 0);
    int kbn = (lane & 8) ? 8 : 0;
    int vkr = (lane & 7) + ((lane & 8) ? 8 : 0);
    int vnc = (lane & 16) ? 8 : 0;
    int r0 = lane >> 2, c0 = (lane & 3) * 2;

    int qrow = qt * 128 + w * 16;
    int ktmax = 2 * qt + 1;

    float m0 = -1e30f, m1 = -1e30f, l0 = 0.f, l1 = 0.f;
    float o[8][4];
#pragma unroll
    for (int i = 0; i < 8; i++)
#pragma unroll
        for (int j = 0; j < 4; j++) o[i][j] = 0.f;

    for (int kt = 0; kt <= ktmax; kt++) {
        asm volatile("cp.async.wait_group 0;" ::: "memory");
        __syncthreads();
        uint32_t kvo = 16384 + (kt & 1) * 16384;
        if (kt < ktmax) ISSUE_KV(kt + 1, 16384 + ((kt + 1) & 1) * 16384);
        uint32_t Kh = sb + kvo, Vh = sb + kvo + 8192;

        if (kt * 64 <= qrow + 15) {
            float s[8][4];
#pragma unroll
            for (int i = 0; i < 8; i++)
#pragma unroll
                for (int j = 0; j < 4; j++) s[i][j] = 0.f;
#pragma unroll
            for (int kc = 0; kc < 4; kc++) {
                uint32_t qh[4], kh[4][4];
                ldm4(qh, Qs + swz((w * 16 + ra) * 128 + (kc * 16 + ka) * 2));
#pragma unroll
                for (int tg = 0; tg < 4; tg++)
                    ldm4(kh[tg], Kh + swz((tg * 16 + rbn) * 128 + (kc * 16 + kbn) * 2));
#pragma unroll
                for (int nt = 0; nt < 8; nt++) {
                    int pr = nt >> 1, oo = (nt & 1) * 2;
                    mma16816(s[nt], qh, kh[pr][oo], kh[pr][oo + 1]);
                }
            }

            if (kt * 64 + 63 > qrow) {
                int row0 = qrow + r0, row1 = row0 + 8;
#pragma unroll
                for (int nt = 0; nt < 8; nt++) {
                    int c = kt * 64 + nt * 8 + c0;
                    if (c > row0) s[nt][0] = -1e30f;
                    if (c + 1 > row0) s[nt][1] = -1e30f;
                    if (c > row1) s[nt][2] = -1e30f;
                    if (c + 1 > row1) s[nt][3] = -1e30f;
                }
            }

            float mt0 = -1e30f, mt1 = -1e30f;
#pragma unroll
            for (int nt = 0; nt < 8; nt++) {
                mt0 = fmaxf(mt0, fmaxf(s[nt][0], s[nt][1]));
                mt1 = fmaxf(mt1, fmaxf(s[nt][2], s[nt][3]));
            }
#pragma unroll
            for (int off = 1; off <= 2; off <<= 1) {
                mt0 = fmaxf(mt0, __shfl_xor_sync(0xffffffffu, mt0, off));
                mt1 = fmaxf(mt1, __shfl_xor_sync(0xffffffffu, mt1, off));
            }
            float mn0 = fmaxf(m0, mt0), mn1 = fmaxf(m1, mt1);
            float sc0 = __expf(m0 - mn0), sc1 = __expf(m1 - mn1);
            float rs0 = 0.f, rs1 = 0.f;
#pragma unroll
            for (int nt = 0; nt < 8; nt++) {
                s[nt][0] = __expf(s[nt][0] - mn0);
                s[nt][1] = __expf(s[nt][1] - mn0);
                s[nt][2] = __expf(s[nt][2] - mn1);
                s[nt][3] = __expf(s[nt][3] - mn1);
                rs0 += s[nt][0] + s[nt][1];
                rs1 += s[nt][2] + s[nt][3];
            }
#pragma unroll
            for (int off = 1; off <= 2; off <<= 1) {
                rs0 += __shfl_xor_sync(0xffffffffu, rs0, off);
                rs1 += __shfl_xor_sync(0xffffffffu, rs1, off);
            }
            l0 = l0 * sc0 + rs0;
            l1 = l1 * sc1 + rs1;
            m0 = mn0;
            m1 = mn1;
#pragma unroll
            for (int i = 0; i < 8; i++) {
                o[i][0] *= sc0; o[i][1] *= sc0;
                o[i][2] *= sc1; o[i][3] *= sc1;
            }

#pragma unroll
            for (int kc = 0; kc < 4; kc++) {
                uint32_t aph[4];
                aph[0] = pack2(s[2 * kc][0], s[2 * kc][1]);
                aph[1] = pack2(s[2 * kc][2], s[2 * kc][3]);
                aph[2] = pack2(s[2 * kc + 1][0], s[2 * kc + 1][1]);
                aph[3] = pack2(s[2 * kc + 1][2], s[2 * kc + 1][3]);
                uint32_t vh[4][4];
#pragma unroll
                for (int dg = 0; dg < 4; dg++)
                    ldm4t(vh[dg], Vh + swz((kc * 16 + vkr) * 128 + (dg * 16 + vnc) * 2));
#pragma unroll
                for (int dt = 0; dt < 8; dt++) {
                    int pr = dt >> 1, oo = (dt & 1) * 2;
                    mma16816(o[dt], aph, vh[pr][oo], vh[pr][oo + 1]);
                }
            }
        }
    }

    float inv0 = 1.f / l0, inv1 = 1.f / l1;
    size_t row0 = (size_t)b * SS + qrow + r0;
    size_t row1 = row0 + 8;
#pragma unroll
    for (int dt = 0; dt < 8; dt++) {
        int d = hoff + dt * 8 + c0;
        *(__half2*)&oh[row0 * EE + d] = __floats2half2_rn(o[dt][0] * inv0, o[dt][1] * inv0);
        *(__half2*)&oh[row1 * EE + d] = __floats2half2_rn(o[dt][2] * inv1, o[dt][3] * inv1);
    }
#undef ISSUE_KV
}

// ---------------- launch ----------------
extern "C" void kernel_launch(void* const* d_in, const int* in_sizes, int n_in,
                              void* d_out, int out_size) {
    const float* x = (const float*)d_in[0];
    const float* Wq = (const float*)d_in[1];
    const float* bq = (const float*)d_in[2];
    const float* Wk = (const float*)d_in[3];
    const float* bk = (const float*)d_in[4];
    const float* Wv = (const float*)d_in[5];
    const float* bv = (const float*)d_in[6];
    const float* Wp = (const float*)d_in[7];
    const float* bp = (const float*)d_in[8];
    const float* ln1_g = (const float*)d_in[9];
    const float* ln1_b = (const float*)d_in[10];
    const float* ln2_g = (const float*)d_in[11];
    const float* ln2_b = (const float*)d_in[12];
    const float* W1 = (const float*)d_in[13];
    const float* b1 = (const float*)d_in[14];
    const float* W2 = (const float*)d_in[15];
    const float* b2 = (const float*)d_in[16];
    const float* lnf_g = (const float*)d_in[17];
    const float* lnf_b = (const float*)d_in[18];
    float* out = (float*)d_out;

    __half *p_ah, *p_fh, *p_qkvh, *p_wq, *p_wp, *p_w1, *p_w2;
    float *p_bqkv, *p_x1, *p_f2;
    cudaGetSymbolAddress((void**)&p_ah, g_ah);
    cudaGetSymbolAddress((void**)&p_fh, g_fh);
    cudaGetSymbolAddress((void**)&p_qkvh, g_qkvh);
    cudaGetSymbolAddress((void**)&p_wq, g_wqkvt);
    cudaGetSymbolAddress((void**)&p_wp, g_wpt);
    cudaGetSymbolAddress((void**)&p_w1, g_w1t);
    cudaGetSymbolAddress((void**)&p_w2, g_w2t);
    cudaGetSymbolAddress((void**)&p_bqkv, g_bqkv);
    cudaGetSymbolAddress((void**)&p_x1, g_x1);
    cudaGetSymbolAddress((void**)&p_f2, g_f2);

    int gsmem = 3 * STG;  // 98304
    cudaFuncSetAttribute(tcgemm<0>, cudaFuncAttributeMaxDynamicSharedMemorySize, gsmem);
    cudaFuncSetAttribute(tcgemm<1>, cudaFuncAttributeMaxDynamicSharedMemorySize, gsmem);
    cudaFuncSetAttribute(tcgemm<2>, cudaFuncAttributeMaxDynamicSharedMemorySize, gsmem);
    cudaFuncSetAttribute(tcgemm<3>, cudaFuncAttributeMaxDynamicSharedMemorySize, gsmem);
    int asmem = 49152;
    cudaFuncSetAttribute(attn_kernel, cudaFuncAttributeMaxDynamicSharedMemorySize, asmem);

    dim3 tb(32, 8);
    pack_wqkv_tiled<<<dim3(2, 24, 36), tb>>>(Wq, Wk, Wv);
    pack_bias_kernel<<<9, 256>>>(bq, bk, bv);
    transpose_h_tiled<<<dim3(EE / 32, EE / 32), tb>>>(Wp, p_wp, EE, EE);
    transpose_h_tiled<<<dim3(FF / 32, EE / 32), tb>>>(W1, p_w1, EE, FF);
    transpose_h_tiled<<<dim3(EE / 32, FF / 32), tb>>>(W2, p_w2, FF, EE);

    ln_h_kernel<<<ROWS / 8, 256>>>(x, ln1_g, ln1_b, p_ah);
    tcgemm<3><<<dim3(QKV_N / 128, ROWS / 128), 128, gsmem>>>(
        p_ah, p_wq, p_bqkv, nullptr, nullptr, p_qkvh, QKV_N, EE);
    attn_kernel<<<dim3(SS / 128, BB * HH), 256, asmem>>>(p_qkvh, p_ah);
    tcgemm<2><<<dim3(EE / 128, ROWS / 128), 128, gsmem>>>(
        p_ah, p_wp, bp, x, p_x1, nullptr, EE, EE);
    ln_h_kernel<<<ROWS / 8, 256>>>(p_x1, ln2_g, ln2_b, p_ah);
    tcgemm<1><<<dim3(FF / 128, ROWS / 128), 128, gsmem>>>(
        p_ah, p_w1, b1, nullptr, nullptr, p_fh, FF, EE);
    tcgemm<0><<<dim3(EE / 128, ROWS / 128), 128, gsmem>>>(
        p_fh, p_w2, b2, nullptr, p_f2, nullptr, EE, FF);
    ln_final_kernel<<<ROWS / 8, 256>>>(p_f2, lnf_g, lnf_b, p_x1, out);
}

// round 15
// speedup vs baseline: 12.0126x; 1.0026x over previous
#include <cuda_runtime.h>
#include <cuda_fp16.h>
#include <math.h>
#include <stdint.h>

#define BB 16
#define SS 1024
#define EE 768
#define HH 12
#define DD 64
#define FF 3072
#define ROWS (BB * SS)
#define QKV_N (3 * EE)

// scratch
__device__ __half g_ah[ROWS * EE];
__device__ __half g_fh[ROWS * FF];
__device__ __half g_qkvh[ROWS * QKV_N];   // qkv; later reused as fp16 f2 buffer
__device__ __half g_wqkvt[QKV_N * EE];
__device__ __half g_wpt[EE * EE];
__device__ __half g_w1t[FF * EE];
__device__ __half g_w2t[EE * FF];
__device__ float g_bqkv[QKV_N];
__device__ float g_x1[ROWS * EE];

__device__ __forceinline__ uint32_t swz(uint32_t o) { return o ^ ((o >> 3) & 0x70); }
__device__ __forceinline__ uint32_t pack2(float x, float y) {
    __half2 t = __floats2half2_rn(x, y);
    return *(uint32_t*)&t;
}

// ---------------- weight prep (tiled, coalesced) ----------------
__global__ void pack_wqkv_tiled(const float* __restrict__ Wq, const float* __restrict__ Wk,
                                const float* __restrict__ Wv) {
    __shared__ float t[32][33];
    int z = blockIdx.z, sec = z / 12, h = z % 12;
    const float* W = (sec == 0) ? Wq : (sec == 1) ? Wk : Wv;
    float sc = (sec == 0) ? 0.125f : 1.0f;
    int d0 = blockIdx.x * 32, e0 = blockIdx.y * 32;
    int tx = threadIdx.x, ty = threadIdx.y;
#pragma unroll
    for (int j = ty; j < 32; j += 8)
        t[j][tx] = W[((size_t)h * EE + e0 + j) * DD + d0 + tx] * sc;
    __syncthreads();
#pragma unroll
    for (int j = ty; j < 32; j += 8)
        g_wqkvt[(size_t)(sec * 768 + h * 64 + d0 + j) * EE + e0 + tx] =
            __float2half_rn(t[tx][j]);
}

__global__ void pack_bias_kernel(const float* __restrict__ bq, const float* __restrict__ bk,
                                 const float* __restrict__ bv) {
    int idx = blockIdx.x * blockDim.x + threadIdx.x;
    if (idx >= QKV_N) return;
    int sec = idx / 768;
    const float* bsrc = (sec == 0) ? bq : (sec == 1) ? bk : bv;
    float v = bsrc[idx % 768];
    g_bqkv[idx] = (sec == 0) ? v * 0.125f : v;
}

__global__ void transpose_h_tiled(const float* __restrict__ in,
                                  __half* __restrict__ oh, int K, int N) {
    __shared__ float t[32][33];
    int n0 = blockIdx.x * 32, k0 = blockIdx.y * 32;
    int tx = threadIdx.x, ty = threadIdx.y;
#pragma unroll
    for (int j = ty; j < 32; j += 8)
        t[j][tx] = in[(size_t)(k0 + j) * N + n0 + tx];
    __syncthreads();
#pragma unroll
    for (int j = ty; j < 32; j += 8)
        oh[(size_t)(n0 + j) * K + k0 + tx] = __float2half_rn(t[tx][j]);
}

// ---------------- LN: warp-per-row, 8 rows/block ----------------
__device__ __forceinline__ float wsum(float v) {
#pragma unroll
    for (int m = 16; m; m >>= 1) v += __shfl_xor_sync(0xffffffffu, v, m);
    return v;
}

__global__ void __launch_bounds__(256) ln_h_kernel(const float* __restrict__ in,
                                                   const float* __restrict__ gam,
                                                   const float* __restrict__ bet,
                                                   __half* __restrict__ oh) {
    int w = threadIdx.x >> 5, lane = threadIdx.x & 31;
    size_t row = (size_t)blockIdx.x * 8 + w;
    const float4* xp = (const float4*)(in + row * EE);
    float4 xv[6];
    float s = 0.f;
#pragma unroll
    for (int i = 0; i < 6; i++) {
        xv[i] = xp[lane + 32 * i];
        s += xv[i].x + xv[i].y + xv[i].z + xv[i].w;
    }
    float mu = wsum(s) * (1.f / EE);
    float v = 0.f;
#pragma unroll
    for (int i = 0; i < 6; i++) {
        xv[i].x -= mu; xv[i].y -= mu; xv[i].z -= mu; xv[i].w -= mu;
        v += xv[i].x * xv[i].x + xv[i].y * xv[i].y + xv[i].z * xv[i].z + xv[i].w * xv[i].w;
    }
    float rstd = rsqrtf(wsum(v) * (1.f / EE) + 1e-5f);
    uint2* op = (uint2*)(oh + row * EE);
#pragma unroll
    for (int i = 0; i < 6; i++) {
        float4 g = __ldg(&((const float4*)gam)[lane + 32 * i]);
        float4 be = __ldg(&((const float4*)bet)[lane + 32 * i]);
        uint2 o;
        o.x = pack2(xv[i].x * rstd * g.x + be.x, xv[i].y * rstd * g.y + be.y);
        o.y = pack2(xv[i].z * rstd * g.z + be.z, xv[i].w * rstd * g.w + be.w);
        op[lane + 32 * i] = o;
    }
}

// final LN: fp16 input (f2), fp32 residual, fp32 out
__global__ void __launch_bounds__(256) ln_final_kernel(const __half* __restrict__ in,
                                                       const float* __restrict__ gam,
                                                       const float* __restrict__ bet,
                                                       const float* __restrict__ res,
                                                       float* __restrict__ out) {
    int w = threadIdx.x >> 5, lane = threadIdx.x & 31;
    size_t row = (size_t)blockIdx.x * 8 + w;
    const uint2* xp = (const uint2*)(in + row * EE);
    float4 xv[6];
    float s = 0.f;
#pragma unroll
    for (int i = 0; i < 6; i++) {
        uint2 p = xp[lane + 32 * i];
        __half2 h0 = *(__half2*)&p.x, h1 = *(__half2*)&p.y;
        float2 f0 = __half22float2(h0), f1 = __half22float2(h1);
        xv[i] = make_float4(f0.x, f0.y, f1.x, f1.y);
        s += xv[i].x + xv[i].y + xv[i].z + xv[i].w;
    }
    float mu = wsum(s) * (1.f / EE);
    float v = 0.f;
#pragma unroll
    for (int i = 0; i < 6; i++) {
        xv[i].x -= mu; xv[i].y -= mu; xv[i].z -= mu; xv[i].w -= mu;
        v += xv[i].x * xv[i].x + xv[i].y * xv[i].y + xv[i].z * xv[i].z + xv[i].w * xv[i].w;
    }
    float rstd = rsqrtf(wsum(v) * (1.f / EE) + 1e-5f);
    float4* op = (float4*)(out + row * EE);
    const float4* rp = (const float4*)(res + row * EE);
#pragma unroll
    for (int i = 0; i < 6; i++) {
        float4 g = __ldg(&((const float4*)gam)[lane + 32 * i]);
        float4 be = __ldg(&((const float4*)bet)[lane + 32 * i]);
        float4 r = rp[lane + 32 * i];
        float4 o;
        o.x = xv[i].x * rstd * g.x + be.x + r.x;
        o.y = xv[i].y * rstd * g.y + be.y + r.y;
        o.z = xv[i].z * rstd * g.z + be.z + r.z;
        o.w = xv[i].w * rstd * g.w + be.w + r.w;
        op[lane + 32 * i] = o;
    }
}

// ---------------- HMMA primitives (fp16) ----------------
__device__ __forceinline__ void cpasync16(uint32_t dst, const void* src) {
    asm volatile("cp.async.cg.shared.global [%0], [%1], 16;" :: "r"(dst), "l"(src));
}
__device__ __forceinline__ void ldm4(uint32_t* r, uint32_t addr) {
    asm volatile("ldmatrix.sync.aligned.m8n8.x4.shared.b16 {%0,%1,%2,%3}, [%4];"
                 : "=r"(r[0]), "=r"(r[1]), "=r"(r[2]), "=r"(r[3]) : "r"(addr));
}
__device__ __forceinline__ void ldm4t(uint32_t* r, uint32_t addr) {
    asm volatile("ldmatrix.sync.aligned.m8n8.x4.trans.shared.b16 {%0,%1,%2,%3}, [%4];"
                 : "=r"(r[0]), "=r"(r[1]), "=r"(r[2]), "=r"(r[3]) : "r"(addr));
}
__device__ __forceinline__ void mma16816(float* d, const uint32_t* a, uint32_t b0, uint32_t b1) {
    asm volatile(
        "mma.sync.aligned.m16n8k16.row.col.f32.f16.f16.f32 "
        "{%0,%1,%2,%3}, {%4,%5,%6,%7}, {%8,%9}, {%0,%1,%2,%3};"
        : "+f"(d[0]), "+f"(d[1]), "+f"(d[2]), "+f"(d[3])
        : "r"(a[0]), "r"(a[1]), "r"(a[2]), "r"(a[3]), "r"(b0), "r"(b1));
}

// ---------------- HMMA GEMM: 128x128 CTA, 128 thr, 64x64 warp, 3-stage ------
// 2 CTAs/SM. EPI: 0 bias->f32, 1 bias+gelu->fp16, 2 bias+res->f32, 3 bias->fp16
#define STG 32768

template <int EPI>
__global__ void __launch_bounds__(128, 2) tcgemm(const __half* __restrict__ Ah,
                                                 const __half* __restrict__ Bh,
                                                 const float* __restrict__ bias,
                                                 const float* __restrict__ res,
                                                 float* __restrict__ C,
                                                 __half* __restrict__ Ch,
                                                 int N, int K) {
    extern __shared__ char sm[];
    uint32_t sbase = (uint32_t)__cvta_generic_to_shared(sm);
    int tid = threadIdx.x;
    int lane = tid & 31, w = tid >> 5;
    int wm = w >> 1, wn = w & 1;
    int bn = blockIdx.x * 128, bm = blockIdx.y * 128;

    float acc[4][8][4];
#pragma unroll
    for (int i = 0; i < 4; i++)
#pragma unroll
        for (int j = 0; j < 8; j++)
#pragma unroll
            for (int q = 0; q < 4; q++) acc[i][j][q] = 0.f;

    int nk = K >> 6;

#define LOAD_STAGE(kc, buf)                                                        \
    {                                                                              \
        uint32_t sb_ = sbase + (buf) * STG;                                        \
        _Pragma("unroll")                                                          \
        for (int ii = 0; ii < 16; ii++) {                                          \
            int i = tid + ii * 128;                                                \
            int t = i >> 10, wrd = i & 1023, r = wrd >> 3, c = wrd & 7;            \
            int rb = t ? bn : bm;                                                  \
            const __half* sp = (t ? Bh : Ah) + (size_t)(rb + r) * K + (kc) * 64 + c * 8; \
            cpasync16(sb_ + t * 16384 + swz(r * 128 + c * 16), sp);                \
        }                                                                          \
        asm volatile("cp.async.commit_group;" ::: "memory");                       \
    }

    LOAD_STAGE(0, 0);
    LOAD_STAGE(1, 1);

    int ra = (lane & 7) + ((lane & 8) ? 8 : 0);
    int ka = (lane & 16) ? 8 : 0;
    int rb_n = (lane & 7) + ((lane & 16) ? 8 : 0);
    int kb_n = (lane & 8) ? 8 : 0;

    int buf = 0;
    for (int kc = 0; kc < nk; kc++) {
        if (kc + 1 < nk) {
            asm volatile("cp.async.wait_group 1;" ::: "memory");
        } else {
            asm volatile("cp.async.wait_group 0;" ::: "memory");
        }
        __syncthreads();
        if (kc + 2 < nk) {
            int nb = buf + 2;
            if (nb >= 3) nb -= 3;
            LOAD_STAGE(kc + 2, nb);
        }
        uint32_t sb = sbase + buf * STG;
#pragma unroll
        for (int ks = 0; ks < 4; ks++) {
            uint32_t Af[4][4], Bf[4][4];
#pragma unroll
            for (int mt = 0; mt < 4; mt++) {
                int row = wm * 64 + mt * 16 + ra;
                ldm4(Af[mt], sb + swz(row * 128 + (ks * 16 + ka) * 2));
            }
#pragma unroll
            for (int pr = 0; pr < 4; pr++) {
                int row = wn * 64 + pr * 16 + rb_n;
                ldm4(Bf[pr], sb + 16384 + swz(row * 128 + (ks * 16 + kb_n) * 2));
            }
#pragma unroll
            for (int mt = 0; mt < 4; mt++)
#pragma unroll
                for (int nt = 0; nt < 8; nt++) {
                    int pr = nt >> 1, o = (nt & 1) * 2;
                    mma16816(acc[mt][nt], Af[mt], Bf[pr][o], Bf[pr][o + 1]);
                }
        }
        if (++buf == 3) buf = 0;
    }

    int l4 = lane >> 2, l2 = (lane & 3) * 2;
#pragma unroll
    for (int mt = 0; mt < 4; mt++)
#pragma unroll
        for (int nt = 0; nt < 8; nt++) {
            int col = bn + wn * 64 + nt * 8 + l2;
            float b0 = __ldg(&bias[col]), b1 = __ldg(&bias[col + 1]);
#pragma unroll
            for (int half = 0; half < 2; half++) {
                size_t row = (size_t)(bm + wm * 64 + mt * 16 + l4 + half * 8);
                float v0 = acc[mt][nt][half * 2 + 0] + b0;
                float v1 = acc[mt][nt][half * 2 + 1] + b1;
                if (EPI == 2) {
                    float2 rr = __ldg((const float2*)&res[row * N + col]);
                    v0 += rr.x;
                    v1 += rr.y;
                }
                if (EPI == 1) {
                    v0 = 0.5f * v0 * (1.0f + erff(v0 * 0.70710678118654752f));
                    v1 = 0.5f * v1 * (1.0f + erff(v1 * 0.70710678118654752f));
                }
                if (EPI == 1 || EPI == 3) {
                    *(__half2*)&Ch[row * N + col] = __floats2half2_rn(v0, v1);
                } else {
                    *(float2*)&C[row * N + col] = make_float2(v0, v1);
                }
            }
        }
#undef LOAD_STAGE
}

// ---------------- HMMA flash attention: 128-row Q tile, 256 threads ----------
__global__ void __launch_bounds__(256, 2) attn_kernel(const __half* __restrict__ qkvh,
                                                      __half* __restrict__ oh) {
    extern __shared__ char smc[];
    uint32_t sb = (uint32_t)__cvta_generic_to_shared(smc);
    uint32_t Qs = sb;

    int qt = gridDim.x - 1 - blockIdx.x;   // heavy (large qt) first
    int bh = blockIdx.y;
    int b = bh / HH, h = bh % HH;
    int tid = threadIdx.x, lane = tid & 31, w = tid >> 5;
    size_t base = (size_t)b * SS * QKV_N;
    int hoff = h * DD;

#pragma unroll
    for (int ii = 0; ii < 4; ii++) {
        int i = tid + ii * 256;
        int r = i >> 3, c = i & 7;
        cpasync16(Qs + swz(r * 128 + c * 16),
                  qkvh + base + (size_t)(qt * 128 + r) * QKV_N + hoff + c * 8);
    }

#define ISSUE_KV(kt, bufo)                                                          \
    {                                                                               \
        _Pragma("unroll")                                                           \
        for (int ii = 0; ii < 4; ii++) {                                            \
            int i = tid + ii * 256;                                                 \
            int ts = i >> 9, wrd = i & 511, r = wrd >> 3, c = wrd & 7;              \
            cpasync16(sb + (bufo) + ts * 8192 + swz(r * 128 + c * 16),              \
                      qkvh + base + (size_t)((kt) * 64 + r) * QKV_N + hoff +        \
                          (ts ? 2 * EE : EE) + c * 8);                              \
        }                                                                           \
        asm volatile("cp.async.commit_group;" ::: "memory");                        \
    }

    ISSUE_KV(0, 16384);

    int ra = (lane & 7) + ((lane & 8) ? 8 : 0);
    int ka = (lane & 16) ? 8 : 0;
    int rbn = (lane & 7) + ((lane & 16) ? 8 : 0);
    int kbn = (lane & 8) ? 8 : 0;
    int vkr = (lane & 7) + ((lane & 8) ? 8 : 0);
    int vnc = (lane & 16) ? 8 : 0;
    int r0 = lane >> 2, c0 = (lane & 3) * 2;

    int qrow = qt * 128 + w * 16;
    int ktmax = 2 * qt + 1;

    float m0 = -1e30f, m1 = -1e30f, l0 = 0.f, l1 = 0.f;
    float o[8][4];
#pragma unroll
    for (int i = 0; i < 8; i++)
#pragma unroll
        for (int j = 0; j < 4; j++) o[i][j] = 0.f;

    for (int kt = 0; kt <= ktmax; kt++) {
        asm volatile("cp.async.wait_group 0;" ::: "memory");
        __syncthreads();
        uint32_t kvo = 16384 + (kt & 1) * 16384;
        if (kt < ktmax) ISSUE_KV(kt + 1, 16384 + ((kt + 1) & 1) * 16384);
        uint32_t Kh = sb + kvo, Vh = sb + kvo + 8192;

        if (kt * 64 <= qrow + 15) {
            float s[8][4];
#pragma unroll
            for (int i = 0; i < 8; i++)
#pragma unroll
                for (int j = 0; j < 4; j++) s[i][j] = 0.f;
#pragma unroll
            for (int kc = 0; kc < 4; kc++) {
                uint32_t qh[4], kh[4][4];
                ldm4(qh, Qs + swz((w * 16 + ra) * 128 + (kc * 16 + ka) * 2));
#pragma unroll
                for (int tg = 0; tg < 4; tg++)
                    ldm4(kh[tg], Kh + swz((tg * 16 + rbn) * 128 + (kc * 16 + kbn) * 2));
#pragma unroll
                for (int nt = 0; nt < 8; nt++) {
                    int pr = nt >> 1, oo = (nt & 1) * 2;
                    mma16816(s[nt], qh, kh[pr][oo], kh[pr][oo + 1]);
                }
            }

            if (kt * 64 + 63 > qrow) {
                int row0 = qrow + r0, row1 = row0 + 8;
#pragma unroll
                for (int nt = 0; nt < 8; nt++) {
                    int c = kt * 64 + nt * 8 + c0;
                    if (c > row0) s[nt][0] = -1e30f;
                    if (c + 1 > row0) s[nt][1] = -1e30f;
                    if (c > row1) s[nt][2] = -1e30f;
                    if (c + 1 > row1) s[nt][3] = -1e30f;
                }
            }

            float mt0 = -1e30f, mt1 = -1e30f;
#pragma unroll
            for (int nt = 0; nt < 8; nt++) {
                mt0 = fmaxf(mt0, fmaxf(s[nt][0], s[nt][1]));
                mt1 = fmaxf(mt1, fmaxf(s[nt][2], s[nt][3]));
            }
#pragma unroll
            for (int off = 1; off <= 2; off <<= 1) {
                mt0 = fmaxf(mt0, __shfl_xor_sync(0xffffffffu, mt0, off));
                mt1 = fmaxf(mt1, __shfl_xor_sync(0xffffffffu, mt1, off));
            }
            float mn0 = fmaxf(m0, mt0), mn1 = fmaxf(m1, mt1);
            float sc0 = __expf(m0 - mn0), sc1 = __expf(m1 - mn1);
            float rs0 = 0.f, rs1 = 0.f;
#pragma unroll
            for (int nt = 0; nt < 8; nt++) {
                s[nt][0] = __expf(s[nt][0] - mn0);
                s[nt][1] = __expf(s[nt][1] - mn0);
                s[nt][2] = __expf(s[nt][2] - mn1);
                s[nt][3] = __expf(s[nt][3] - mn1);
                rs0 += s[nt][0] + s[nt][1];
                rs1 += s[nt][2] + s[nt][3];
            }
#pragma unroll
            for (int off = 1; off <= 2; off <<= 1) {
                rs0 += __shfl_xor_sync(0xffffffffu, rs0, off);
                rs1 += __shfl_xor_sync(0xffffffffu, rs1, off);
            }
            l0 = l0 * sc0 + rs0;
            l1 = l1 * sc1 + rs1;
            m0 = mn0;
            m1 = mn1;
#pragma unroll
            for (int i = 0; i < 8; i++) {
                o[i][0] *= sc0; o[i][1] *= sc0;
                o[i][2] *= sc1; o[i][3] *= sc1;
            }

#pragma unroll
            for (int kc = 0; kc < 4; kc++) {
                uint32_t aph[4];
                aph[0] = pack2(s[2 * kc][0], s[2 * kc][1]);
                aph[1] = pack2(s[2 * kc][2], s[2 * kc][3]);
                aph[2] = pack2(s[2 * kc + 1][0], s[2 * kc + 1][1]);
                aph[3] = pack2(s[2 * kc + 1][2], s[2 * kc + 1][3]);
                uint32_t vh[4][4];
#pragma unroll
                for (int dg = 0; dg < 4; dg++)
                    ldm4t(vh[dg], Vh + swz((kc * 16 + vkr) * 128 + (dg * 16 + vnc) * 2));
#pragma unroll
                for (int dt = 0; dt < 8; dt++) {
                    int pr = dt >> 1, oo = (dt & 1) * 2;
                    mma16816(o[dt], aph, vh[pr][oo], vh[pr][oo + 1]);
                }
            }
        }
    }

    float inv0 = 1.f / l0, inv1 = 1.f / l1;
    size_t row0 = (size_t)b * SS + qrow + r0;
    size_t row1 = row0 + 8;
#pragma unroll
    for (int dt = 0; dt < 8; dt++) {
        int d = hoff + dt * 8 + c0;
        *(__half2*)&oh[row0 * EE + d] = __floats2half2_rn(o[dt][0] * inv0, o[dt][1] * inv0);
        *(__half2*)&oh[row1 * EE + d] = __floats2half2_rn(o[dt][2] * inv1, o[dt][3] * inv1);
    }
#undef ISSUE_KV
}

// ---------------- launch ----------------
extern "C" void kernel_launch(void* const* d_in, const int* in_sizes, int n_in,
                              void* d_out, int out_size) {
    const float* x = (const float*)d_in[0];
    const float* Wq = (const float*)d_in[1];
    const float* bq = (const float*)d_in[2];
    const float* Wk = (const float*)d_in[3];
    const float* bk = (const float*)d_in[4];
    const float* Wv = (const float*)d_in[5];
    const float* bv = (const float*)d_in[6];
    const float* Wp = (const float*)d_in[7];
    const float* bp = (const float*)d_in[8];
    const float* ln1_g = (const float*)d_in[9];
    const float* ln1_b = (const float*)d_in[10];
    const float* ln2_g = (const float*)d_in[11];
    const float* ln2_b = (const float*)d_in[12];
    const float* W1 = (const float*)d_in[13];
    const float* b1 = (const float*)d_in[14];
    const float* W2 = (const float*)d_in[15];
    const float* b2 = (const float*)d_in[16];
    const float* lnf_g = (const float*)d_in[17];
    const float* lnf_b = (const float*)d_in[18];
    float* out = (float*)d_out;

    __half *p_ah, *p_fh, *p_qkvh, *p_wq, *p_wp, *p_w1, *p_w2;
    float *p_bqkv, *p_x1;
    cudaGetSymbolAddress((void**)&p_ah, g_ah);
    cudaGetSymbolAddress((void**)&p_fh, g_fh);
    cudaGetSymbolAddress((void**)&p_qkvh, g_qkvh);
    cudaGetSymbolAddress((void**)&p_wq, g_wqkvt);
    cudaGetSymbolAddress((void**)&p_wp, g_wpt);
    cudaGetSymbolAddress((void**)&p_w1, g_w1t);
    cudaGetSymbolAddress((void**)&p_w2, g_w2t);
    cudaGetSymbolAddress((void**)&p_bqkv, g_bqkv);
    cudaGetSymbolAddress((void**)&p_x1, g_x1);
    __half* p_f2h = p_qkvh;   // reuse qkv storage (dead after attention) for fp16 f2

    int gsmem = 3 * STG;  // 98304
    cudaFuncSetAttribute(tcgemm<0>, cudaFuncAttributeMaxDynamicSharedMemorySize, gsmem);
    cudaFuncSetAttribute(tcgemm<1>, cudaFuncAttributeMaxDynamicSharedMemorySize, gsmem);
    cudaFuncSetAttribute(tcgemm<2>, cudaFuncAttributeMaxDynamicSharedMemorySize, gsmem);
    cudaFuncSetAttribute(tcgemm<3>, cudaFuncAttributeMaxDynamicSharedMemorySize, gsmem);
    int asmem = 49152;
    cudaFuncSetAttribute(attn_kernel, cudaFuncAttributeMaxDynamicSharedMemorySize, asmem);

    dim3 tb(32, 8);
    pack_wqkv_tiled<<<dim3(2, 24, 36), tb>>>(Wq, Wk, Wv);
    pack_bias_kernel<<<9, 256>>>(bq, bk, bv);
    transpose_h_tiled<<<dim3(EE / 32, EE / 32), tb>>>(Wp, p_wp, EE, EE);
    transpose_h_tiled<<<dim3(FF / 32, EE / 32), tb>>>(W1, p_w1, EE, FF);
    transpose_h_tiled<<<dim3(EE / 32, FF / 32), tb>>>(W2, p_w2, FF, EE);

    ln_h_kernel<<<ROWS / 8, 256>>>(x, ln1_g, ln1_b, p_ah);
    tcgemm<3><<<dim3(QKV_N / 128, ROWS / 128), 128, gsmem>>>(
        p_ah, p_wq, p_bqkv, nullptr, nullptr, p_qkvh, QKV_N, EE);
    attn_kernel<<<dim3(SS / 128, BB * HH), 256, asmem>>>(p_qkvh, p_ah);
    tcgemm<2><<<dim3(EE / 128, ROWS / 128), 128, gsmem>>>(
        p_ah, p_wp, bp, x, p_x1, nullptr, EE, EE);
    ln_h_kernel<<<ROWS / 8, 256>>>(p_x1, ln2_g, ln2_b, p_ah);
    tcgemm<1><<<dim3(FF / 128, ROWS / 128), 128, gsmem>>>(
        p_ah, p_w1, b1, nullptr, nullptr, p_fh, FF, EE);
    tcgemm<3><<<dim3(EE / 128, ROWS / 128), 128, gsmem>>>(
        p_fh, p_w2, b2, nullptr, nullptr, p_f2h, EE, FF);
    ln_final_kernel<<<ROWS / 8, 256>>>(p_f2h, lnf_g, lnf_b, p_x1, out);
}

// round 16
// speedup vs baseline: 12.2908x; 1.0232x over previous
#include <cuda_runtime.h>
#include <cuda_fp16.h>
#include <math.h>
#include <stdint.h>

#define BB 16
#define SS 1024
#define EE 768
#define HH 12
#define DD 64
#define FF 3072
#define ROWS (BB * SS)
#define QKV_N (3 * EE)

// scratch
__device__ __half g_ah[ROWS * EE];
__device__ __half g_fh[ROWS * FF];
__device__ __half g_qkvh[ROWS * QKV_N];   // qkv; later reused as fp16 f2 buffer
__device__ __half g_wqkvt[QKV_N * EE];
__device__ __half g_wpt[EE * EE];
__device__ __half g_w1t[FF * EE];
__device__ __half g_w2t[EE * FF];
__device__ float g_bqkv[QKV_N];
__device__ float g_x1[ROWS * EE];

__device__ __forceinline__ uint32_t swz(uint32_t o) { return o ^ ((o >> 3) & 0x70); }
__device__ __forceinline__ uint32_t pack2(float x, float y) {
    __half2 t = __floats2half2_rn(x, y);
    return *(uint32_t*)&t;
}

// ---------------- weight prep (tiled, coalesced) ----------------
__global__ void pack_wqkv_tiled(const float* __restrict__ Wq, const float* __restrict__ Wk,
                                const float* __restrict__ Wv) {
    __shared__ float t[32][33];
    int z = blockIdx.z, sec = z / 12, h = z % 12;
    const float* W = (sec == 0) ? Wq : (sec == 1) ? Wk : Wv;
    float sc = (sec == 0) ? 0.125f : 1.0f;
    int d0 = blockIdx.x * 32, e0 = blockIdx.y * 32;
    int tx = threadIdx.x, ty = threadIdx.y;
#pragma unroll
    for (int j = ty; j < 32; j += 8)
        t[j][tx] = W[((size_t)h * EE + e0 + j) * DD + d0 + tx] * sc;
    __syncthreads();
#pragma unroll
    for (int j = ty; j < 32; j += 8)
        g_wqkvt[(size_t)(sec * 768 + h * 64 + d0 + j) * EE + e0 + tx] =
            __float2half_rn(t[tx][j]);
}

__global__ void pack_bias_kernel(const float* __restrict__ bq, const float* __restrict__ bk,
                                 const float* __restrict__ bv) {
    int idx = blockIdx.x * blockDim.x + threadIdx.x;
    if (idx >= QKV_N) return;
    int sec = idx / 768;
    const float* bsrc = (sec == 0) ? bq : (sec == 1) ? bk : bv;
    float v = bsrc[idx % 768];
    g_bqkv[idx] = (sec == 0) ? v * 0.125f : v;
}

__global__ void transpose_h_tiled(const float* __restrict__ in,
                                  __half* __restrict__ oh, int K, int N) {
    __shared__ float t[32][33];
    int n0 = blockIdx.x * 32, k0 = blockIdx.y * 32;
    int tx = threadIdx.x, ty = threadIdx.y;
#pragma unroll
    for (int j = ty; j < 32; j += 8)
        t[j][tx] = in[(size_t)(k0 + j) * N + n0 + tx];
    __syncthreads();
#pragma unroll
    for (int j = ty; j < 32; j += 8)
        oh[(size_t)(n0 + j) * K + k0 + tx] = __float2half_rn(t[tx][j]);
}

// ---------------- LN: warp-per-row, 8 rows/block ----------------
__device__ __forceinline__ float wsum(float v) {
#pragma unroll
    for (int m = 16; m; m >>= 1) v += __shfl_xor_sync(0xffffffffu, v, m);
    return v;
}

__global__ void __launch_bounds__(256) ln_h_kernel(const float* __restrict__ in,
                                                   const float* __restrict__ gam,
                                                   const float* __restrict__ bet,
                                                   __half* __restrict__ oh) {
    int w = threadIdx.x >> 5, lane = threadIdx.x & 31;
    size_t row = (size_t)blockIdx.x * 8 + w;
    const float4* xp = (const float4*)(in + row * EE);
    float4 xv[6];
    float s = 0.f;
#pragma unroll
    for (int i = 0; i < 6; i++) {
        xv[i] = xp[lane + 32 * i];
        s += xv[i].x + xv[i].y + xv[i].z + xv[i].w;
    }
    float mu = wsum(s) * (1.f / EE);
    float v = 0.f;
#pragma unroll
    for (int i = 0; i < 6; i++) {
        xv[i].x -= mu; xv[i].y -= mu; xv[i].z -= mu; xv[i].w -= mu;
        v += xv[i].x * xv[i].x + xv[i].y * xv[i].y + xv[i].z * xv[i].z + xv[i].w * xv[i].w;
    }
    float rstd = rsqrtf(wsum(v) * (1.f / EE) + 1e-5f);
    uint2* op = (uint2*)(oh + row * EE);
#pragma unroll
    for (int i = 0; i < 6; i++) {
        float4 g = __ldg(&((const float4*)gam)[lane + 32 * i]);
        float4 be = __ldg(&((const float4*)bet)[lane + 32 * i]);
        uint2 o;
        o.x = pack2(xv[i].x * rstd * g.x + be.x, xv[i].y * rstd * g.y + be.y);
        o.y = pack2(xv[i].z * rstd * g.z + be.z, xv[i].w * rstd * g.w + be.w);
        op[lane + 32 * i] = o;
    }
}

// final LN: fp16 input (f2), fp32 residual, fp32 out
__global__ void __launch_bounds__(256) ln_final_kernel(const __half* __restrict__ in,
                                                       const float* __restrict__ gam,
                                                       const float* __restrict__ bet,
                                                       const float* __restrict__ res,
                                                       float* __restrict__ out) {
    int w = threadIdx.x >> 5, lane = threadIdx.x & 31;
    size_t row = (size_t)blockIdx.x * 8 + w;
    const uint2* xp = (const uint2*)(in + row * EE);
    float4 xv[6];
    float s = 0.f;
#pragma unroll
    for (int i = 0; i < 6; i++) {
        uint2 p = xp[lane + 32 * i];
        __half2 h0 = *(__half2*)&p.x, h1 = *(__half2*)&p.y;
        float2 f0 = __half22float2(h0), f1 = __half22float2(h1);
        xv[i] = make_float4(f0.x, f0.y, f1.x, f1.y);
        s += xv[i].x + xv[i].y + xv[i].z + xv[i].w;
    }
    float mu = wsum(s) * (1.f / EE);
    float v = 0.f;
#pragma unroll
    for (int i = 0; i < 6; i++) {
        xv[i].x -= mu; xv[i].y -= mu; xv[i].z -= mu; xv[i].w -= mu;
        v += xv[i].x * xv[i].x + xv[i].y * xv[i].y + xv[i].z * xv[i].z + xv[i].w * xv[i].w;
    }
    float rstd = rsqrtf(wsum(v) * (1.f / EE) + 1e-5f);
    float4* op = (float4*)(out + row * EE);
    const float4* rp = (const float4*)(res + row * EE);
#pragma unroll
    for (int i = 0; i < 6; i++) {
        float4 g = __ldg(&((const float4*)gam)[lane + 32 * i]);
        float4 be = __ldg(&((const float4*)bet)[lane + 32 * i]);
        float4 r = rp[lane + 32 * i];
        float4 o;
        o.x = xv[i].x * rstd * g.x + be.x + r.x;
        o.y = xv[i].y * rstd * g.y + be.y + r.y;
        o.z = xv[i].z * rstd * g.z + be.z + r.z;
        o.w = xv[i].w * rstd * g.w + be.w + r.w;
        op[lane + 32 * i] = o;
    }
}

// ---------------- HMMA primitives (fp16) ----------------
__device__ __forceinline__ void cpasync16(uint32_t dst, const void* src) {
    asm volatile("cp.async.cg.shared.global [%0], [%1], 16;" :: "r"(dst), "l"(src));
}
__device__ __forceinline__ void ldm4(uint32_t* r, uint32_t addr) {
    asm volatile("ldmatrix.sync.aligned.m8n8.x4.shared.b16 {%0,%1,%2,%3}, [%4];"
                 : "=r"(r[0]), "=r"(r[1]), "=r"(r[2]), "=r"(r[3]) : "r"(addr));
}
__device__ __forceinline__ void ldm4t(uint32_t* r, uint32_t addr) {
    asm volatile("ldmatrix.sync.aligned.m8n8.x4.trans.shared.b16 {%0,%1,%2,%3}, [%4];"
                 : "=r"(r[0]), "=r"(r[1]), "=r"(r[2]), "=r"(r[3]) : "r"(addr));
}
__device__ __forceinline__ void mma16816(float* d, const uint32_t* a, uint32_t b0, uint32_t b1) {
    asm volatile(
        "mma.sync.aligned.m16n8k16.row.col.f32.f16.f16.f32 "
        "{%0,%1,%2,%3}, {%4,%5,%6,%7}, {%8,%9}, {%0,%1,%2,%3};"
        : "+f"(d[0]), "+f"(d[1]), "+f"(d[2]), "+f"(d[3])
        : "r"(a[0]), "r"(a[1]), "r"(a[2]), "r"(a[3]), "r"(b0), "r"(b1));
}

// ---------------- HMMA GEMM: 128x128 CTA, 128 thr, 64x64 warp, 3-stage ------
// Register double-buffered fragments: LDSM(ks+1) overlaps HMMA(ks).
// 2 CTAs/SM. EPI: 0 bias->f32, 1 bias+gelu->fp16, 2 bias+res->f32, 3 bias->fp16
#define STG 32768

template <int EPI>
__global__ void __launch_bounds__(128, 2) tcgemm(const __half* __restrict__ Ah,
                                                 const __half* __restrict__ Bh,
                                                 const float* __restrict__ bias,
                                                 const float* __restrict__ res,
                                                 float* __restrict__ C,
                                                 __half* __restrict__ Ch,
                                                 int N, int K) {
    extern __shared__ char sm[];
    uint32_t sbase = (uint32_t)__cvta_generic_to_shared(sm);
    int tid = threadIdx.x;
    int lane = tid & 31, w = tid >> 5;
    int wm = w >> 1, wn = w & 1;
    int bn = blockIdx.x * 128, bm = blockIdx.y * 128;

    float acc[4][8][4];
#pragma unroll
    for (int i = 0; i < 4; i++)
#pragma unroll
        for (int j = 0; j < 8; j++)
#pragma unroll
            for (int q = 0; q < 4; q++) acc[i][j][q] = 0.f;

    int nk = K >> 6;

#define LOAD_STAGE(kc, buf)                                                        \
    {                                                                              \
        uint32_t sb_ = sbase + (buf) * STG;                                        \
        _Pragma("unroll")                                                          \
        for (int ii = 0; ii < 16; ii++) {                                          \
            int i = tid + ii * 128;                                                \
            int t = i >> 10, wrd = i & 1023, r = wrd >> 3, c = wrd & 7;            \
            int rb = t ? bn : bm;                                                  \
            const __half* sp = (t ? Bh : Ah) + (size_t)(rb + r) * K + (kc) * 64 + c * 8; \
            cpasync16(sb_ + t * 16384 + swz(r * 128 + c * 16), sp);                \
        }                                                                          \
        asm volatile("cp.async.commit_group;" ::: "memory");                       \
    }

// load fragment set for sub-step ks from smem base sb into slot p
#define LOAD_FRAGS(sb, ks, p)                                                      \
    {                                                                              \
        _Pragma("unroll")                                                          \
        for (int mt = 0; mt < 4; mt++) {                                           \
            int row = wm * 64 + mt * 16 + ra;                                      \
            ldm4(Af[p][mt], (sb) + swz(row * 128 + ((ks) * 16 + ka) * 2));         \
        }                                                                          \
        _Pragma("unroll")                                                          \
        for (int pr = 0; pr < 4; pr++) {                                           \
            int row = wn * 64 + pr * 16 + rb_n;                                    \
            ldm4(Bf[p][pr], (sb) + 16384 + swz(row * 128 + ((ks) * 16 + kb_n) * 2)); \
        }                                                                          \
    }

    LOAD_STAGE(0, 0);
    LOAD_STAGE(1, 1);

    int ra = (lane & 7) + ((lane & 8) ? 8 : 0);
    int ka = (lane & 16) ? 8 : 0;
    int rb_n = (lane & 7) + ((lane & 16) ? 8 : 0);
    int kb_n = (lane & 8) ? 8 : 0;

    uint32_t Af[2][4][4], Bf[2][4][4];
    int buf = 0;
    for (int kc = 0; kc < nk; kc++) {
        if (kc + 1 < nk) {
            asm volatile("cp.async.wait_group 1;" ::: "memory");
        } else {
            asm volatile("cp.async.wait_group 0;" ::: "memory");
        }
        __syncthreads();
        if (kc + 2 < nk) {
            int nb = buf + 2;
            if (nb >= 3) nb -= 3;
            LOAD_STAGE(kc + 2, nb);
        }
        uint32_t sb = sbase + buf * STG;
        LOAD_FRAGS(sb, 0, 0);
#pragma unroll
        for (int ks = 0; ks < 4; ks++) {
            int cur = ks & 1;
            if (ks < 3) LOAD_FRAGS(sb, ks + 1, cur ^ 1);
#pragma unroll
            for (int mt = 0; mt < 4; mt++)
#pragma unroll
                for (int nt = 0; nt < 8; nt++) {
                    int pr = nt >> 1, o = (nt & 1) * 2;
                    mma16816(acc[mt][nt], Af[cur][mt], Bf[cur][pr][o], Bf[cur][pr][o + 1]);
                }
        }
        if (++buf == 3) buf = 0;
    }

    int l4 = lane >> 2, l2 = (lane & 3) * 2;
#pragma unroll
    for (int mt = 0; mt < 4; mt++)
#pragma unroll
        for (int nt = 0; nt < 8; nt++) {
            int col = bn + wn * 64 + nt * 8 + l2;
            float b0 = __ldg(&bias[col]), b1 = __ldg(&bias[col + 1]);
#pragma unroll
            for (int half = 0; half < 2; half++) {
                size_t row = (size_t)(bm + wm * 64 + mt * 16 + l4 + half * 8);
                float v0 = acc[mt][nt][half * 2 + 0] + b0;
                float v1 = acc[mt][nt][half * 2 + 1] + b1;
                if (EPI == 2) {
                    float2 rr = __ldg((const float2*)&res[row * N + col]);
                    v0 += rr.x;
                    v1 += rr.y;
                }
                if (EPI == 1) {
                    v0 = 0.5f * v0 * (1.0f + erff(v0 * 0.70710678118654752f));
                    v1 = 0.5f * v1 * (1.0f + erff(v1 * 0.70710678118654752f));
                }
                if (EPI == 1 || EPI == 3) {
                    *(__half2*)&Ch[row * N + col] = __floats2half2_rn(v0, v1);
                } else {
                    *(float2*)&C[row * N + col] = make_float2(v0, v1);
                }
            }
        }
#undef LOAD_FRAGS
#undef LOAD_STAGE
}

// ---------------- HMMA flash attention: 128-row Q tile, 256 threads ----------
__global__ void __launch_bounds__(256, 2) attn_kernel(const __half* __restrict__ qkvh,
                                                      __half* __restrict__ oh) {
    extern __shared__ char smc[];
    uint32_t sb = (uint32_t)__cvta_generic_to_shared(smc);
    uint32_t Qs = sb;

    int qt = gridDim.x - 1 - blockIdx.x;   // heavy (large qt) first
    int bh = blockIdx.y;
    int b = bh / HH, h = bh % HH;
    int tid = threadIdx.x, lane = tid & 31, w = tid >> 5;
    size_t base = (size_t)b * SS * QKV_N;
    int hoff = h * DD;

#pragma unroll
    for (int ii = 0; ii < 4; ii++) {
        int i = tid + ii * 256;
        int r = i >> 3, c = i & 7;
        cpasync16(Qs + swz(r * 128 + c * 16),
                  qkvh + base + (size_t)(qt * 128 + r) * QKV_N + hoff + c * 8);
    }

#define ISSUE_KV(kt, bufo)                                                          \
    {                                                                               \
        _Pragma("unroll")                                                           \
        for (int ii = 0; ii < 4; ii++) {                                            \
            int i = tid + ii * 256;                                                 \
            int ts = i >> 9, wrd = i & 511, r = wrd >> 3, c = wrd & 7;              \
            cpasync16(sb + (bufo) + ts * 8192 + swz(r * 128 + c * 16),              \
                      qkvh + base + (size_t)((kt) * 64 + r) * QKV_N + hoff +        \
                          (ts ? 2 * EE : EE) + c * 8);                              \
        }                                                                           \
        asm volatile("cp.async.commit_group;" ::: "memory");                        \
    }

    ISSUE_KV(0, 16384);

    int ra = (lane & 7) + ((lane & 8) ? 8 : 0);
    int ka = (lane & 16) ? 8 : 0;
    int rbn = (lane & 7) + ((lane & 16) ? 8 : 0);
    int kbn = (lane & 8) ? 8 : 0;
    int vkr = (lane & 7) + ((lane & 8) ? 8 : 0);
    int vnc = (lane & 16) ? 8 : 0;
    int r0 = lane >> 2, c0 = (lane & 3) * 2;

    int qrow = qt * 128 + w * 16;
    int ktmax = 2 * qt + 1;

    float m0 = -1e30f, m1 = -1e30f, l0 = 0.f, l1 = 0.f;
    float o[8][4];
#pragma unroll
    for (int i = 0; i < 8; i++)
#pragma unroll
        for (int j = 0; j < 4; j++) o[i][j] = 0.f;

    for (int kt = 0; kt <= ktmax; kt++) {
        asm volatile("cp.async.wait_group 0;" ::: "memory");
        __syncthreads();
        uint32_t kvo = 16384 + (kt & 1) * 16384;
        if (kt < ktmax) ISSUE_KV(kt + 1, 16384 + ((kt + 1) & 1) * 16384);
        uint32_t Kh = sb + kvo, Vh = sb + kvo + 8192;

        if (kt * 64 <= qrow + 15) {
            float s[8][4];
#pragma unroll
            for (int i = 0; i < 8; i++)
#pragma unroll
                for (int j = 0; j < 4; j++) s[i][j] = 0.f;
#pragma unroll
            for (int kc = 0; kc < 4; kc++) {
                uint32_t qh[4], kh[4][4];
                ldm4(qh, Qs + swz((w * 16 + ra) * 128 + (kc * 16 + ka) * 2));
#pragma unroll
                for (int tg = 0; tg < 4; tg++)
                    ldm4(kh[tg], Kh + swz((tg * 16 + rbn) * 128 + (kc * 16 + kbn) * 2));
#pragma unroll
                for (int nt = 0; nt < 8; nt++) {
                    int pr = nt >> 1, oo = (nt & 1) * 2;
                    mma16816(s[nt], qh, kh[pr][oo], kh[pr][oo + 1]);
                }
            }

            if (kt * 64 + 63 > qrow) {
                int row0 = qrow + r0, row1 = row0 + 8;
#pragma unroll
                for (int nt = 0; nt < 8; nt++) {
                    int c = kt * 64 + nt * 8 + c0;
                    if (c > row0) s[nt][0] = -1e30f;
                    if (c + 1 > row0) s[nt][1] = -1e30f;
                    if (c > row1) s[nt][2] = -1e30f;
                    if (c + 1 > row1) s[nt][3] = -1e30f;
                }
            }

            float mt0 = -1e30f, mt1 = -1e30f;
#pragma unroll
            for (int nt = 0; nt < 8; nt++) {
                mt0 = fmaxf(mt0, fmaxf(s[nt][0], s[nt][1]));
                mt1 = fmaxf(mt1, fmaxf(s[nt][2], s[nt][3]));
            }
#pragma unroll
            for (int off = 1; off <= 2; off <<= 1) {
                mt0 = fmaxf(mt0, __shfl_xor_sync(0xffffffffu, mt0, off));
                mt1 = fmaxf(mt1, __shfl_xor_sync(0xffffffffu, mt1, off));
            }
            float mn0 = fmaxf(m0, mt0), mn1 = fmaxf(m1, mt1);
            float sc0 = __expf(m0 - mn0), sc1 = __expf(m1 - mn1);
            float rs0 = 0.f, rs1 = 0.f;
#pragma unroll
            for (int nt = 0; nt < 8; nt++) {
                s[nt][0] = __expf(s[nt][0] - mn0);
                s[nt][1] = __expf(s[nt][1] - mn0);
                s[nt][2] = __expf(s[nt][2] - mn1);
                s[nt][3] = __expf(s[nt][3] - mn1);
                rs0 += s[nt][0] + s[nt][1];
                rs1 += s[nt][2] + s[nt][3];
            }
#pragma unroll
            for (int off = 1; off <= 2; off <<= 1) {
                rs0 += __shfl_xor_sync(0xffffffffu, rs0, off);
                rs1 += __shfl_xor_sync(0xffffffffu, rs1, off);
            }
            l0 = l0 * sc0 + rs0;
            l1 = l1 * sc1 + rs1;
            m0 = mn0;
            m1 = mn1;
#pragma unroll
            for (int i = 0; i < 8; i++) {
                o[i][0] *= sc0; o[i][1] *= sc0;
                o[i][2] *= sc1; o[i][3] *= sc1;
            }

#pragma unroll
            for (int kc = 0; kc < 4; kc++) {
                uint32_t aph[4];
                aph[0] = pack2(s[2 * kc][0], s[2 * kc][1]);
                aph[1] = pack2(s[2 * kc][2], s[2 * kc][3]);
                aph[2] = pack2(s[2 * kc + 1][0], s[2 * kc + 1][1]);
                aph[3] = pack2(s[2 * kc + 1][2], s[2 * kc + 1][3]);
                uint32_t vh[4][4];
#pragma unroll
                for (int dg = 0; dg < 4; dg++)
                    ldm4t(vh[dg], Vh + swz((kc * 16 + vkr) * 128 + (dg * 16 + vnc) * 2));
#pragma unroll
                for (int dt = 0; dt < 8; dt++) {
                    int pr = dt >> 1, oo = (dt & 1) * 2;
                    mma16816(o[dt], aph, vh[pr][oo], vh[pr][oo + 1]);
                }
            }
        }
    }

    float inv0 = 1.f / l0, inv1 = 1.f / l1;
    size_t row0 = (size_t)b * SS + qrow + r0;
    size_t row1 = row0 + 8;
#pragma unroll
    for (int dt = 0; dt < 8; dt++) {
        int d = hoff + dt * 8 + c0;
        *(__half2*)&oh[row0 * EE + d] = __floats2half2_rn(o[dt][0] * inv0, o[dt][1] * inv0);
        *(__half2*)&oh[row1 * EE + d] = __floats2half2_rn(o[dt][2] * inv1, o[dt][3] * inv1);
    }
#undef ISSUE_KV
}

// ---------------- launch ----------------
extern "C" void kernel_launch(void* const* d_in, const int* in_sizes, int n_in,
                              void* d_out, int out_size) {
    const float* x = (const float*)d_in[0];
    const float* Wq = (const float*)d_in[1];
    const float* bq = (const float*)d_in[2];
    const float* Wk = (const float*)d_in[3];
    const float* bk = (const float*)d_in[4];
    const float* Wv = (const float*)d_in[5];
    const float* bv = (const float*)d_in[6];
    const float* Wp = (const float*)d_in[7];
    const float* bp = (const float*)d_in[8];
    const float* ln1_g = (const float*)d_in[9];
    const float* ln1_b = (const float*)d_in[10];
    const float* ln2_g = (const float*)d_in[11];
    const float* ln2_b = (const float*)d_in[12];
    const float* W1 = (const float*)d_in[13];
    const float* b1 = (const float*)d_in[14];
    const float* W2 = (const float*)d_in[15];
    const float* b2 = (const float*)d_in[16];
    const float* lnf_g = (const float*)d_in[17];
    const float* lnf_b = (const float*)d_in[18];
    float* out = (float*)d_out;

    __half *p_ah, *p_fh, *p_qkvh, *p_wq, *p_wp, *p_w1, *p_w2;
    float *p_bqkv, *p_x1;
    cudaGetSymbolAddress((void**)&p_ah, g_ah);
    cudaGetSymbolAddress((void**)&p_fh, g_fh);
    cudaGetSymbolAddress((void**)&p_qkvh, g_qkvh);
    cudaGetSymbolAddress((void**)&p_wq, g_wqkvt);
    cudaGetSymbolAddress((void**)&p_wp, g_wpt);
    cudaGetSymbolAddress((void**)&p_w1, g_w1t);
    cudaGetSymbolAddress((void**)&p_w2, g_w2t);
    cudaGetSymbolAddress((void**)&p_bqkv, g_bqkv);
    cudaGetSymbolAddress((void**)&p_x1, g_x1);
    __half* p_f2h = p_qkvh;   // reuse qkv storage (dead after attention) for fp16 f2

    int gsmem = 3 * STG;  // 98304
    cudaFuncSetAttribute(tcgemm<0>, cudaFuncAttributeMaxDynamicSharedMemorySize, gsmem);
    cudaFuncSetAttribute(tcgemm<1>, cudaFuncAttributeMaxDynamicSharedMemorySize, gsmem);
    cudaFuncSetAttribute(tcgemm<2>, cudaFuncAttributeMaxDynamicSharedMemorySize, gsmem);
    cudaFuncSetAttribute(tcgemm<3>, cudaFuncAttributeMaxDynamicSharedMemorySize, gsmem);
    int asmem = 49152;
    cudaFuncSetAttribute(attn_kernel, cudaFuncAttributeMaxDynamicSharedMemorySize, asmem);

    dim3 tb(32, 8);
    pack_wqkv_tiled<<<dim3(2, 24, 36), tb>>>(Wq, Wk, Wv);
    pack_bias_kernel<<<9, 256>>>(bq, bk, bv);
    transpose_h_tiled<<<dim3(EE / 32, EE / 32), tb>>>(Wp, p_wp, EE, EE);
    transpose_h_tiled<<<dim3(FF / 32, EE / 32), tb>>>(W1, p_w1, EE, FF);
    transpose_h_tiled<<<dim3(EE / 32, FF / 32), tb>>>(W2, p_w2, FF, EE);

    ln_h_kernel<<<ROWS / 8, 256>>>(x, ln1_g, ln1_b, p_ah);
    tcgemm<3><<<dim3(QKV_N / 128, ROWS / 128), 128, gsmem>>>(
        p_ah, p_wq, p_bqkv, nullptr, nullptr, p_qkvh, QKV_N, EE);
    attn_kernel<<<dim3(SS / 128, BB * HH), 256, asmem>>>(p_qkvh, p_ah);
    tcgemm<2><<<dim3(EE / 128, ROWS / 128), 128, gsmem>>>(
        p_ah, p_wp, bp, x, p_x1, nullptr, EE, EE);
    ln_h_kernel<<<ROWS / 8, 256>>>(p_x1, ln2_g, ln2_b, p_ah);
    tcgemm<1><<<dim3(FF / 128, ROWS / 128), 128, gsmem>>>(
        p_ah, p_w1, b1, nullptr, nullptr, p_fh, FF, EE);
    tcgemm<3><<<dim3(EE / 128, ROWS / 128), 128, gsmem>>>(
        p_fh, p_w2, b2, nullptr, nullptr, p_f2h, EE, FF);
    ln_final_kernel<<<ROWS / 8, 256>>>(p_f2h, lnf_g, lnf_b, p_x1, out);
}